// round 6
// baseline (speedup 1.0000x reference)
#include <cuda_runtime.h>
#include <cuda_bf16.h>
#include <cstdint>
#include <cstddef>

#define BB 16
#define LL 32768
#define HH 64
#define NN 16
#define DMM 32

typedef unsigned long long u64;
typedef uint32_t u32;
typedef __nv_bfloat16 bf16;

// strides (elements)
#define USTR 72
#define MSTR 72
#define VSTR 72
#define ESTR 40
#define SSTR 40
#define YSTR 68
#define LSTR 521

// smem byte offsets (total 225408 <= 232448)
#define SM_MH 0
#define SM_ML 9216
#define SM_VH 18432
#define SM_VL 23040
#define SM_EH 27648
#define SM_EL 32768
#define SM_UH 37888
#define SM_UL 56320
#define SM_SLOC 74752
#define SM_SINH 141440
#define SM_SINL 182400
#define SM_GBUF 223360
#define SM_TOT 225408

// ---------------- scratch ----------------
__device__ float g_u[(size_t)BB * HH * LL];
__device__ float g_z[(size_t)BB * HH * LL];
__device__ bf16 g_Mh[HH * 4096], g_Ml[HH * 4096];
__device__ bf16 g_Vh[HH * 2048], g_Vl[HH * 2048];
__device__ bf16 g_Eh[HH * 2048], g_El[HH * 2048];
__device__ float2 g_w64c[HH * 16], g_w2048c[HH * 16];
__device__ float g_gamma[BB * HH], g_beta[BB * HH];

// ---------------- helpers ----------------
__device__ __forceinline__ u64 pk(float lo, float hi) {
    u64 r; asm("mov.b64 %0, {%1,%2};" : "=l"(r) : "f"(lo), "f"(hi)); return r;
}
__device__ __forceinline__ void upk(u64 a, float& lo, float& hi) {
    asm("mov.b64 {%0,%1}, %2;" : "=f"(lo), "=f"(hi) : "l"(a));
}
__device__ __forceinline__ u64 fma2(u64 a, u64 b, u64 c) {
    u64 d; asm("fma.rn.f32x2 %0, %1, %2, %3;" : "=l"(d) : "l"(a), "l"(b), "l"(c)); return d;
}
__device__ __forceinline__ float gelu_f(float x) {
    float x3 = x * x * x;
    float z = 0.7978845608028654f * fmaf(0.044715f, x3, x);
    float az = fabsf(z);
    float e = __expf(2.0f * az);
    float t = 1.0f - __fdividef(2.0f, e + 1.0f);
    t = copysignf(t, z);
    return 0.5f * x * (1.0f + t);
}
__device__ __forceinline__ void bsplit(float v, bf16* ph, bf16* pl) {
    bf16 hi = __float2bfloat16(v);
    *ph = hi; *pl = __float2bfloat16(v - __bfloat162float(hi));
}
__device__ __forceinline__ u32 pk2bf(bf16 a, bf16 b) {
    __nv_bfloat162 v; v.x = a; v.y = b; return *reinterpret_cast<u32*>(&v);
}
__device__ __forceinline__ void mma16816(float* c, const u32* a, const u32* b) {
    asm volatile(
        "mma.sync.aligned.m16n8k16.row.col.f32.bf16.bf16.f32 "
        "{%0,%1,%2,%3}, {%4,%5,%6,%7}, {%8,%9}, {%0,%1,%2,%3};"
        : "+f"(c[0]), "+f"(c[1]), "+f"(c[2]), "+f"(c[3])
        : "r"(a[0]), "r"(a[1]), "r"(a[2]), "r"(a[3]), "r"(b[0]), "r"(b[1]));
}
__device__ __forceinline__ void ldA(u32* a, const bf16* base, int stride,
                                    int r0, int k0, int lane) {
    const bf16* p = base + (r0 + (lane >> 2)) * stride + k0 + (lane & 3) * 2;
    a[0] = *(const u32*)p;
    a[1] = *(const u32*)(p + 8 * stride);
    a[2] = *(const u32*)(p + 8);
    a[3] = *(const u32*)(p + 8 * stride + 8);
}
__device__ __forceinline__ void ldB(u32* b, const bf16* base, int stride,
                                    int n0, int k0, int lane) {
    const bf16* p = base + (n0 + (lane >> 2)) * stride + k0 + (lane & 3) * 2;
    b[0] = *(const u32*)p;
    b[1] = *(const u32*)(p + 8);
}
__device__ __forceinline__ void stage_u(const float4* gu4, int q,
                                        bf16* UH, bf16* UL, int t) {
    #pragma unroll
    for (int k = 0; k < 8; k++) {
        int f = t + k * 256;
        float4 v = gu4[q * 2048 + f];
        int c = f >> 4, i0 = (f & 15) * 4;
        bf16 h0 = __float2bfloat16(v.x), h1 = __float2bfloat16(v.y);
        bf16 h2 = __float2bfloat16(v.z), h3 = __float2bfloat16(v.w);
        *(u32*)&UH[c * USTR + i0] = pk2bf(h0, h1);
        *(u32*)&UH[c * USTR + i0 + 2] = pk2bf(h2, h3);
        *(u32*)&UL[c * USTR + i0] = pk2bf(
            __float2bfloat16(v.x - __bfloat162float(h0)),
            __float2bfloat16(v.y - __bfloat162float(h1)));
        *(u32*)&UL[c * USTR + i0 + 2] = pk2bf(
            __float2bfloat16(v.z - __bfloat162float(h2)),
            __float2bfloat16(v.w - __bfloat162float(h3)));
    }
}

// ---------------- K0: per-h tables (64 blocks x 64 threads) ----------------
__global__ void k_setup_tab(const float* __restrict__ log_dt,
                            const float* __restrict__ A_re, const float* __restrict__ A_im,
                            const float* __restrict__ C_re, const float* __restrict__ C_im,
                            const float* __restrict__ Dv)
{
    int h = blockIdx.x;
    int j = threadIdx.x;          // 0..63
    __shared__ float Ks[64];
    double dt = exp((double)log_dt[h]);
    double kacc = 0.0;
    for (int n = 0; n < NN; n++) {
        int i = h * NN + n;
        double ar = A_re[i], ai = A_im[i];
        double mre = dt * ar, mim = dt * ai;
        double e1 = exp(mre);
        double wr = e1 * cos(mim), wi = e1 * sin(mim);
        double den = ar * ar + ai * ai;
        double nr = wr - 1.0, ni = wi;
        double qr = (nr * ar + ni * ai) / den, qi = (ni * ar - nr * ai) / den;
        double cr = C_re[i], ci = C_im[i];
        double c2r = 2.0 * (cr * qr - ci * qi), c2i = 2.0 * (cr * qi + ci * qr);
        double ej = exp(j * mre);
        kacc += c2r * ej * cos(j * mim) - c2i * ej * sin(j * mim);
        double ep = exp((j + 1) * mre);
        double pr = ep * cos((j + 1) * mim), pi = ep * sin((j + 1) * mim);
        bsplit((float)(c2r * pr - c2i * pi),
               &g_Eh[h * 2048 + j * 32 + n], &g_El[h * 2048 + j * 32 + n]);
        bsplit((float)(-(c2r * pi + c2i * pr)),
               &g_Eh[h * 2048 + j * 32 + 16 + n], &g_El[h * 2048 + j * 32 + 16 + n]);
        double ev = exp((63 - j) * mre);
        bsplit((float)(ev * cos((63 - j) * mim)),
               &g_Vh[h * 2048 + n * 64 + j], &g_Vl[h * 2048 + n * 64 + j]);
        bsplit((float)(ev * sin((63 - j) * mim)),
               &g_Vh[h * 2048 + (16 + n) * 64 + j], &g_Vl[h * 2048 + (16 + n) * 64 + j]);
    }
    Ks[j] = (float)kacc;
    if (j < NN) {
        int i = h * NN + j;
        double ar = A_re[i], ai = A_im[i];
        double mre = dt * ar, mim = dt * ai;
        double e64 = exp(64.0 * mre);
        g_w64c[h * 16 + j] = make_float2((float)(e64 * cos(64.0 * mim)),
                                         (float)(e64 * sin(64.0 * mim)));
        double eg = exp(2048.0 * mre);
        g_w2048c[h * 16 + j] = make_float2((float)(eg * cos(2048.0 * mim)),
                                           (float)(eg * sin(2048.0 * mim)));
    }
    __syncthreads();
    float dD = Dv[h];
    for (int i2 = 0; i2 < 64; i2++) {
        float m = (i2 < j) ? Ks[j - i2] : (i2 == j ? Ks[0] + dD : 0.0f);
        bsplit(m, &g_Mh[h * 4096 + j * 64 + i2], &g_Ml[h * 4096 + j * 64 + i2]);
    }
}

// ---------------- K1: conditioning MLP + FiLM ----------------
__global__ void k_setup_mlp(const float* __restrict__ cp,
                            const float* __restrict__ W0, const float* __restrict__ b0,
                            const float* __restrict__ W1, const float* __restrict__ b1,
                            const float* __restrict__ W2, const float* __restrict__ b2,
                            const float* __restrict__ W_film, const float* __restrict__ b_film)
{
    __shared__ float c0[BB * DMM];
    __shared__ float c1[BB * DMM];
    int t = threadIdx.x;
    for (int i = t; i < BB * DMM; i += blockDim.x) {
        int b = i / DMM, d = i % DMM;
        float v = fmaf(cp[b * 2 + 0], W0[d], fmaf(cp[b * 2 + 1], W0[DMM + d], b0[d]));
        c0[i] = gelu_f(v);
    }
    __syncthreads();
    for (int i = t; i < BB * DMM; i += blockDim.x) {
        int b = i / DMM, d = i % DMM;
        float v = b1[d];
        for (int k = 0; k < DMM; k++) v = fmaf(c0[b * DMM + k], W1[k * DMM + d], v);
        c1[i] = gelu_f(v);
    }
    __syncthreads();
    for (int i = t; i < BB * DMM; i += blockDim.x) {
        int b = i / DMM, d = i % DMM;
        float v = b2[d];
        for (int k = 0; k < DMM; k++) v = fmaf(c1[b * DMM + k], W2[k * DMM + d], v);
        c0[i] = gelu_f(v);
    }
    __syncthreads();
    for (int i = t; i < BB * 2 * HH; i += blockDim.x) {
        int b = i / (2 * HH), j = i % (2 * HH);
        float v = b_film[j];
        for (int k = 0; k < DMM; k++) v = fmaf(c0[b * DMM + k], W_film[k * 2 * HH + j], v);
        if (j < HH) g_gamma[b * HH + j] = v;
        else        g_beta[b * HH + j - HH] = v;
    }
}

// ---------------- K2: u = gelu(x @ W_lin + b_lin) -> [B,H,L] ----------------
__global__ __launch_bounds__(256) void k_linear(const float* __restrict__ x,
                                                const float* __restrict__ W,
                                                const float* __restrict__ bias)
{
    extern __shared__ float sm2[];
    float* xs = sm2;
    float* Ws = sm2 + 256 * 65;
    int t = threadIdx.x;
    int b = blockIdx.x >> 7;
    int tile = blockIdx.x & 127;
    int l0 = tile * 256;
    const float* xg = x + ((size_t)b * LL + l0) * HH;

    for (int i = t; i < 64 * 64; i += 256) Ws[i] = W[i];
    for (int i = t; i < 256 * 64; i += 256) {
        int l = i >> 6, k = i & 63;
        xs[l * 65 + k] = xg[i];
    }
    __syncthreads();

    int li = t & 63;
    int hb = (t >> 6) * 16;
    u64 acc[4][8];
    #pragma unroll
    for (int p = 0; p < 8; p++) {
        u64 bp = *reinterpret_cast<const u64*>(bias + hb + 2 * p);
        acc[0][p] = bp; acc[1][p] = bp; acc[2][p] = bp; acc[3][p] = bp;
    }
    for (int k = 0; k < 64; k++) {
        float x0 = xs[li * 65 + k];
        float x1 = xs[(li + 64) * 65 + k];
        float x2v = xs[(li + 128) * 65 + k];
        float x3 = xs[(li + 192) * 65 + k];
        u64 xa = pk(x0, x0), xb = pk(x1, x1), xc = pk(x2v, x2v), xd = pk(x3, x3);
        const u64* wrow = reinterpret_cast<const u64*>(Ws + k * 64 + hb);
        #pragma unroll
        for (int p = 0; p < 8; p++) {
            u64 w2 = wrow[p];
            acc[0][p] = fma2(xa, w2, acc[0][p]);
            acc[1][p] = fma2(xb, w2, acc[1][p]);
            acc[2][p] = fma2(xc, w2, acc[2][p]);
            acc[3][p] = fma2(xd, w2, acc[3][p]);
        }
    }
    #pragma unroll
    for (int lg = 0; lg < 4; lg++) {
        int l = l0 + li + lg * 64;
        #pragma unroll
        for (int p = 0; p < 8; p++) {
            float v0, v1; upk(acc[lg][p], v0, v1);
            int h0 = hb + 2 * p;
            g_u[((size_t)b * HH + h0) * LL + l] = gelu_f(v0);
            g_u[((size_t)b * HH + h0 + 1) * LL + l] = gelu_f(v1);
        }
    }
}

// ---------------- K3: chunked S4 conv via bf16-split tensor-core GEMMs ----------------
__global__ __launch_bounds__(256) void k_scan_mma()
{
    extern __shared__ char smem[];
    bf16* MHs = (bf16*)(smem + SM_MH);
    bf16* MLs = (bf16*)(smem + SM_ML);
    bf16* VHs = (bf16*)(smem + SM_VH);
    bf16* VLs = (bf16*)(smem + SM_VL);
    bf16* EHs = (bf16*)(smem + SM_EH);
    bf16* ELs = (bf16*)(smem + SM_EL);
    bf16* UHs = (bf16*)(smem + SM_UH);
    bf16* ULs = (bf16*)(smem + SM_UL);
    float* SLOC = (float*)(smem + SM_SLOC);
    bf16* SINH = (bf16*)(smem + SM_SINH);
    bf16* SINL = (bf16*)(smem + SM_SINL);
    float2* GBUF = (float2*)(smem + SM_GBUF);

    int t = threadIdx.x;
    int bh = blockIdx.x;
    int h = bh & 63;
    int wid = t >> 5, lane = t & 31;

    // stage tables (insert pads)
    {
        const u32* gmh = (const u32*)(g_Mh + (size_t)h * 4096);
        const u32* gml = (const u32*)(g_Ml + (size_t)h * 4096);
        u32* smh = (u32*)MHs; u32* sml = (u32*)MLs;
        for (int i = t; i < 2048; i += 256) {
            int r = i >> 5, c = i & 31;
            smh[r * 36 + c] = gmh[i]; sml[r * 36 + c] = gml[i];
        }
        const u32* gvh = (const u32*)(g_Vh + (size_t)h * 2048);
        const u32* gvl = (const u32*)(g_Vl + (size_t)h * 2048);
        u32* svh = (u32*)VHs; u32* svl = (u32*)VLs;
        for (int i = t; i < 1024; i += 256) {
            int r = i >> 5, c = i & 31;
            svh[r * 36 + c] = gvh[i]; svl[r * 36 + c] = gvl[i];
        }
        const u32* geh = (const u32*)(g_Eh + (size_t)h * 2048);
        const u32* gel = (const u32*)(g_El + (size_t)h * 2048);
        u32* seh = (u32*)EHs; u32* sel = (u32*)ELs;
        for (int i = t; i < 1024; i += 256) {
            int r = i >> 4, c = i & 15;
            seh[r * 20 + c] = geh[i]; sel[r * 20 + c] = gel[i];
        }
    }
    __syncthreads();

    const float4* gu4 = (const float4*)(g_u + (size_t)bh * LL);

    // ---- pass 1: S_local = V @ U ----
    for (int q = 0; q < 4; q++) {
        stage_u(gu4, q, UHs, ULs, t);
        __syncthreads();
        int cloc = wid * 16, cglob = q * 128 + cloc;
        float C1[2][2][4] = {};
        #pragma unroll
        for (int kt = 0; kt < 4; kt++) {
            int k0 = kt * 16;
            u32 bh_[2][2], bl_[2][2];
            #pragma unroll
            for (int nt = 0; nt < 2; nt++) {
                ldB(bh_[nt], UHs, USTR, cloc + nt * 8, k0, lane);
                ldB(bl_[nt], ULs, USTR, cloc + nt * 8, k0, lane);
            }
            #pragma unroll
            for (int mt = 0; mt < 2; mt++) {
                u32 ah[4], al[4];
                ldA(ah, VHs, VSTR, mt * 16, k0, lane);
                ldA(al, VLs, VSTR, mt * 16, k0, lane);
                #pragma unroll
                for (int nt = 0; nt < 2; nt++) {
                    mma16816(C1[mt][nt], ah, bh_[nt]);
                    mma16816(C1[mt][nt], ah, bl_[nt]);
                    mma16816(C1[mt][nt], al, bh_[nt]);
                }
            }
        }
        #pragma unroll
        for (int mt = 0; mt < 2; mt++)
            #pragma unroll
            for (int nt = 0; nt < 2; nt++) {
                int r = mt * 16 + (lane >> 2);
                int cc = cglob + nt * 8 + (lane & 3) * 2;
                SLOC[r * LSTR + cc] = C1[mt][nt][0];
                SLOC[r * LSTR + cc + 1] = C1[mt][nt][1];
                SLOC[(r + 8) * LSTR + cc] = C1[mt][nt][2];
                SLOC[(r + 8) * LSTR + cc + 1] = C1[mt][nt][3];
            }
        __syncthreads();
    }

    // ---- chunk-state scan (512 chunks = 16 groups x 32) ----
    {
        int n = t & 15, g = t >> 4;
        float2 w64 = g_w64c[h * 16 + n];
        float sr = 0.f, si = 0.f;
        for (int m = 0; m < 32; m++) {
            int c = g * 32 + m;
            float xr = SLOC[n * LSTR + c], xi = SLOC[(16 + n) * LSTR + c];
            float nr = fmaf(w64.x, sr, fmaf(-w64.y, si, xr));
            si = fmaf(w64.x, si, fmaf(w64.y, sr, xi));
            sr = nr;
        }
        GBUF[g * 16 + n] = make_float2(sr, si);
        __syncthreads();
        if (t < 16) {
            float2 wG = g_w2048c[h * 16 + t];
            float pr = 0.f, pi = 0.f;
            for (int gg = 0; gg < 16; gg++) {
                float2 tm = GBUF[gg * 16 + t];
                GBUF[gg * 16 + t] = make_float2(pr, pi);
                float nr = fmaf(wG.x, pr, fmaf(-wG.y, pi, tm.x));
                pi = fmaf(wG.x, pi, fmaf(wG.y, pr, tm.y));
                pr = nr;
            }
        }
        __syncthreads();
        float2 I = GBUF[g * 16 + n];
        sr = I.x; si = I.y;
        for (int m = 0; m < 32; m++) {
            int c = g * 32 + m;
            bsplit(sr, &SINH[c * SSTR + n], &SINL[c * SSTR + n]);
            bsplit(si, &SINH[c * SSTR + 16 + n], &SINL[c * SSTR + 16 + n]);
            float xr = SLOC[n * LSTR + c], xi = SLOC[(16 + n) * LSTR + c];
            float nr = fmaf(w64.x, sr, fmaf(-w64.y, si, xr));
            si = fmaf(w64.x, si, fmaf(w64.y, sr, xi));
            sr = nr;
        }
        __syncthreads();
    }

    // ---- pass 2: Y = M@U + E@S_in, FiLM, writeback ----
    float gam = g_gamma[bh];
    float bet = g_beta[bh];
    float* Ys = SLOC;        // reuse
    float4* gz4 = (float4*)(g_z + (size_t)bh * LL);

    for (int q = 0; q < 4; q++) {
        stage_u(gu4, q, UHs, ULs, t);
        __syncthreads();
        int cloc = wid * 16, cglob = q * 128 + cloc;
        float C2[4][2][4] = {};
        #pragma unroll
        for (int kt = 0; kt < 4; kt++) {
            int k0 = kt * 16;
            u32 bh_[2][2], bl_[2][2];
            #pragma unroll
            for (int nt = 0; nt < 2; nt++) {
                ldB(bh_[nt], UHs, USTR, cloc + nt * 8, k0, lane);
                ldB(bl_[nt], ULs, USTR, cloc + nt * 8, k0, lane);
            }
            #pragma unroll
            for (int mt = 0; mt < 4; mt++) {
                if (kt > mt) continue;
                u32 ah[4], al[4];
                ldA(ah, MHs, MSTR, mt * 16, k0, lane);
                ldA(al, MLs, MSTR, mt * 16, k0, lane);
                #pragma unroll
                for (int nt = 0; nt < 2; nt++) {
                    mma16816(C2[mt][nt], ah, bh_[nt]);
                    mma16816(C2[mt][nt], ah, bl_[nt]);
                    mma16816(C2[mt][nt], al, bh_[nt]);
                }
            }
        }
        #pragma unroll
        for (int kt = 0; kt < 2; kt++) {
            int k0 = kt * 16;
            u32 bh_[2][2], bl_[2][2];
            #pragma unroll
            for (int nt = 0; nt < 2; nt++) {
                ldB(bh_[nt], SINH, SSTR, cglob + nt * 8, k0, lane);
                ldB(bl_[nt], SINL, SSTR, cglob + nt * 8, k0, lane);
            }
            #pragma unroll
            for (int mt = 0; mt < 4; mt++) {
                u32 ah[4], al[4];
                ldA(ah, EHs, ESTR, mt * 16, k0, lane);
                ldA(al, ELs, ESTR, mt * 16, k0, lane);
                #pragma unroll
                for (int nt = 0; nt < 2; nt++) {
                    mma16816(C2[mt][nt], ah, bh_[nt]);
                    mma16816(C2[mt][nt], ah, bl_[nt]);
                    mma16816(C2[mt][nt], al, bh_[nt]);
                }
            }
        }
        __syncthreads();   // Ys overlaps nothing live, but order stage->compute->store
        #pragma unroll
        for (int mt = 0; mt < 4; mt++)
            #pragma unroll
            for (int nt = 0; nt < 2; nt++) {
                int j = mt * 16 + (lane >> 2);
                int cc = cloc + nt * 8 + (lane & 3) * 2;
                Ys[cc * YSTR + j] = fmaf(C2[mt][nt][0], gam, bet);
                Ys[(cc + 1) * YSTR + j] = fmaf(C2[mt][nt][1], gam, bet);
                Ys[cc * YSTR + j + 8] = fmaf(C2[mt][nt][2], gam, bet);
                Ys[(cc + 1) * YSTR + j + 8] = fmaf(C2[mt][nt][3], gam, bet);
            }
        __syncthreads();
        #pragma unroll
        for (int k = 0; k < 8; k++) {
            int f = t + k * 256;
            int c = f >> 4, qq = f & 15;
            float4 o = *(const float4*)&Ys[c * YSTR + qq * 4];
            gz4[q * 2048 + f] = o;
        }
        __syncthreads();
    }
}

// ---------------- K4: out = x * gelu(z) ----------------
__global__ __launch_bounds__(256) void k_epilogue(const float* __restrict__ x,
                                                  float* __restrict__ out)
{
    __shared__ float zt[64 * 65];
    int t = threadIdx.x;
    int b = blockIdx.x >> 9;
    int tile = blockIdx.x & 511;
    int l0 = tile * 64;
    #pragma unroll
    for (int i = t; i < 1024; i += 256) {
        int hh = i >> 4, q = i & 15;
        float4 v = *reinterpret_cast<const float4*>(
            g_z + ((size_t)b * HH + hh) * LL + l0 + 4 * q);
        float* d = zt + hh * 65 + 4 * q;
        d[0] = v.x; d[1] = v.y; d[2] = v.z; d[3] = v.w;
    }
    __syncthreads();
    #pragma unroll
    for (int i = t; i < 1024; i += 256) {
        int l = i >> 4, hq = i & 15;
        float z0 = zt[(4 * hq + 0) * 65 + l];
        float z1 = zt[(4 * hq + 1) * 65 + l];
        float z2 = zt[(4 * hq + 2) * 65 + l];
        float z3 = zt[(4 * hq + 3) * 65 + l];
        size_t base = ((size_t)b * LL + l0 + l) * HH + 4 * hq;
        float4 xv = *reinterpret_cast<const float4*>(x + base);
        float4 o;
        o.x = xv.x * gelu_f(z0);
        o.y = xv.y * gelu_f(z1);
        o.z = xv.z * gelu_f(z2);
        o.w = xv.w * gelu_f(z3);
        *reinterpret_cast<float4*>(out + base) = o;
    }
}

// ---------------- launch ----------------
extern "C" void kernel_launch(void* const* d_in, const int* in_sizes, int n_in,
                              void* d_out, int out_size)
{
    const float* x      = (const float*)d_in[0];
    const float* cp     = (const float*)d_in[1];
    const float* W0     = (const float*)d_in[2];
    const float* b0     = (const float*)d_in[3];
    const float* W1     = (const float*)d_in[4];
    const float* b1     = (const float*)d_in[5];
    const float* W2     = (const float*)d_in[6];
    const float* b2     = (const float*)d_in[7];
    const float* W_lin  = (const float*)d_in[8];
    const float* b_lin  = (const float*)d_in[9];
    const float* log_dt = (const float*)d_in[10];
    const float* A_re   = (const float*)d_in[11];
    const float* A_im   = (const float*)d_in[12];
    const float* C_re   = (const float*)d_in[13];
    const float* C_im   = (const float*)d_in[14];
    const float* Dv     = (const float*)d_in[15];
    const float* W_film = (const float*)d_in[16];
    const float* b_film = (const float*)d_in[17];
    float* out = (float*)d_out;

    const int smem_lin = (256 * 65 + 64 * 64) * 4;
    cudaFuncSetAttribute(k_linear, cudaFuncAttributeMaxDynamicSharedMemorySize, smem_lin);
    cudaFuncSetAttribute(k_scan_mma, cudaFuncAttributeMaxDynamicSharedMemorySize, SM_TOT);

    k_setup_tab<<<HH, 64>>>(log_dt, A_re, A_im, C_re, C_im, Dv);
    k_setup_mlp<<<1, 256>>>(cp, W0, b0, W1, b1, W2, b2, W_film, b_film);
    k_linear<<<BB * (LL / 256), 256, smem_lin>>>(x, W_lin, b_lin);
    k_scan_mma<<<BB * HH, 256, SM_TOT>>>();
    k_epilogue<<<BB * (LL / 64), 256>>>(x, out);
}

// round 7
// speedup vs baseline: 1.1832x; 1.1832x over previous
#include <cuda_runtime.h>
#include <cuda_bf16.h>
#include <cstdint>
#include <cstddef>

#define BB 16
#define LL 32768
#define HH 64
#define NN 16
#define DMM 32

typedef unsigned long long u64;
typedef uint32_t u32;
typedef __nv_bfloat16 bf16;

// strides (elements)
#define USTR 72
#define MSTR 72
#define VSTR 72
#define ESTR 40
#define SSTR 40
#define YSTR 68
#define LSTR 521

// smem byte offsets (total 225408 <= 232448)
#define SM_MH 0
#define SM_ML 9216
#define SM_VH 18432
#define SM_VL 23040
#define SM_EH 27648
#define SM_EL 32768
#define SM_UH 37888
#define SM_UL 56320
#define SM_SLOC 74752
#define SM_SINH 141440
#define SM_SINL 182400
#define SM_GBUF 223360
#define SM_TOT 225408

// ---------------- scratch ----------------
__device__ float g_u[(size_t)BB * HH * LL];
__device__ float g_z[(size_t)BB * HH * LL];
__device__ bf16 g_Mh[HH * 4096], g_Ml[HH * 4096];
__device__ bf16 g_Vh[HH * 2048], g_Vl[HH * 2048];
__device__ bf16 g_Eh[HH * 2048], g_El[HH * 2048];
__device__ float2 g_w64c[HH * 16], g_w2048c[HH * 16];
__device__ float g_gamma[BB * HH], g_beta[BB * HH];

// ---------------- helpers ----------------
__device__ __forceinline__ u64 pk(float lo, float hi) {
    u64 r; asm("mov.b64 %0, {%1,%2};" : "=l"(r) : "f"(lo), "f"(hi)); return r;
}
__device__ __forceinline__ void upk(u64 a, float& lo, float& hi) {
    asm("mov.b64 {%0,%1}, %2;" : "=f"(lo), "=f"(hi) : "l"(a));
}
__device__ __forceinline__ u64 fma2(u64 a, u64 b, u64 c) {
    u64 d; asm("fma.rn.f32x2 %0, %1, %2, %3;" : "=l"(d) : "l"(a), "l"(b), "l"(c)); return d;
}
__device__ __forceinline__ float gelu_f(float x) {
    float x3 = x * x * x;
    float z = 0.7978845608028654f * fmaf(0.044715f, x3, x);
    float az = fabsf(z);
    float e = __expf(2.0f * az);
    float t = 1.0f - __fdividef(2.0f, e + 1.0f);
    t = copysignf(t, z);
    return 0.5f * x * (1.0f + t);
}
__device__ __forceinline__ void bsplit(float v, bf16* ph, bf16* pl) {
    bf16 hi = __float2bfloat16(v);
    *ph = hi; *pl = __float2bfloat16(v - __bfloat162float(hi));
}
__device__ __forceinline__ u32 pk2bf(bf16 a, bf16 b) {
    __nv_bfloat162 v; v.x = a; v.y = b; return *reinterpret_cast<u32*>(&v);
}
__device__ __forceinline__ double2 cmul(double2 a, double2 b) {
    return make_double2(a.x * b.x - a.y * b.y, a.x * b.y + a.y * b.x);
}
__device__ __forceinline__ double2 cpow(double2 w, int e) {
    double2 r = make_double2(1.0, 0.0);
    while (e) {
        if (e & 1) r = cmul(r, w);
        w = cmul(w, w);
        e >>= 1;
    }
    return r;
}
__device__ __forceinline__ void mma16816(float* c, const u32* a, const u32* b) {
    asm volatile(
        "mma.sync.aligned.m16n8k16.row.col.f32.bf16.bf16.f32 "
        "{%0,%1,%2,%3}, {%4,%5,%6,%7}, {%8,%9}, {%0,%1,%2,%3};"
        : "+f"(c[0]), "+f"(c[1]), "+f"(c[2]), "+f"(c[3])
        : "r"(a[0]), "r"(a[1]), "r"(a[2]), "r"(a[3]), "r"(b[0]), "r"(b[1]));
}
__device__ __forceinline__ void ldA(u32* a, const bf16* base, int stride,
                                    int r0, int k0, int lane) {
    const bf16* p = base + (r0 + (lane >> 2)) * stride + k0 + (lane & 3) * 2;
    a[0] = *(const u32*)p;
    a[1] = *(const u32*)(p + 8 * stride);
    a[2] = *(const u32*)(p + 8);
    a[3] = *(const u32*)(p + 8 * stride + 8);
}
__device__ __forceinline__ void ldB(u32* b, const bf16* base, int stride,
                                    int n0, int k0, int lane) {
    const bf16* p = base + (n0 + (lane >> 2)) * stride + k0 + (lane & 3) * 2;
    b[0] = *(const u32*)p;
    b[1] = *(const u32*)(p + 8);
}
__device__ __forceinline__ void stage_u(const float4* gu4, int q,
                                        bf16* UH, bf16* UL, int t) {
    #pragma unroll
    for (int k = 0; k < 8; k++) {
        int f = t + k * 256;
        float4 v = gu4[q * 2048 + f];
        int c = f >> 4, i0 = (f & 15) * 4;
        bf16 h0 = __float2bfloat16(v.x), h1 = __float2bfloat16(v.y);
        bf16 h2 = __float2bfloat16(v.z), h3 = __float2bfloat16(v.w);
        *(u32*)&UH[c * USTR + i0] = pk2bf(h0, h1);
        *(u32*)&UH[c * USTR + i0 + 2] = pk2bf(h2, h3);
        *(u32*)&UL[c * USTR + i0] = pk2bf(
            __float2bfloat16(v.x - __bfloat162float(h0)),
            __float2bfloat16(v.y - __bfloat162float(h1)));
        *(u32*)&UL[c * USTR + i0 + 2] = pk2bf(
            __float2bfloat16(v.z - __bfloat162float(h2)),
            __float2bfloat16(v.w - __bfloat162float(h3)));
    }
}

// ---------------- K0: per-h tables (64 blocks x 64 threads) ----------------
// Transcendentals ONCE per (h,n) (16 threads); all powers via complex binpow in double.
__global__ void k_setup_tab(const float* __restrict__ log_dt,
                            const float* __restrict__ A_re, const float* __restrict__ A_im,
                            const float* __restrict__ C_re, const float* __restrict__ C_im,
                            const float* __restrict__ Dv)
{
    int h = blockIdx.x;
    int j = threadIdx.x;          // 0..63
    __shared__ double2 wd[NN];
    __shared__ double2 c2d[NN];
    __shared__ float Ks[64];

    double dt = exp((double)log_dt[h]);
    if (j < NN) {
        int i = h * NN + j;
        double ar = A_re[i], ai = A_im[i];
        double mre = dt * ar, mim = dt * ai;
        double e1 = exp(mre);
        double wr = e1 * cos(mim), wi = e1 * sin(mim);
        wd[j] = make_double2(wr, wi);
        double den = ar * ar + ai * ai;
        double nr = wr - 1.0, ni = wi;
        double qr = (nr * ar + ni * ai) / den, qi = (ni * ar - nr * ai) / den;
        double cr = C_re[i], ci = C_im[i];
        c2d[j] = make_double2(2.0 * (cr * qr - ci * qi), 2.0 * (cr * qi + ci * qr));
        // chunk-jump constants
        double2 w64 = cpow(make_double2(wr, wi), 64);
        g_w64c[h * 16 + j] = make_float2((float)w64.x, (float)w64.y);
        double2 wg = cpow(w64, 32);   // w^2048
        g_w2048c[h * 16 + j] = make_float2((float)wg.x, (float)wg.y);
    }
    __syncthreads();

    double kacc = 0.0;
    for (int n = 0; n < NN; n++) {
        double2 w = wd[n];
        double2 c2 = c2d[n];
        double2 wj = cpow(w, j);              // w^j
        kacc += c2.x * wj.x - c2.y * wj.y;    // K[j] += Re(c2 w^j)
        double2 wj1 = cmul(wj, w);            // w^{j+1}
        double er = c2.x * wj1.x - c2.y * wj1.y;
        double ei = c2.x * wj1.y + c2.y * wj1.x;
        bsplit((float)er, &g_Eh[h * 2048 + j * 32 + n], &g_El[h * 2048 + j * 32 + n]);
        bsplit((float)(-ei), &g_Eh[h * 2048 + j * 32 + 16 + n], &g_El[h * 2048 + j * 32 + 16 + n]);
        double2 wv = cpow(w, 63 - j);         // w^{63-j}
        bsplit((float)wv.x, &g_Vh[h * 2048 + n * 64 + j], &g_Vl[h * 2048 + n * 64 + j]);
        bsplit((float)wv.y, &g_Vh[h * 2048 + (16 + n) * 64 + j], &g_Vl[h * 2048 + (16 + n) * 64 + j]);
    }
    Ks[j] = (float)kacc;
    __syncthreads();

    float dD = Dv[h];
    for (int i2 = 0; i2 < 64; i2++) {
        float m = (i2 < j) ? Ks[j - i2] : (i2 == j ? Ks[0] + dD : 0.0f);
        bsplit(m, &g_Mh[h * 4096 + j * 64 + i2], &g_Ml[h * 4096 + j * 64 + i2]);
    }
}

// ---------------- K1: conditioning MLP + FiLM ----------------
__global__ void k_setup_mlp(const float* __restrict__ cp,
                            const float* __restrict__ W0, const float* __restrict__ b0,
                            const float* __restrict__ W1, const float* __restrict__ b1,
                            const float* __restrict__ W2, const float* __restrict__ b2,
                            const float* __restrict__ W_film, const float* __restrict__ b_film)
{
    __shared__ float c0[BB * DMM];
    __shared__ float c1[BB * DMM];
    int t = threadIdx.x;
    for (int i = t; i < BB * DMM; i += blockDim.x) {
        int b = i / DMM, d = i % DMM;
        float v = fmaf(cp[b * 2 + 0], W0[d], fmaf(cp[b * 2 + 1], W0[DMM + d], b0[d]));
        c0[i] = gelu_f(v);
    }
    __syncthreads();
    for (int i = t; i < BB * DMM; i += blockDim.x) {
        int b = i / DMM, d = i % DMM;
        float v = b1[d];
        for (int k = 0; k < DMM; k++) v = fmaf(c0[b * DMM + k], W1[k * DMM + d], v);
        c1[i] = gelu_f(v);
    }
    __syncthreads();
    for (int i = t; i < BB * DMM; i += blockDim.x) {
        int b = i / DMM, d = i % DMM;
        float v = b2[d];
        for (int k = 0; k < DMM; k++) v = fmaf(c1[b * DMM + k], W2[k * DMM + d], v);
        c0[i] = gelu_f(v);
    }
    __syncthreads();
    for (int i = t; i < BB * 2 * HH; i += blockDim.x) {
        int b = i / (2 * HH), j = i % (2 * HH);
        float v = b_film[j];
        for (int k = 0; k < DMM; k++) v = fmaf(c0[b * DMM + k], W_film[k * 2 * HH + j], v);
        if (j < HH) g_gamma[b * HH + j] = v;
        else        g_beta[b * HH + j - HH] = v;
    }
}

// ---------------- K2: u = gelu(x @ W_lin + b_lin) -> [B,H,L] ----------------
__global__ __launch_bounds__(256) void k_linear(const float* __restrict__ x,
                                                const float* __restrict__ W,
                                                const float* __restrict__ bias)
{
    extern __shared__ float sm2[];
    float* xs = sm2;
    float* Ws = sm2 + 256 * 65;
    int t = threadIdx.x;
    int b = blockIdx.x >> 7;
    int tile = blockIdx.x & 127;
    int l0 = tile * 256;
    const float* xg = x + ((size_t)b * LL + l0) * HH;

    for (int i = t; i < 64 * 64; i += 256) Ws[i] = W[i];
    for (int i = t; i < 256 * 64; i += 256) {
        int l = i >> 6, k = i & 63;
        xs[l * 65 + k] = xg[i];
    }
    __syncthreads();

    int li = t & 63;
    int hb = (t >> 6) * 16;
    u64 acc[4][8];
    #pragma unroll
    for (int p = 0; p < 8; p++) {
        u64 bp = *reinterpret_cast<const u64*>(bias + hb + 2 * p);
        acc[0][p] = bp; acc[1][p] = bp; acc[2][p] = bp; acc[3][p] = bp;
    }
    for (int k = 0; k < 64; k++) {
        float x0 = xs[li * 65 + k];
        float x1 = xs[(li + 64) * 65 + k];
        float x2v = xs[(li + 128) * 65 + k];
        float x3 = xs[(li + 192) * 65 + k];
        u64 xa = pk(x0, x0), xb = pk(x1, x1), xc = pk(x2v, x2v), xd = pk(x3, x3);
        const u64* wrow = reinterpret_cast<const u64*>(Ws + k * 64 + hb);
        #pragma unroll
        for (int p = 0; p < 8; p++) {
            u64 w2 = wrow[p];
            acc[0][p] = fma2(xa, w2, acc[0][p]);
            acc[1][p] = fma2(xb, w2, acc[1][p]);
            acc[2][p] = fma2(xc, w2, acc[2][p]);
            acc[3][p] = fma2(xd, w2, acc[3][p]);
        }
    }
    #pragma unroll
    for (int lg = 0; lg < 4; lg++) {
        int l = l0 + li + lg * 64;
        #pragma unroll
        for (int p = 0; p < 8; p++) {
            float v0, v1; upk(acc[lg][p], v0, v1);
            int h0 = hb + 2 * p;
            g_u[((size_t)b * HH + h0) * LL + l] = gelu_f(v0);
            g_u[((size_t)b * HH + h0 + 1) * LL + l] = gelu_f(v1);
        }
    }
}

// ---------------- K3: chunked S4 conv via bf16-split tensor-core GEMMs ----------------
__global__ __launch_bounds__(256) void k_scan_mma()
{
    extern __shared__ char smem[];
    bf16* MHs = (bf16*)(smem + SM_MH);
    bf16* MLs = (bf16*)(smem + SM_ML);
    bf16* VHs = (bf16*)(smem + SM_VH);
    bf16* VLs = (bf16*)(smem + SM_VL);
    bf16* EHs = (bf16*)(smem + SM_EH);
    bf16* ELs = (bf16*)(smem + SM_EL);
    bf16* UHs = (bf16*)(smem + SM_UH);
    bf16* ULs = (bf16*)(smem + SM_UL);
    float* SLOC = (float*)(smem + SM_SLOC);
    bf16* SINH = (bf16*)(smem + SM_SINH);
    bf16* SINL = (bf16*)(smem + SM_SINL);
    float2* GBUF = (float2*)(smem + SM_GBUF);

    int t = threadIdx.x;
    int bh = blockIdx.x;
    int h = bh & 63;
    int wid = t >> 5, lane = t & 31;

    // stage tables (insert pads)
    {
        const u32* gmh = (const u32*)(g_Mh + (size_t)h * 4096);
        const u32* gml = (const u32*)(g_Ml + (size_t)h * 4096);
        u32* smh = (u32*)MHs; u32* sml = (u32*)MLs;
        for (int i = t; i < 2048; i += 256) {
            int r = i >> 5, c = i & 31;
            smh[r * 36 + c] = gmh[i]; sml[r * 36 + c] = gml[i];
        }
        const u32* gvh = (const u32*)(g_Vh + (size_t)h * 2048);
        const u32* gvl = (const u32*)(g_Vl + (size_t)h * 2048);
        u32* svh = (u32*)VHs; u32* svl = (u32*)VLs;
        for (int i = t; i < 1024; i += 256) {
            int r = i >> 5, c = i & 31;
            svh[r * 36 + c] = gvh[i]; svl[r * 36 + c] = gvl[i];
        }
        const u32* geh = (const u32*)(g_Eh + (size_t)h * 2048);
        const u32* gel = (const u32*)(g_El + (size_t)h * 2048);
        u32* seh = (u32*)EHs; u32* sel = (u32*)ELs;
        for (int i = t; i < 1024; i += 256) {
            int r = i >> 4, c = i & 15;
            seh[r * 20 + c] = geh[i]; sel[r * 20 + c] = gel[i];
        }
    }
    __syncthreads();

    const float4* gu4 = (const float4*)(g_u + (size_t)bh * LL);

    // ---- pass 1: S_local = V @ U ----
    for (int q = 0; q < 4; q++) {
        stage_u(gu4, q, UHs, ULs, t);
        __syncthreads();
        int cloc = wid * 16, cglob = q * 128 + cloc;
        float C1[2][2][4] = {};
        #pragma unroll
        for (int kt = 0; kt < 4; kt++) {
            int k0 = kt * 16;
            u32 bh_[2][2], bl_[2][2];
            #pragma unroll
            for (int nt = 0; nt < 2; nt++) {
                ldB(bh_[nt], UHs, USTR, cloc + nt * 8, k0, lane);
                ldB(bl_[nt], ULs, USTR, cloc + nt * 8, k0, lane);
            }
            #pragma unroll
            for (int mt = 0; mt < 2; mt++) {
                u32 ah[4], al[4];
                ldA(ah, VHs, VSTR, mt * 16, k0, lane);
                ldA(al, VLs, VSTR, mt * 16, k0, lane);
                #pragma unroll
                for (int nt = 0; nt < 2; nt++) {
                    mma16816(C1[mt][nt], ah, bh_[nt]);
                    mma16816(C1[mt][nt], ah, bl_[nt]);
                    mma16816(C1[mt][nt], al, bh_[nt]);
                }
            }
        }
        #pragma unroll
        for (int mt = 0; mt < 2; mt++)
            #pragma unroll
            for (int nt = 0; nt < 2; nt++) {
                int r = mt * 16 + (lane >> 2);
                int cc = cglob + nt * 8 + (lane & 3) * 2;
                SLOC[r * LSTR + cc] = C1[mt][nt][0];
                SLOC[r * LSTR + cc + 1] = C1[mt][nt][1];
                SLOC[(r + 8) * LSTR + cc] = C1[mt][nt][2];
                SLOC[(r + 8) * LSTR + cc + 1] = C1[mt][nt][3];
            }
        __syncthreads();
    }

    // ---- chunk-state scan (512 chunks = 16 groups x 32) ----
    {
        int n = t & 15, g = t >> 4;
        float2 w64 = g_w64c[h * 16 + n];
        float sr = 0.f, si = 0.f;
        for (int m = 0; m < 32; m++) {
            int c = g * 32 + m;
            float xr = SLOC[n * LSTR + c], xi = SLOC[(16 + n) * LSTR + c];
            float nr = fmaf(w64.x, sr, fmaf(-w64.y, si, xr));
            si = fmaf(w64.x, si, fmaf(w64.y, sr, xi));
            sr = nr;
        }
        GBUF[g * 16 + n] = make_float2(sr, si);
        __syncthreads();
        if (t < 16) {
            float2 wG = g_w2048c[h * 16 + t];
            float pr = 0.f, pi = 0.f;
            for (int gg = 0; gg < 16; gg++) {
                float2 tm = GBUF[gg * 16 + t];
                GBUF[gg * 16 + t] = make_float2(pr, pi);
                float nr = fmaf(wG.x, pr, fmaf(-wG.y, pi, tm.x));
                pi = fmaf(wG.x, pi, fmaf(wG.y, pr, tm.y));
                pr = nr;
            }
        }
        __syncthreads();
        float2 I = GBUF[g * 16 + n];
        sr = I.x; si = I.y;
        for (int m = 0; m < 32; m++) {
            int c = g * 32 + m;
            bsplit(sr, &SINH[c * SSTR + n], &SINL[c * SSTR + n]);
            bsplit(si, &SINH[c * SSTR + 16 + n], &SINL[c * SSTR + 16 + n]);
            float xr = SLOC[n * LSTR + c], xi = SLOC[(16 + n) * LSTR + c];
            float nr = fmaf(w64.x, sr, fmaf(-w64.y, si, xr));
            si = fmaf(w64.x, si, fmaf(w64.y, sr, xi));
            sr = nr;
        }
        __syncthreads();
    }

    // ---- pass 2: Y = M@U + E@S_in, FiLM, writeback ----
    float gam = g_gamma[bh];
    float bet = g_beta[bh];
    float* Ys = SLOC;        // reuse
    float4* gz4 = (float4*)(g_z + (size_t)bh * LL);

    for (int q = 0; q < 4; q++) {
        stage_u(gu4, q, UHs, ULs, t);
        __syncthreads();
        int cloc = wid * 16, cglob = q * 128 + cloc;
        float C2[4][2][4] = {};
        #pragma unroll
        for (int kt = 0; kt < 4; kt++) {
            int k0 = kt * 16;
            u32 bh_[2][2], bl_[2][2];
            #pragma unroll
            for (int nt = 0; nt < 2; nt++) {
                ldB(bh_[nt], UHs, USTR, cloc + nt * 8, k0, lane);
                ldB(bl_[nt], ULs, USTR, cloc + nt * 8, k0, lane);
            }
            #pragma unroll
            for (int mt = 0; mt < 4; mt++) {
                if (kt > mt) continue;
                u32 ah[4], al[4];
                ldA(ah, MHs, MSTR, mt * 16, k0, lane);
                ldA(al, MLs, MSTR, mt * 16, k0, lane);
                #pragma unroll
                for (int nt = 0; nt < 2; nt++) {
                    mma16816(C2[mt][nt], ah, bh_[nt]);
                    mma16816(C2[mt][nt], ah, bl_[nt]);
                    mma16816(C2[mt][nt], al, bh_[nt]);
                }
            }
        }
        #pragma unroll
        for (int kt = 0; kt < 2; kt++) {
            int k0 = kt * 16;
            u32 bh_[2][2], bl_[2][2];
            #pragma unroll
            for (int nt = 0; nt < 2; nt++) {
                ldB(bh_[nt], SINH, SSTR, cglob + nt * 8, k0, lane);
                ldB(bl_[nt], SINL, SSTR, cglob + nt * 8, k0, lane);
            }
            #pragma unroll
            for (int mt = 0; mt < 4; mt++) {
                u32 ah[4], al[4];
                ldA(ah, EHs, ESTR, mt * 16, k0, lane);
                ldA(al, ELs, ESTR, mt * 16, k0, lane);
                #pragma unroll
                for (int nt = 0; nt < 2; nt++) {
                    mma16816(C2[mt][nt], ah, bh_[nt]);
                    mma16816(C2[mt][nt], ah, bl_[nt]);
                    mma16816(C2[mt][nt], al, bh_[nt]);
                }
            }
        }
        __syncthreads();
        #pragma unroll
        for (int mt = 0; mt < 4; mt++)
            #pragma unroll
            for (int nt = 0; nt < 2; nt++) {
                int j = mt * 16 + (lane >> 2);
                int cc = cloc + nt * 8 + (lane & 3) * 2;
                Ys[cc * YSTR + j] = fmaf(C2[mt][nt][0], gam, bet);
                Ys[(cc + 1) * YSTR + j] = fmaf(C2[mt][nt][1], gam, bet);
                Ys[cc * YSTR + j + 8] = fmaf(C2[mt][nt][2], gam, bet);
                Ys[(cc + 1) * YSTR + j + 8] = fmaf(C2[mt][nt][3], gam, bet);
            }
        __syncthreads();
        #pragma unroll
        for (int k = 0; k < 8; k++) {
            int f = t + k * 256;
            int c = f >> 4, qq = f & 15;
            float4 o = *(const float4*)&Ys[c * YSTR + qq * 4];
            gz4[q * 2048 + f] = o;
        }
        __syncthreads();
    }
}

// ---------------- K4: out = x * gelu(z) ----------------
__global__ __launch_bounds__(256) void k_epilogue(const float* __restrict__ x,
                                                  float* __restrict__ out)
{
    __shared__ float zt[64 * 65];
    int t = threadIdx.x;
    int b = blockIdx.x >> 9;
    int tile = blockIdx.x & 511;
    int l0 = tile * 64;
    #pragma unroll
    for (int i = t; i < 1024; i += 256) {
        int hh = i >> 4, q = i & 15;
        float4 v = *reinterpret_cast<const float4*>(
            g_z + ((size_t)b * HH + hh) * LL + l0 + 4 * q);
        float* d = zt + hh * 65 + 4 * q;
        d[0] = v.x; d[1] = v.y; d[2] = v.z; d[3] = v.w;
    }
    __syncthreads();
    #pragma unroll
    for (int i = t; i < 1024; i += 256) {
        int l = i >> 4, hq = i & 15;
        float z0 = zt[(4 * hq + 0) * 65 + l];
        float z1 = zt[(4 * hq + 1) * 65 + l];
        float z2 = zt[(4 * hq + 2) * 65 + l];
        float z3 = zt[(4 * hq + 3) * 65 + l];
        size_t base = ((size_t)b * LL + l0 + l) * HH + 4 * hq;
        float4 xv = *reinterpret_cast<const float4*>(x + base);
        float4 o;
        o.x = xv.x * gelu_f(z0);
        o.y = xv.y * gelu_f(z1);
        o.z = xv.z * gelu_f(z2);
        o.w = xv.w * gelu_f(z3);
        *reinterpret_cast<float4*>(out + base) = o;
    }
}

// ---------------- launch ----------------
extern "C" void kernel_launch(void* const* d_in, const int* in_sizes, int n_in,
                              void* d_out, int out_size)
{
    const float* x      = (const float*)d_in[0];
    const float* cp     = (const float*)d_in[1];
    const float* W0     = (const float*)d_in[2];
    const float* b0     = (const float*)d_in[3];
    const float* W1     = (const float*)d_in[4];
    const float* b1     = (const float*)d_in[5];
    const float* W2     = (const float*)d_in[6];
    const float* b2     = (const float*)d_in[7];
    const float* W_lin  = (const float*)d_in[8];
    const float* b_lin  = (const float*)d_in[9];
    const float* log_dt = (const float*)d_in[10];
    const float* A_re   = (const float*)d_in[11];
    const float* A_im   = (const float*)d_in[12];
    const float* C_re   = (const float*)d_in[13];
    const float* C_im   = (const float*)d_in[14];
    const float* Dv     = (const float*)d_in[15];
    const float* W_film = (const float*)d_in[16];
    const float* b_film = (const float*)d_in[17];
    float* out = (float*)d_out;

    const int smem_lin = (256 * 65 + 64 * 64) * 4;
    cudaFuncSetAttribute(k_linear, cudaFuncAttributeMaxDynamicSharedMemorySize, smem_lin);
    cudaFuncSetAttribute(k_scan_mma, cudaFuncAttributeMaxDynamicSharedMemorySize, SM_TOT);

    k_setup_tab<<<HH, 64>>>(log_dt, A_re, A_im, C_re, C_im, Dv);
    k_setup_mlp<<<1, 256>>>(cp, W0, b0, W1, b1, W2, b2, W_film, b_film);
    k_linear<<<BB * (LL / 256), 256, smem_lin>>>(x, W_lin, b_lin);
    k_scan_mma<<<BB * HH, 256, SM_TOT>>>();
    k_epilogue<<<BB * (LL / 64), 256>>>(x, out);
}

// round 8
// speedup vs baseline: 1.4298x; 1.2084x over previous
#include <cuda_runtime.h>
#include <cuda_bf16.h>
#include <cstdint>
#include <cstddef>

#define BB 16
#define LL 32768
#define HH 64
#define NN 16
#define DMM 32

typedef unsigned long long u64;
typedef uint32_t u32;
typedef __nv_bfloat16 bf16;

// strides (elements)
#define USTR 72
#define MSTR 72
#define VSTR 72
#define ESTR 40
#define SSTR 40
#define YSTR 68
#define LSTR 521

// scan smem byte offsets (total 225408)
#define SM_MH 0
#define SM_ML 9216
#define SM_VH 18432
#define SM_VL 23040
#define SM_EH 27648
#define SM_EL 32768
#define SM_UH 37888
#define SM_UL 56320
#define SM_SLOC 74752
#define SM_SINH 141440
#define SM_SINL 182400
#define SM_GBUF 223360
#define SM_TOT 225408

// linear-mma smem layout (bytes): WtH 9216 | WtL 9216 | bias 256 | XH 36864 | XL 36864 | Ys 67584
#define LM_WTH 0
#define LM_WTL 9216
#define LM_BS 18432
#define LM_XH 18688
#define LM_XL 55552
#define LM_YS 92416
#define LM_TOT 160000
#define XSTR 72
#define WSTR 72
#define YL 264

// ---------------- scratch ----------------
__device__ float g_u[(size_t)BB * HH * LL];
__device__ float g_z[(size_t)BB * HH * LL];
__device__ bf16 g_Mh[HH * 4096], g_Ml[HH * 4096];
__device__ bf16 g_Vh[HH * 2048], g_Vl[HH * 2048];
__device__ bf16 g_Eh[HH * 2048], g_El[HH * 2048];
__device__ float2 g_w64c[HH * 16], g_w2048c[HH * 16];
__device__ float g_gamma[BB * HH], g_beta[BB * HH];

// ---------------- helpers ----------------
__device__ __forceinline__ float gelu_f(float x) {
    float x3 = x * x * x;
    float z = 0.7978845608028654f * fmaf(0.044715f, x3, x);
    float az = fabsf(z);
    float e = __expf(2.0f * az);
    float t = 1.0f - __fdividef(2.0f, e + 1.0f);
    t = copysignf(t, z);
    return 0.5f * x * (1.0f + t);
}
__device__ __forceinline__ void bsplit(float v, bf16* ph, bf16* pl) {
    bf16 hi = __float2bfloat16(v);
    *ph = hi; *pl = __float2bfloat16(v - __bfloat162float(hi));
}
__device__ __forceinline__ u32 pk2bf(bf16 a, bf16 b) {
    __nv_bfloat162 v; v.x = a; v.y = b; return *reinterpret_cast<u32*>(&v);
}
__device__ __forceinline__ float2 cmulf(float2 a, float2 b) {
    return make_float2(a.x * b.x - a.y * b.y, a.x * b.y + a.y * b.x);
}
__device__ __forceinline__ float2 cpowf(float2 w, int e) {
    float2 r = make_float2(1.0f, 0.0f);
    while (e) {
        if (e & 1) r = cmulf(r, w);
        w = cmulf(w, w);
        e >>= 1;
    }
    return r;
}
__device__ __forceinline__ void mma16816(float* c, const u32* a, const u32* b) {
    asm volatile(
        "mma.sync.aligned.m16n8k16.row.col.f32.bf16.bf16.f32 "
        "{%0,%1,%2,%3}, {%4,%5,%6,%7}, {%8,%9}, {%0,%1,%2,%3};"
        : "+f"(c[0]), "+f"(c[1]), "+f"(c[2]), "+f"(c[3])
        : "r"(a[0]), "r"(a[1]), "r"(a[2]), "r"(a[3]), "r"(b[0]), "r"(b[1]));
}
__device__ __forceinline__ void ldA(u32* a, const bf16* base, int stride,
                                    int r0, int k0, int lane) {
    const bf16* p = base + (r0 + (lane >> 2)) * stride + k0 + (lane & 3) * 2;
    a[0] = *(const u32*)p;
    a[1] = *(const u32*)(p + 8 * stride);
    a[2] = *(const u32*)(p + 8);
    a[3] = *(const u32*)(p + 8 * stride + 8);
}
__device__ __forceinline__ void ldB(u32* b, const bf16* base, int stride,
                                    int n0, int k0, int lane) {
    const bf16* p = base + (n0 + (lane >> 2)) * stride + k0 + (lane & 3) * 2;
    b[0] = *(const u32*)p;
    b[1] = *(const u32*)(p + 8);
}
__device__ __forceinline__ void split_store4(float4 v, bf16* H, bf16* L, int off) {
    bf16 h0 = __float2bfloat16(v.x), h1 = __float2bfloat16(v.y);
    bf16 h2 = __float2bfloat16(v.z), h3 = __float2bfloat16(v.w);
    *(u32*)&H[off] = pk2bf(h0, h1);
    *(u32*)&H[off + 2] = pk2bf(h2, h3);
    *(u32*)&L[off] = pk2bf(
        __float2bfloat16(v.x - __bfloat162float(h0)),
        __float2bfloat16(v.y - __bfloat162float(h1)));
    *(u32*)&L[off + 2] = pk2bf(
        __float2bfloat16(v.z - __bfloat162float(h2)),
        __float2bfloat16(v.w - __bfloat162float(h3)));
}
__device__ __forceinline__ void stage_u(const float4* gu4, int q,
                                        bf16* UH, bf16* UL, int t) {
    #pragma unroll
    for (int k = 0; k < 8; k++) {
        int f = t + k * 256;
        float4 v = gu4[q * 2048 + f];
        int c = f >> 4, i0 = (f & 15) * 4;
        split_store4(v, UH, UL, c * USTR + i0);
    }
}

// ---------------- K0: per-h tables; DP transcendentals once per (h,n), fp32 binpow ----------------
__global__ void k_setup_tab(const float* __restrict__ log_dt,
                            const float* __restrict__ A_re, const float* __restrict__ A_im,
                            const float* __restrict__ C_re, const float* __restrict__ C_im,
                            const float* __restrict__ Dv)
{
    int h = blockIdx.x;
    int j = threadIdx.x;          // 0..63
    __shared__ float2 wf[NN];
    __shared__ float2 c2f[NN];
    __shared__ float Ks[64];

    double dt = exp((double)log_dt[h]);
    if (j < NN) {
        int i = h * NN + j;
        float ar = A_re[i], ai = A_im[i];
        double mre = dt * (double)ar, mim = dt * (double)ai;
        double e1 = exp(mre);
        float wr = (float)(e1 * cos(mim)), wi = (float)(e1 * sin(mim));
        wf[j] = make_float2(wr, wi);
        float den = ar * ar + ai * ai;
        float nr = wr - 1.0f, ni = wi;
        float qr = (nr * ar + ni * ai) / den, qi = (ni * ar - nr * ai) / den;
        float cr = C_re[i], ci = C_im[i];
        c2f[j] = make_float2(2.0f * (cr * qr - ci * qi), 2.0f * (cr * qi + ci * qr));
        float2 w64 = cpowf(make_float2(wr, wi), 64);
        g_w64c[h * 16 + j] = w64;
        g_w2048c[h * 16 + j] = cpowf(w64, 32);
    }
    __syncthreads();

    float kacc = 0.0f;
    for (int n = 0; n < NN; n++) {
        float2 w = wf[n];
        float2 c2 = c2f[n];
        float2 wj = cpowf(w, j);
        kacc += c2.x * wj.x - c2.y * wj.y;
        float2 wj1 = cmulf(wj, w);
        bsplit(c2.x * wj1.x - c2.y * wj1.y,
               &g_Eh[h * 2048 + j * 32 + n], &g_El[h * 2048 + j * 32 + n]);
        bsplit(-(c2.x * wj1.y + c2.y * wj1.x),
               &g_Eh[h * 2048 + j * 32 + 16 + n], &g_El[h * 2048 + j * 32 + 16 + n]);
        float2 wv = cpowf(w, 63 - j);
        bsplit(wv.x, &g_Vh[h * 2048 + n * 64 + j], &g_Vl[h * 2048 + n * 64 + j]);
        bsplit(wv.y, &g_Vh[h * 2048 + (16 + n) * 64 + j], &g_Vl[h * 2048 + (16 + n) * 64 + j]);
    }
    Ks[j] = kacc;
    __syncthreads();

    float dD = Dv[h];
    for (int i2 = 0; i2 < 64; i2++) {
        float m = (i2 < j) ? Ks[j - i2] : (i2 == j ? Ks[0] + dD : 0.0f);
        bsplit(m, &g_Mh[h * 4096 + j * 64 + i2], &g_Ml[h * 4096 + j * 64 + i2]);
    }
}

// ---------------- K1: conditioning MLP + FiLM ----------------
__global__ void k_setup_mlp(const float* __restrict__ cp,
                            const float* __restrict__ W0, const float* __restrict__ b0,
                            const float* __restrict__ W1, const float* __restrict__ b1,
                            const float* __restrict__ W2, const float* __restrict__ b2,
                            const float* __restrict__ W_film, const float* __restrict__ b_film)
{
    __shared__ float c0[BB * DMM];
    __shared__ float c1[BB * DMM];
    int t = threadIdx.x;
    for (int i = t; i < BB * DMM; i += blockDim.x) {
        int b = i / DMM, d = i % DMM;
        float v = fmaf(cp[b * 2 + 0], W0[d], fmaf(cp[b * 2 + 1], W0[DMM + d], b0[d]));
        c0[i] = gelu_f(v);
    }
    __syncthreads();
    for (int i = t; i < BB * DMM; i += blockDim.x) {
        int b = i / DMM, d = i % DMM;
        float v = b1[d];
        for (int k = 0; k < DMM; k++) v = fmaf(c0[b * DMM + k], W1[k * DMM + d], v);
        c1[i] = gelu_f(v);
    }
    __syncthreads();
    for (int i = t; i < BB * DMM; i += blockDim.x) {
        int b = i / DMM, d = i % DMM;
        float v = b2[d];
        for (int k = 0; k < DMM; k++) v = fmaf(c1[b * DMM + k], W2[k * DMM + d], v);
        c0[i] = gelu_f(v);
    }
    __syncthreads();
    for (int i = t; i < BB * 2 * HH; i += blockDim.x) {
        int b = i / (2 * HH), j = i % (2 * HH);
        float v = b_film[j];
        for (int k = 0; k < DMM; k++) v = fmaf(c0[b * DMM + k], W_film[k * 2 * HH + j], v);
        if (j < HH) g_gamma[b * HH + j] = v;
        else        g_beta[b * HH + j - HH] = v;
    }
}

// ---------------- K2: u = gelu(x @ W_lin + b_lin) via bf16-split MMA -> [B,H,L] ----------------
__global__ __launch_bounds__(256) void k_linear_mma(const float* __restrict__ x,
                                                    const float* __restrict__ W,
                                                    const float* __restrict__ bias)
{
    extern __shared__ char sm[];
    bf16* WtH = (bf16*)(sm + LM_WTH);   // [64 h][72 k]
    bf16* WtL = (bf16*)(sm + LM_WTL);
    float* bs = (float*)(sm + LM_BS);   // [64]
    bf16* XH = (bf16*)(sm + LM_XH);     // [256 l][72 k]
    bf16* XL = (bf16*)(sm + LM_XL);
    float* Ys = (float*)(sm + LM_YS);   // [64 h][264 l]

    int t = threadIdx.x, wid = t >> 5, lane = t & 31;
    int b = blockIdx.x >> 7, tile = blockIdx.x & 127;
    int l0 = tile * 256;

    // stage W transposed + split; bias
    for (int i = t; i < 4096; i += 256) {
        int k = i >> 6, h = i & 63;
        bsplit(W[i], &WtH[h * WSTR + k], &WtL[h * WSTR + k]);
    }
    if (t < 64) bs[t] = bias[t];
    // stage x split
    const float4* xg4 = (const float4*)(x + ((size_t)b * LL + l0) * HH);
    #pragma unroll
    for (int kk = 0; kk < 16; kk++) {
        int f = t + kk * 256;          // 0..4095
        float4 v = xg4[f];
        int l = f >> 4, i0 = (f & 15) * 4;
        split_store4(v, XH, XL, l * XSTR + i0);
    }
    __syncthreads();

    // warp tile: 32 l x 64 h
    float C[2][8][4];
    #pragma unroll
    for (int mt = 0; mt < 2; mt++)
        #pragma unroll
        for (int nt = 0; nt < 8; nt++) {
            int c0 = nt * 8 + (lane & 3) * 2;
            C[mt][nt][0] = bs[c0]; C[mt][nt][1] = bs[c0 + 1];
            C[mt][nt][2] = bs[c0]; C[mt][nt][3] = bs[c0 + 1];
        }
    #pragma unroll
    for (int kt = 0; kt < 4; kt++) {
        int k0 = kt * 16;
        u32 bhf[8][2], blf[8][2];
        #pragma unroll
        for (int nt = 0; nt < 8; nt++) {
            ldB(bhf[nt], WtH, WSTR, nt * 8, k0, lane);
            ldB(blf[nt], WtL, WSTR, nt * 8, k0, lane);
        }
        #pragma unroll
        for (int mt = 0; mt < 2; mt++) {
            u32 ah[4], al[4];
            ldA(ah, XH, XSTR, wid * 32 + mt * 16, k0, lane);
            ldA(al, XL, XSTR, wid * 32 + mt * 16, k0, lane);
            #pragma unroll
            for (int nt = 0; nt < 8; nt++) {
                mma16816(C[mt][nt], ah, bhf[nt]);
                mma16816(C[mt][nt], ah, blf[nt]);
                mma16816(C[mt][nt], al, bhf[nt]);
            }
        }
    }
    // gelu + transpose into Ys[h][l]
    #pragma unroll
    for (int mt = 0; mt < 2; mt++)
        #pragma unroll
        for (int nt = 0; nt < 8; nt++) {
            int l = wid * 32 + mt * 16 + (lane >> 2);
            int h0 = nt * 8 + (lane & 3) * 2;
            Ys[h0 * YL + l] = gelu_f(C[mt][nt][0]);
            Ys[(h0 + 1) * YL + l] = gelu_f(C[mt][nt][1]);
            Ys[h0 * YL + l + 8] = gelu_f(C[mt][nt][2]);
            Ys[(h0 + 1) * YL + l + 8] = gelu_f(C[mt][nt][3]);
        }
    __syncthreads();
    // coalesced write to g_u [B,H,L]
    #pragma unroll
    for (int i = t; i < 4096; i += 256) {
        int h = i >> 6, q = i & 63;
        float4 v = *(const float4*)&Ys[h * YL + q * 4];
        *(float4*)(g_u + ((size_t)b * HH + h) * LL + l0 + q * 4) = v;
    }
}

// ---------------- K3: chunked S4 conv via bf16-split tensor-core GEMMs ----------------
__global__ __launch_bounds__(256) void k_scan_mma()
{
    extern __shared__ char smem[];
    bf16* MHs = (bf16*)(smem + SM_MH);
    bf16* MLs = (bf16*)(smem + SM_ML);
    bf16* VHs = (bf16*)(smem + SM_VH);
    bf16* VLs = (bf16*)(smem + SM_VL);
    bf16* EHs = (bf16*)(smem + SM_EH);
    bf16* ELs = (bf16*)(smem + SM_EL);
    bf16* UHs = (bf16*)(smem + SM_UH);
    bf16* ULs = (bf16*)(smem + SM_UL);
    float* SLOC = (float*)(smem + SM_SLOC);
    bf16* SINH = (bf16*)(smem + SM_SINH);
    bf16* SINL = (bf16*)(smem + SM_SINL);
    float2* GBUF = (float2*)(smem + SM_GBUF);

    int t = threadIdx.x;
    int bh = blockIdx.x;
    int h = bh & 63;
    int wid = t >> 5, lane = t & 31;

    {
        const u32* gmh = (const u32*)(g_Mh + (size_t)h * 4096);
        const u32* gml = (const u32*)(g_Ml + (size_t)h * 4096);
        u32* smh = (u32*)MHs; u32* sml = (u32*)MLs;
        for (int i = t; i < 2048; i += 256) {
            int r = i >> 5, c = i & 31;
            smh[r * 36 + c] = gmh[i]; sml[r * 36 + c] = gml[i];
        }
        const u32* gvh = (const u32*)(g_Vh + (size_t)h * 2048);
        const u32* gvl = (const u32*)(g_Vl + (size_t)h * 2048);
        u32* svh = (u32*)VHs; u32* svl = (u32*)VLs;
        for (int i = t; i < 1024; i += 256) {
            int r = i >> 5, c = i & 31;
            svh[r * 36 + c] = gvh[i]; svl[r * 36 + c] = gvl[i];
        }
        const u32* geh = (const u32*)(g_Eh + (size_t)h * 2048);
        const u32* gel = (const u32*)(g_El + (size_t)h * 2048);
        u32* seh = (u32*)EHs; u32* sel = (u32*)ELs;
        for (int i = t; i < 1024; i += 256) {
            int r = i >> 4, c = i & 15;
            seh[r * 20 + c] = geh[i]; sel[r * 20 + c] = gel[i];
        }
    }
    __syncthreads();

    const float4* gu4 = (const float4*)(g_u + (size_t)bh * LL);

    // ---- pass 1: S_local = V @ U ----
    for (int q = 0; q < 4; q++) {
        stage_u(gu4, q, UHs, ULs, t);
        __syncthreads();
        int cloc = wid * 16, cglob = q * 128 + cloc;
        float C1[2][2][4] = {};
        #pragma unroll
        for (int kt = 0; kt < 4; kt++) {
            int k0 = kt * 16;
            u32 bh_[2][2], bl_[2][2];
            #pragma unroll
            for (int nt = 0; nt < 2; nt++) {
                ldB(bh_[nt], UHs, USTR, cloc + nt * 8, k0, lane);
                ldB(bl_[nt], ULs, USTR, cloc + nt * 8, k0, lane);
            }
            #pragma unroll
            for (int mt = 0; mt < 2; mt++) {
                u32 ah[4], al[4];
                ldA(ah, VHs, VSTR, mt * 16, k0, lane);
                ldA(al, VLs, VSTR, mt * 16, k0, lane);
                #pragma unroll
                for (int nt = 0; nt < 2; nt++) {
                    mma16816(C1[mt][nt], ah, bh_[nt]);
                    mma16816(C1[mt][nt], ah, bl_[nt]);
                    mma16816(C1[mt][nt], al, bh_[nt]);
                }
            }
        }
        #pragma unroll
        for (int mt = 0; mt < 2; mt++)
            #pragma unroll
            for (int nt = 0; nt < 2; nt++) {
                int r = mt * 16 + (lane >> 2);
                int cc = cglob + nt * 8 + (lane & 3) * 2;
                SLOC[r * LSTR + cc] = C1[mt][nt][0];
                SLOC[r * LSTR + cc + 1] = C1[mt][nt][1];
                SLOC[(r + 8) * LSTR + cc] = C1[mt][nt][2];
                SLOC[(r + 8) * LSTR + cc + 1] = C1[mt][nt][3];
            }
        __syncthreads();
    }

    // ---- chunk-state scan ----
    {
        int n = t & 15, g = t >> 4;
        float2 w64 = g_w64c[h * 16 + n];
        float sr = 0.f, si = 0.f;
        for (int m = 0; m < 32; m++) {
            int c = g * 32 + m;
            float xr = SLOC[n * LSTR + c], xi = SLOC[(16 + n) * LSTR + c];
            float nr = fmaf(w64.x, sr, fmaf(-w64.y, si, xr));
            si = fmaf(w64.x, si, fmaf(w64.y, sr, xi));
            sr = nr;
        }
        GBUF[g * 16 + n] = make_float2(sr, si);
        __syncthreads();
        if (t < 16) {
            float2 wG = g_w2048c[h * 16 + t];
            float pr = 0.f, pi = 0.f;
            for (int gg = 0; gg < 16; gg++) {
                float2 tm = GBUF[gg * 16 + t];
                GBUF[gg * 16 + t] = make_float2(pr, pi);
                float nr = fmaf(wG.x, pr, fmaf(-wG.y, pi, tm.x));
                pi = fmaf(wG.x, pi, fmaf(wG.y, pr, tm.y));
                pr = nr;
            }
        }
        __syncthreads();
        float2 I = GBUF[g * 16 + n];
        sr = I.x; si = I.y;
        for (int m = 0; m < 32; m++) {
            int c = g * 32 + m;
            bsplit(sr, &SINH[c * SSTR + n], &SINL[c * SSTR + n]);
            bsplit(si, &SINH[c * SSTR + 16 + n], &SINL[c * SSTR + 16 + n]);
            float xr = SLOC[n * LSTR + c], xi = SLOC[(16 + n) * LSTR + c];
            float nr = fmaf(w64.x, sr, fmaf(-w64.y, si, xr));
            si = fmaf(w64.x, si, fmaf(w64.y, sr, xi));
            sr = nr;
        }
        __syncthreads();
    }

    // ---- pass 2: Y = M@U + E@S_in, FiLM, writeback ----
    float gam = g_gamma[bh];
    float bet = g_beta[bh];
    float* Ys = SLOC;
    float4* gz4 = (float4*)(g_z + (size_t)bh * LL);

    for (int q = 0; q < 4; q++) {
        stage_u(gu4, q, UHs, ULs, t);
        __syncthreads();
        int cloc = wid * 16, cglob = q * 128 + cloc;
        float C2[4][2][4] = {};
        #pragma unroll
        for (int kt = 0; kt < 4; kt++) {
            int k0 = kt * 16;
            u32 bh_[2][2], bl_[2][2];
            #pragma unroll
            for (int nt = 0; nt < 2; nt++) {
                ldB(bh_[nt], UHs, USTR, cloc + nt * 8, k0, lane);
                ldB(bl_[nt], ULs, USTR, cloc + nt * 8, k0, lane);
            }
            #pragma unroll
            for (int mt = 0; mt < 4; mt++) {
                if (kt > mt) continue;
                u32 ah[4], al[4];
                ldA(ah, MHs, MSTR, mt * 16, k0, lane);
                ldA(al, MLs, MSTR, mt * 16, k0, lane);
                #pragma unroll
                for (int nt = 0; nt < 2; nt++) {
                    mma16816(C2[mt][nt], ah, bh_[nt]);
                    mma16816(C2[mt][nt], ah, bl_[nt]);
                    mma16816(C2[mt][nt], al, bh_[nt]);
                }
            }
        }
        #pragma unroll
        for (int kt = 0; kt < 2; kt++) {
            int k0 = kt * 16;
            u32 bh_[2][2], bl_[2][2];
            #pragma unroll
            for (int nt = 0; nt < 2; nt++) {
                ldB(bh_[nt], SINH, SSTR, cglob + nt * 8, k0, lane);
                ldB(bl_[nt], SINL, SSTR, cglob + nt * 8, k0, lane);
            }
            #pragma unroll
            for (int mt = 0; mt < 4; mt++) {
                u32 ah[4], al[4];
                ldA(ah, EHs, ESTR, mt * 16, k0, lane);
                ldA(al, ELs, ESTR, mt * 16, k0, lane);
                #pragma unroll
                for (int nt = 0; nt < 2; nt++) {
                    mma16816(C2[mt][nt], ah, bh_[nt]);
                    mma16816(C2[mt][nt], ah, bl_[nt]);
                    mma16816(C2[mt][nt], al, bh_[nt]);
                }
            }
        }
        __syncthreads();
        #pragma unroll
        for (int mt = 0; mt < 4; mt++)
            #pragma unroll
            for (int nt = 0; nt < 2; nt++) {
                int j = mt * 16 + (lane >> 2);
                int cc = cloc + nt * 8 + (lane & 3) * 2;
                Ys[cc * YSTR + j] = fmaf(C2[mt][nt][0], gam, bet);
                Ys[(cc + 1) * YSTR + j] = fmaf(C2[mt][nt][1], gam, bet);
                Ys[cc * YSTR + j + 8] = fmaf(C2[mt][nt][2], gam, bet);
                Ys[(cc + 1) * YSTR + j + 8] = fmaf(C2[mt][nt][3], gam, bet);
            }
        __syncthreads();
        #pragma unroll
        for (int k = 0; k < 8; k++) {
            int f = t + k * 256;
            int c = f >> 4, qq = f & 15;
            float4 o = *(const float4*)&Ys[c * YSTR + qq * 4];
            gz4[q * 2048 + f] = o;
        }
        __syncthreads();
    }
}

// ---------------- K4: out = x * gelu(z) ----------------
__global__ __launch_bounds__(256) void k_epilogue(const float* __restrict__ x,
                                                  float* __restrict__ out)
{
    __shared__ float zt[64 * 65];
    int t = threadIdx.x;
    int b = blockIdx.x >> 9;
    int tile = blockIdx.x & 511;
    int l0 = tile * 64;
    #pragma unroll
    for (int i = t; i < 1024; i += 256) {
        int hh = i >> 4, q = i & 15;
        float4 v = *reinterpret_cast<const float4*>(
            g_z + ((size_t)b * HH + hh) * LL + l0 + 4 * q);
        float* d = zt + hh * 65 + 4 * q;
        d[0] = v.x; d[1] = v.y; d[2] = v.z; d[3] = v.w;
    }
    __syncthreads();
    #pragma unroll
    for (int i = t; i < 1024; i += 256) {
        int l = i >> 4, hq = i & 15;
        float z0 = zt[(4 * hq + 0) * 65 + l];
        float z1 = zt[(4 * hq + 1) * 65 + l];
        float z2 = zt[(4 * hq + 2) * 65 + l];
        float z3 = zt[(4 * hq + 3) * 65 + l];
        size_t base = ((size_t)b * LL + l0 + l) * HH + 4 * hq;
        float4 xv = *reinterpret_cast<const float4*>(x + base);
        float4 o;
        o.x = xv.x * gelu_f(z0);
        o.y = xv.y * gelu_f(z1);
        o.z = xv.z * gelu_f(z2);
        o.w = xv.w * gelu_f(z3);
        *reinterpret_cast<float4*>(out + base) = o;
    }
}

// ---------------- launch ----------------
extern "C" void kernel_launch(void* const* d_in, const int* in_sizes, int n_in,
                              void* d_out, int out_size)
{
    const float* x      = (const float*)d_in[0];
    const float* cp     = (const float*)d_in[1];
    const float* W0     = (const float*)d_in[2];
    const float* b0     = (const float*)d_in[3];
    const float* W1     = (const float*)d_in[4];
    const float* b1     = (const float*)d_in[5];
    const float* W2     = (const float*)d_in[6];
    const float* b2     = (const float*)d_in[7];
    const float* W_lin  = (const float*)d_in[8];
    const float* b_lin  = (const float*)d_in[9];
    const float* log_dt = (const float*)d_in[10];
    const float* A_re   = (const float*)d_in[11];
    const float* A_im   = (const float*)d_in[12];
    const float* C_re   = (const float*)d_in[13];
    const float* C_im   = (const float*)d_in[14];
    const float* Dv     = (const float*)d_in[15];
    const float* W_film = (const float*)d_in[16];
    const float* b_film = (const float*)d_in[17];
    float* out = (float*)d_out;

    cudaFuncSetAttribute(k_linear_mma, cudaFuncAttributeMaxDynamicSharedMemorySize, LM_TOT);
    cudaFuncSetAttribute(k_scan_mma, cudaFuncAttributeMaxDynamicSharedMemorySize, SM_TOT);

    k_setup_tab<<<HH, 64>>>(log_dt, A_re, A_im, C_re, C_im, Dv);
    k_setup_mlp<<<1, 256>>>(cp, W0, b0, W1, b1, W2, b2, W_film, b_film);
    k_linear_mma<<<BB * (LL / 256), 256, LM_TOT>>>(x, W_lin, b_lin);
    k_scan_mma<<<BB * HH, 256, SM_TOT>>>();
    k_epilogue<<<BB * (LL / 64), 256>>>(x, out);
}

// round 9
// speedup vs baseline: 1.5989x; 1.1183x over previous
#include <cuda_runtime.h>
#include <cuda_bf16.h>
#include <cstdint>
#include <cstddef>

#define BB 16
#define LL 32768
#define HH 64
#define NN 16
#define DMM 32

typedef unsigned long long u64;
typedef uint32_t u32;
typedef __nv_bfloat16 bf16;

// strides (elements)
#define USTR 72
#define MSTR 72
#define VSTR 72
#define ESTR 40
#define SSTR 40
#define YSTR 68
#define LSTR 521

// scan smem byte offsets (total 227456 <= 232448)
#define SM_MH 0
#define SM_ML 9216
#define SM_VH 18432
#define SM_VL 23040
#define SM_EH 27648
#define SM_EL 32768
#define SM_UH 37888
#define SM_UL 56320
#define SM_SLOC 74752
#define SM_SINH 141440
#define SM_SINL 182400
#define SM_GBUF 223360
#define SM_TOT 227456

// linear-mma smem: W 18KB | bias | XH/XL 73.7KB ; Ys OVERLAYS XH/XL after MMA
#define LM_WTH 0
#define LM_WTL 9216
#define LM_BS 18432
#define LM_XH 18688
#define LM_XL 55552
#define LM_YS 18688
#define LM_TOT 92416
#define XSTR 72
#define WSTR 72
#define YL 264

// ---------------- scratch ----------------
__device__ float g_u[(size_t)BB * HH * LL];
__device__ float g_z[(size_t)BB * HH * LL];
__device__ bf16 g_Mh[HH * 4096], g_Ml[HH * 4096];
__device__ bf16 g_Vh[HH * 2048], g_Vl[HH * 2048];
__device__ bf16 g_Eh[HH * 2048], g_El[HH * 2048];
__device__ float2 g_w64c[HH * 16], g_wGc[HH * 16];   // w^64, w^1024
__device__ float g_gamma[BB * HH], g_beta[BB * HH];

// ---------------- helpers ----------------
__device__ __forceinline__ float gelu_f(float x) {
    float x3 = x * x * x;
    float z = 0.7978845608028654f * fmaf(0.044715f, x3, x);
    float az = fabsf(z);
    float e = __expf(2.0f * az);
    float t = 1.0f - __fdividef(2.0f, e + 1.0f);
    t = copysignf(t, z);
    return 0.5f * x * (1.0f + t);
}
__device__ __forceinline__ void bsplit(float v, bf16* ph, bf16* pl) {
    bf16 hi = __float2bfloat16(v);
    *ph = hi; *pl = __float2bfloat16(v - __bfloat162float(hi));
}
__device__ __forceinline__ u32 pk2bf(bf16 a, bf16 b) {
    __nv_bfloat162 v; v.x = a; v.y = b; return *reinterpret_cast<u32*>(&v);
}
__device__ __forceinline__ float2 cmulf(float2 a, float2 b) {
    return make_float2(a.x * b.x - a.y * b.y, a.x * b.y + a.y * b.x);
}
__device__ __forceinline__ float2 cpowf(float2 w, int e) {
    float2 r = make_float2(1.0f, 0.0f);
    while (e) {
        if (e & 1) r = cmulf(r, w);
        w = cmulf(w, w);
        e >>= 1;
    }
    return r;
}
__device__ __forceinline__ void mma16816(float* c, const u32* a, const u32* b) {
    asm volatile(
        "mma.sync.aligned.m16n8k16.row.col.f32.bf16.bf16.f32 "
        "{%0,%1,%2,%3}, {%4,%5,%6,%7}, {%8,%9}, {%0,%1,%2,%3};"
        : "+f"(c[0]), "+f"(c[1]), "+f"(c[2]), "+f"(c[3])
        : "r"(a[0]), "r"(a[1]), "r"(a[2]), "r"(a[3]), "r"(b[0]), "r"(b[1]));
}
__device__ __forceinline__ void ldA(u32* a, const bf16* base, int stride,
                                    int r0, int k0, int lane) {
    const bf16* p = base + (r0 + (lane >> 2)) * stride + k0 + (lane & 3) * 2;
    a[0] = *(const u32*)p;
    a[1] = *(const u32*)(p + 8 * stride);
    a[2] = *(const u32*)(p + 8);
    a[3] = *(const u32*)(p + 8 * stride + 8);
}
__device__ __forceinline__ void ldB(u32* b, const bf16* base, int stride,
                                    int n0, int k0, int lane) {
    const bf16* p = base + (n0 + (lane >> 2)) * stride + k0 + (lane & 3) * 2;
    b[0] = *(const u32*)p;
    b[1] = *(const u32*)(p + 8);
}
__device__ __forceinline__ void split_store4(float4 v, bf16* H, bf16* L, int off) {
    bf16 h0 = __float2bfloat16(v.x), h1 = __float2bfloat16(v.y);
    bf16 h2 = __float2bfloat16(v.z), h3 = __float2bfloat16(v.w);
    *(u32*)&H[off] = pk2bf(h0, h1);
    *(u32*)&H[off + 2] = pk2bf(h2, h3);
    *(u32*)&L[off] = pk2bf(
        __float2bfloat16(v.x - __bfloat162float(h0)),
        __float2bfloat16(v.y - __bfloat162float(h1)));
    *(u32*)&L[off + 2] = pk2bf(
        __float2bfloat16(v.z - __bfloat162float(h2)),
        __float2bfloat16(v.w - __bfloat162float(h3)));
}
// register-prefetch staging for the scan (512 threads)
__device__ __forceinline__ void load_q(const float4* gu4, int q, int t, float4* v) {
    #pragma unroll
    for (int k = 0; k < 4; k++) v[k] = gu4[q * 2048 + t + k * 512];
}
__device__ __forceinline__ void store_q(const float4* v, bf16* UH, bf16* UL, int t) {
    #pragma unroll
    for (int k = 0; k < 4; k++) {
        int f = t + k * 512;
        int c = f >> 4, i0 = (f & 15) * 4;
        split_store4(v[k], UH, UL, c * USTR + i0);
    }
}

// ---------------- K0: per-h tables ----------------
__global__ void k_setup_tab(const float* __restrict__ log_dt,
                            const float* __restrict__ A_re, const float* __restrict__ A_im,
                            const float* __restrict__ C_re, const float* __restrict__ C_im,
                            const float* __restrict__ Dv)
{
    int h = blockIdx.x;
    int j = threadIdx.x;          // 0..63
    __shared__ float2 wf[NN];
    __shared__ float2 c2f[NN];
    __shared__ float Ks[64];

    double dt = exp((double)log_dt[h]);
    if (j < NN) {
        int i = h * NN + j;
        float ar = A_re[i], ai = A_im[i];
        double mre = dt * (double)ar, mim = dt * (double)ai;
        double e1 = exp(mre);
        float wr = (float)(e1 * cos(mim)), wi = (float)(e1 * sin(mim));
        wf[j] = make_float2(wr, wi);
        float den = ar * ar + ai * ai;
        float nr = wr - 1.0f, ni = wi;
        float qr = (nr * ar + ni * ai) / den, qi = (ni * ar - nr * ai) / den;
        float cr = C_re[i], ci = C_im[i];
        c2f[j] = make_float2(2.0f * (cr * qr - ci * qi), 2.0f * (cr * qi + ci * qr));
        float2 w64 = cpowf(make_float2(wr, wi), 64);
        g_w64c[h * 16 + j] = w64;
        g_wGc[h * 16 + j] = cpowf(w64, 16);   // w^1024
    }
    __syncthreads();

    float kacc = 0.0f;
    for (int n = 0; n < NN; n++) {
        float2 w = wf[n];
        float2 c2 = c2f[n];
        float2 wj = cpowf(w, j);
        kacc += c2.x * wj.x - c2.y * wj.y;
        float2 wj1 = cmulf(wj, w);
        bsplit(c2.x * wj1.x - c2.y * wj1.y,
               &g_Eh[h * 2048 + j * 32 + n], &g_El[h * 2048 + j * 32 + n]);
        bsplit(-(c2.x * wj1.y + c2.y * wj1.x),
               &g_Eh[h * 2048 + j * 32 + 16 + n], &g_El[h * 2048 + j * 32 + 16 + n]);
        float2 wv = cpowf(w, 63 - j);
        bsplit(wv.x, &g_Vh[h * 2048 + n * 64 + j], &g_Vl[h * 2048 + n * 64 + j]);
        bsplit(wv.y, &g_Vh[h * 2048 + (16 + n) * 64 + j], &g_Vl[h * 2048 + (16 + n) * 64 + j]);
    }
    Ks[j] = kacc;
    __syncthreads();

    float dD = Dv[h];
    for (int i2 = 0; i2 < 64; i2++) {
        float m = (i2 < j) ? Ks[j - i2] : (i2 == j ? Ks[0] + dD : 0.0f);
        bsplit(m, &g_Mh[h * 4096 + j * 64 + i2], &g_Ml[h * 4096 + j * 64 + i2]);
    }
}

// ---------------- K1: conditioning MLP + FiLM ----------------
__global__ void k_setup_mlp(const float* __restrict__ cp,
                            const float* __restrict__ W0, const float* __restrict__ b0,
                            const float* __restrict__ W1, const float* __restrict__ b1,
                            const float* __restrict__ W2, const float* __restrict__ b2,
                            const float* __restrict__ W_film, const float* __restrict__ b_film)
{
    __shared__ float c0[BB * DMM];
    __shared__ float c1[BB * DMM];
    int t = threadIdx.x;
    for (int i = t; i < BB * DMM; i += blockDim.x) {
        int b = i / DMM, d = i % DMM;
        float v = fmaf(cp[b * 2 + 0], W0[d], fmaf(cp[b * 2 + 1], W0[DMM + d], b0[d]));
        c0[i] = gelu_f(v);
    }
    __syncthreads();
    for (int i = t; i < BB * DMM; i += blockDim.x) {
        int b = i / DMM, d = i % DMM;
        float v = b1[d];
        for (int k = 0; k < DMM; k++) v = fmaf(c0[b * DMM + k], W1[k * DMM + d], v);
        c1[i] = gelu_f(v);
    }
    __syncthreads();
    for (int i = t; i < BB * DMM; i += blockDim.x) {
        int b = i / DMM, d = i % DMM;
        float v = b2[d];
        for (int k = 0; k < DMM; k++) v = fmaf(c1[b * DMM + k], W2[k * DMM + d], v);
        c0[i] = gelu_f(v);
    }
    __syncthreads();
    for (int i = t; i < BB * 2 * HH; i += blockDim.x) {
        int b = i / (2 * HH), j = i % (2 * HH);
        float v = b_film[j];
        for (int k = 0; k < DMM; k++) v = fmaf(c0[b * DMM + k], W_film[k * 2 * HH + j], v);
        if (j < HH) g_gamma[b * HH + j] = v;
        else        g_beta[b * HH + j - HH] = v;
    }
}

// ---------------- K2: u = gelu(x @ W_lin + b_lin) via bf16-split MMA, 2 blocks/SM ----------------
__global__ __launch_bounds__(256, 2) void k_linear_mma(const float* __restrict__ x,
                                                       const float* __restrict__ W,
                                                       const float* __restrict__ bias)
{
    extern __shared__ char sm[];
    bf16* WtH = (bf16*)(sm + LM_WTH);   // [64 h][72 k]
    bf16* WtL = (bf16*)(sm + LM_WTL);
    float* bs = (float*)(sm + LM_BS);   // [64]
    bf16* XH = (bf16*)(sm + LM_XH);     // [256 l][72 k]
    bf16* XL = (bf16*)(sm + LM_XL);
    float* Ys = (float*)(sm + LM_YS);   // OVERLAYS XH/XL after MMA

    int t = threadIdx.x, wid = t >> 5, lane = t & 31;
    int b = blockIdx.x >> 7, tile = blockIdx.x & 127;
    int l0 = tile * 256;

    for (int i = t; i < 4096; i += 256) {
        int k = i >> 6, h = i & 63;
        bsplit(W[i], &WtH[h * WSTR + k], &WtL[h * WSTR + k]);
    }
    if (t < 64) bs[t] = bias[t];
    const float4* xg4 = (const float4*)(x + ((size_t)b * LL + l0) * HH);
    #pragma unroll
    for (int kk = 0; kk < 16; kk++) {
        int f = t + kk * 256;
        float4 v = xg4[f];
        int l = f >> 4, i0 = (f & 15) * 4;
        split_store4(v, XH, XL, l * XSTR + i0);
    }
    __syncthreads();

    float C[2][8][4];
    #pragma unroll
    for (int mt = 0; mt < 2; mt++)
        #pragma unroll
        for (int nt = 0; nt < 8; nt++) {
            int c0 = nt * 8 + (lane & 3) * 2;
            C[mt][nt][0] = bs[c0]; C[mt][nt][1] = bs[c0 + 1];
            C[mt][nt][2] = bs[c0]; C[mt][nt][3] = bs[c0 + 1];
        }
    #pragma unroll
    for (int kt = 0; kt < 4; kt++) {
        int k0 = kt * 16;
        u32 bhf[8][2], blf[8][2];
        #pragma unroll
        for (int nt = 0; nt < 8; nt++) {
            ldB(bhf[nt], WtH, WSTR, nt * 8, k0, lane);
            ldB(blf[nt], WtL, WSTR, nt * 8, k0, lane);
        }
        #pragma unroll
        for (int mt = 0; mt < 2; mt++) {
            u32 ah[4], al[4];
            ldA(ah, XH, XSTR, wid * 32 + mt * 16, k0, lane);
            ldA(al, XL, XSTR, wid * 32 + mt * 16, k0, lane);
            #pragma unroll
            for (int nt = 0; nt < 8; nt++) {
                mma16816(C[mt][nt], ah, bhf[nt]);
                mma16816(C[mt][nt], ah, blf[nt]);
                mma16816(C[mt][nt], al, bhf[nt]);
            }
        }
    }
    __syncthreads();   // all XH/XL reads done before Ys overlay writes
    #pragma unroll
    for (int mt = 0; mt < 2; mt++)
        #pragma unroll
        for (int nt = 0; nt < 8; nt++) {
            int l = wid * 32 + mt * 16 + (lane >> 2);
            int h0 = nt * 8 + (lane & 3) * 2;
            Ys[h0 * YL + l] = gelu_f(C[mt][nt][0]);
            Ys[(h0 + 1) * YL + l] = gelu_f(C[mt][nt][1]);
            Ys[h0 * YL + l + 8] = gelu_f(C[mt][nt][2]);
            Ys[(h0 + 1) * YL + l + 8] = gelu_f(C[mt][nt][3]);
        }
    __syncthreads();
    #pragma unroll
    for (int i = t; i < 4096; i += 256) {
        int h = i >> 6, q = i & 63;
        float4 v = *(const float4*)&Ys[h * YL + q * 4];
        *(float4*)(g_u + ((size_t)b * HH + h) * LL + l0 + q * 4) = v;
    }
}

// ---------------- K3: chunked S4 conv, 512 threads + register prefetch ----------------
__global__ __launch_bounds__(512) void k_scan_mma()
{
    extern __shared__ char smem[];
    bf16* MHs = (bf16*)(smem + SM_MH);
    bf16* MLs = (bf16*)(smem + SM_ML);
    bf16* VHs = (bf16*)(smem + SM_VH);
    bf16* VLs = (bf16*)(smem + SM_VL);
    bf16* EHs = (bf16*)(smem + SM_EH);
    bf16* ELs = (bf16*)(smem + SM_EL);
    bf16* UHs = (bf16*)(smem + SM_UH);
    bf16* ULs = (bf16*)(smem + SM_UL);
    float* SLOC = (float*)(smem + SM_SLOC);
    bf16* SINH = (bf16*)(smem + SM_SINH);
    bf16* SINL = (bf16*)(smem + SM_SINL);
    float2* GBUF = (float2*)(smem + SM_GBUF);   // [32 g][16 n]

    int t = threadIdx.x;
    int bh = blockIdx.x;
    int h = bh & 63;
    int wid = t >> 5, lane = t & 31;   // wid 0..15

    {
        const u32* gmh = (const u32*)(g_Mh + (size_t)h * 4096);
        const u32* gml = (const u32*)(g_Ml + (size_t)h * 4096);
        u32* smh = (u32*)MHs; u32* sml = (u32*)MLs;
        for (int i = t; i < 2048; i += 512) {
            int r = i >> 5, c = i & 31;
            smh[r * 36 + c] = gmh[i]; sml[r * 36 + c] = gml[i];
        }
        const u32* gvh = (const u32*)(g_Vh + (size_t)h * 2048);
        const u32* gvl = (const u32*)(g_Vl + (size_t)h * 2048);
        u32* svh = (u32*)VHs; u32* svl = (u32*)VLs;
        for (int i = t; i < 1024; i += 512) {
            int r = i >> 5, c = i & 31;
            svh[r * 36 + c] = gvh[i]; svl[r * 36 + c] = gvl[i];
        }
        const u32* geh = (const u32*)(g_Eh + (size_t)h * 2048);
        const u32* gel = (const u32*)(g_El + (size_t)h * 2048);
        u32* seh = (u32*)EHs; u32* sel = (u32*)ELs;
        for (int i = t; i < 1024; i += 512) {
            int r = i >> 4, c = i & 15;
            seh[r * 20 + c] = geh[i]; sel[r * 20 + c] = gel[i];
        }
    }

    const float4* gu4 = (const float4*)(g_u + (size_t)bh * LL);
    float4 v[4];
    load_q(gu4, 0, t, v);

    // ---- pass 1: S_local = V @ U (warp = 8 chunks) ----
    for (int q = 0; q < 4; q++) {
        __syncthreads();
        store_q(v, UHs, ULs, t);
        __syncthreads();
        if (q < 3) load_q(gu4, q + 1, t, v);
        int cloc = wid * 8, cglob = q * 128 + cloc;
        float C1[2][4] = {};
        #pragma unroll
        for (int kt = 0; kt < 4; kt++) {
            int k0 = kt * 16;
            u32 bh_[2], bl_[2];
            ldB(bh_, UHs, USTR, cloc, k0, lane);
            ldB(bl_, ULs, USTR, cloc, k0, lane);
            #pragma unroll
            for (int mt = 0; mt < 2; mt++) {
                u32 ah[4], al[4];
                ldA(ah, VHs, VSTR, mt * 16, k0, lane);
                ldA(al, VLs, VSTR, mt * 16, k0, lane);
                mma16816(C1[mt], ah, bh_);
                mma16816(C1[mt], ah, bl_);
                mma16816(C1[mt], al, bh_);
            }
        }
        #pragma unroll
        for (int mt = 0; mt < 2; mt++) {
            int r = mt * 16 + (lane >> 2);
            int cc = cglob + (lane & 3) * 2;
            SLOC[r * LSTR + cc] = C1[mt][0];
            SLOC[r * LSTR + cc + 1] = C1[mt][1];
            SLOC[(r + 8) * LSTR + cc] = C1[mt][2];
            SLOC[(r + 8) * LSTR + cc + 1] = C1[mt][3];
        }
    }
    __syncthreads();

    // ---- chunk-state scan: 32 groups x 16 chunks ----
    {
        int n = t & 15, g = t >> 4;   // g 0..31
        float2 w64 = g_w64c[h * 16 + n];
        float sr = 0.f, si = 0.f;
        for (int m = 0; m < 16; m++) {
            int c = g * 16 + m;
            float xr = SLOC[n * LSTR + c], xi = SLOC[(16 + n) * LSTR + c];
            float nr = fmaf(w64.x, sr, fmaf(-w64.y, si, xr));
            si = fmaf(w64.x, si, fmaf(w64.y, sr, xi));
            sr = nr;
        }
        GBUF[g * 16 + n] = make_float2(sr, si);
        __syncthreads();
        if (t < 16) {
            float2 wG = g_wGc[h * 16 + t];   // w^1024
            float pr = 0.f, pi = 0.f;
            for (int gg = 0; gg < 32; gg++) {
                float2 tm = GBUF[gg * 16 + t];
                GBUF[gg * 16 + t] = make_float2(pr, pi);
                float nr = fmaf(wG.x, pr, fmaf(-wG.y, pi, tm.x));
                pi = fmaf(wG.x, pi, fmaf(wG.y, pr, tm.y));
                pr = nr;
            }
        }
        __syncthreads();
        float2 I = GBUF[g * 16 + n];
        sr = I.x; si = I.y;
        for (int m = 0; m < 16; m++) {
            int c = g * 16 + m;
            bsplit(sr, &SINH[c * SSTR + n], &SINL[c * SSTR + n]);
            bsplit(si, &SINH[c * SSTR + 16 + n], &SINL[c * SSTR + 16 + n]);
            float xr = SLOC[n * LSTR + c], xi = SLOC[(16 + n) * LSTR + c];
            float nr = fmaf(w64.x, sr, fmaf(-w64.y, si, xr));
            si = fmaf(w64.x, si, fmaf(w64.y, sr, xi));
            sr = nr;
        }
    }

    // ---- pass 2: Y = M@U + E@S_in, FiLM, writeback ----
    float gam = g_gamma[bh];
    float bet = g_beta[bh];
    float* Ys = SLOC;
    float4* gz4 = (float4*)(g_z + (size_t)bh * LL);
    load_q(gu4, 0, t, v);

    for (int q = 0; q < 4; q++) {
        __syncthreads();
        store_q(v, UHs, ULs, t);
        __syncthreads();
        if (q < 3) load_q(gu4, q + 1, t, v);
        int cloc = wid * 8, cglob = q * 128 + cloc;
        float C2[4][4] = {};
        #pragma unroll
        for (int kt = 0; kt < 4; kt++) {
            int k0 = kt * 16;
            u32 bh_[2], bl_[2];
            ldB(bh_, UHs, USTR, cloc, k0, lane);
            ldB(bl_, ULs, USTR, cloc, k0, lane);
            #pragma unroll
            for (int mt = 0; mt < 4; mt++) {
                if (kt > mt) continue;
                u32 ah[4], al[4];
                ldA(ah, MHs, MSTR, mt * 16, k0, lane);
                ldA(al, MLs, MSTR, mt * 16, k0, lane);
                mma16816(C2[mt], ah, bh_);
                mma16816(C2[mt], ah, bl_);
                mma16816(C2[mt], al, bh_);
            }
        }
        #pragma unroll
        for (int kt = 0; kt < 2; kt++) {
            int k0 = kt * 16;
            u32 bh_[2], bl_[2];
            ldB(bh_, SINH, SSTR, cglob, k0, lane);
            ldB(bl_, SINL, SSTR, cglob, k0, lane);
            #pragma unroll
            for (int mt = 0; mt < 4; mt++) {
                u32 ah[4], al[4];
                ldA(ah, EHs, ESTR, mt * 16, k0, lane);
                ldA(al, ELs, ESTR, mt * 16, k0, lane);
                mma16816(C2[mt], ah, bh_);
                mma16816(C2[mt], ah, bl_);
                mma16816(C2[mt], al, bh_);
            }
        }
        #pragma unroll
        for (int mt = 0; mt < 4; mt++) {
            int j = mt * 16 + (lane >> 2);
            int cc = cloc + (lane & 3) * 2;
            Ys[cc * YSTR + j] = fmaf(C2[mt][0], gam, bet);
            Ys[(cc + 1) * YSTR + j] = fmaf(C2[mt][1], gam, bet);
            Ys[cc * YSTR + j + 8] = fmaf(C2[mt][2], gam, bet);
            Ys[(cc + 1) * YSTR + j + 8] = fmaf(C2[mt][3], gam, bet);
        }
        __syncthreads();
        #pragma unroll
        for (int k = 0; k < 4; k++) {
            int f = t + k * 512;
            int c = f >> 4, qq = f & 15;
            float4 o = *(const float4*)&Ys[c * YSTR + qq * 4];
            gz4[q * 2048 + f] = o;
        }
    }
}

// ---------------- K4: out = x * gelu(z) ----------------
__global__ __launch_bounds__(256) void k_epilogue(const float* __restrict__ x,
                                                  float* __restrict__ out)
{
    __shared__ float zt[64 * 65];
    int t = threadIdx.x;
    int b = blockIdx.x >> 9;
    int tile = blockIdx.x & 511;
    int l0 = tile * 64;
    #pragma unroll
    for (int i = t; i < 1024; i += 256) {
        int hh = i >> 4, q = i & 15;
        float4 v = *reinterpret_cast<const float4*>(
            g_z + ((size_t)b * HH + hh) * LL + l0 + 4 * q);
        float* d = zt + hh * 65 + 4 * q;
        d[0] = v.x; d[1] = v.y; d[2] = v.z; d[3] = v.w;
    }
    __syncthreads();
    #pragma unroll
    for (int i = t; i < 1024; i += 256) {
        int l = i >> 4, hq = i & 15;
        float z0 = zt[(4 * hq + 0) * 65 + l];
        float z1 = zt[(4 * hq + 1) * 65 + l];
        float z2 = zt[(4 * hq + 2) * 65 + l];
        float z3 = zt[(4 * hq + 3) * 65 + l];
        size_t base = ((size_t)b * LL + l0 + l) * HH + 4 * hq;
        float4 xv = *reinterpret_cast<const float4*>(x + base);
        float4 o;
        o.x = xv.x * gelu_f(z0);
        o.y = xv.y * gelu_f(z1);
        o.z = xv.z * gelu_f(z2);
        o.w = xv.w * gelu_f(z3);
        *reinterpret_cast<float4*>(out + base) = o;
    }
}

// ---------------- launch ----------------
extern "C" void kernel_launch(void* const* d_in, const int* in_sizes, int n_in,
                              void* d_out, int out_size)
{
    const float* x      = (const float*)d_in[0];
    const float* cp     = (const float*)d_in[1];
    const float* W0     = (const float*)d_in[2];
    const float* b0     = (const float*)d_in[3];
    const float* W1     = (const float*)d_in[4];
    const float* b1     = (const float*)d_in[5];
    const float* W2     = (const float*)d_in[6];
    const float* b2     = (const float*)d_in[7];
    const float* W_lin  = (const float*)d_in[8];
    const float* b_lin  = (const float*)d_in[9];
    const float* log_dt = (const float*)d_in[10];
    const float* A_re   = (const float*)d_in[11];
    const float* A_im   = (const float*)d_in[12];
    const float* C_re   = (const float*)d_in[13];
    const float* C_im   = (const float*)d_in[14];
    const float* Dv     = (const float*)d_in[15];
    const float* W_film = (const float*)d_in[16];
    const float* b_film = (const float*)d_in[17];
    float* out = (float*)d_out;

    cudaFuncSetAttribute(k_linear_mma, cudaFuncAttributeMaxDynamicSharedMemorySize, LM_TOT);
    cudaFuncSetAttribute(k_scan_mma, cudaFuncAttributeMaxDynamicSharedMemorySize, SM_TOT);

    k_setup_tab<<<HH, 64>>>(log_dt, A_re, A_im, C_re, C_im, Dv);
    k_setup_mlp<<<1, 256>>>(cp, W0, b0, W1, b1, W2, b2, W_film, b_film);
    k_linear_mma<<<BB * (LL / 256), 256, LM_TOT>>>(x, W_lin, b_lin);
    k_scan_mma<<<BB * HH, 512, SM_TOT>>>();
    k_epilogue<<<BB * (LL / 64), 256>>>(x, out);
}

// round 10
// speedup vs baseline: 1.6105x; 1.0073x over previous
#include <cuda_runtime.h>
#include <cuda_bf16.h>
#include <cstdint>
#include <cstddef>

#define BB 16
#define LL 32768
#define HH 64
#define NN 16
#define DMM 32

typedef unsigned long long u64;
typedef uint32_t u32;
typedef __nv_bfloat16 bf16;

// strides (elements)
#define USTR 72
#define MSTR 72
#define VSTR 72
#define ESTR 40
#define SSTR 40
#define YSTR 68
#define LSTR 521

// scan smem byte offsets (total 227456 <= 232448)
#define SM_MH 0
#define SM_ML 9216
#define SM_VH 18432
#define SM_VL 23040
#define SM_EH 27648
#define SM_EL 32768
#define SM_UH 37888
#define SM_UL 56320
#define SM_SLOC 74752
#define SM_SINH 141440
#define SM_SINL 182400
#define SM_GBUF 223360
#define SM_TOT 227456

// linear-mma smem: W 18KB | bias | XH/XL 73.7KB ; Ys OVERLAYS XH/XL after MMA
#define LM_WTH 0
#define LM_WTL 9216
#define LM_BS 18432
#define LM_XH 18688
#define LM_XL 55552
#define LM_YS 18688
#define LM_TOT 92416
#define XSTR 72
#define WSTR 72
#define YL 264

// ---------------- scratch ----------------
__device__ float g_u[(size_t)BB * HH * LL];
__device__ float g_z[(size_t)BB * HH * LL];
__device__ bf16 g_Mh[HH * 4096], g_Ml[HH * 4096];
__device__ bf16 g_Vh[HH * 2048], g_Vl[HH * 2048];
__device__ bf16 g_Eh[HH * 2048], g_El[HH * 2048];
__device__ float2 g_w64c[HH * 16], g_wGc[HH * 16];   // w^64, w^1024
__device__ float g_gamma[BB * HH], g_beta[BB * HH];

// ---------------- helpers ----------------
__device__ __forceinline__ float gelu_f(float x) {
    float x3 = x * x * x;
    float z = 0.7978845608028654f * fmaf(0.044715f, x3, x);
    float az = fabsf(z);
    float e = __expf(2.0f * az);
    float t = 1.0f - __fdividef(2.0f, e + 1.0f);
    t = copysignf(t, z);
    return 0.5f * x * (1.0f + t);
}
__device__ __forceinline__ void bsplit(float v, bf16* ph, bf16* pl) {
    bf16 hi = __float2bfloat16(v);
    *ph = hi; *pl = __float2bfloat16(v - __bfloat162float(hi));
}
__device__ __forceinline__ u32 pk2bf(bf16 a, bf16 b) {
    __nv_bfloat162 v; v.x = a; v.y = b; return *reinterpret_cast<u32*>(&v);
}
__device__ __forceinline__ float2 cmulf(float2 a, float2 b) {
    return make_float2(a.x * b.x - a.y * b.y, a.x * b.y + a.y * b.x);
}
__device__ __forceinline__ float2 cpowf(float2 w, int e) {
    float2 r = make_float2(1.0f, 0.0f);
    while (e) {
        if (e & 1) r = cmulf(r, w);
        w = cmulf(w, w);
        e >>= 1;
    }
    return r;
}
__device__ __forceinline__ void mma16816(float* c, const u32* a, const u32* b) {
    asm volatile(
        "mma.sync.aligned.m16n8k16.row.col.f32.bf16.bf16.f32 "
        "{%0,%1,%2,%3}, {%4,%5,%6,%7}, {%8,%9}, {%0,%1,%2,%3};"
        : "+f"(c[0]), "+f"(c[1]), "+f"(c[2]), "+f"(c[3])
        : "r"(a[0]), "r"(a[1]), "r"(a[2]), "r"(a[3]), "r"(b[0]), "r"(b[1]));
}
__device__ __forceinline__ void ldA(u32* a, const bf16* base, int stride,
                                    int r0, int k0, int lane) {
    const bf16* p = base + (r0 + (lane >> 2)) * stride + k0 + (lane & 3) * 2;
    a[0] = *(const u32*)p;
    a[1] = *(const u32*)(p + 8 * stride);
    a[2] = *(const u32*)(p + 8);
    a[3] = *(const u32*)(p + 8 * stride + 8);
}
__device__ __forceinline__ void ldB(u32* b, const bf16* base, int stride,
                                    int n0, int k0, int lane) {
    const bf16* p = base + (n0 + (lane >> 2)) * stride + k0 + (lane & 3) * 2;
    b[0] = *(const u32*)p;
    b[1] = *(const u32*)(p + 8);
}
__device__ __forceinline__ void split_store4(float4 v, bf16* H, bf16* L, int off) {
    bf16 h0 = __float2bfloat16(v.x), h1 = __float2bfloat16(v.y);
    bf16 h2 = __float2bfloat16(v.z), h3 = __float2bfloat16(v.w);
    *(u32*)&H[off] = pk2bf(h0, h1);
    *(u32*)&H[off + 2] = pk2bf(h2, h3);
    *(u32*)&L[off] = pk2bf(
        __float2bfloat16(v.x - __bfloat162float(h0)),
        __float2bfloat16(v.y - __bfloat162float(h1)));
    *(u32*)&L[off + 2] = pk2bf(
        __float2bfloat16(v.z - __bfloat162float(h2)),
        __float2bfloat16(v.w - __bfloat162float(h3)));
}
// register-prefetch staging for the scan (512 threads)
__device__ __forceinline__ void load_q(const float4* gu4, int q, int t, float4* v) {
    #pragma unroll
    for (int k = 0; k < 4; k++) v[k] = gu4[q * 2048 + t + k * 512];
}
__device__ __forceinline__ void store_q(const float4* v, bf16* UH, bf16* UL, int t) {
    #pragma unroll
    for (int k = 0; k < 4; k++) {
        int f = t + k * 512;
        int c = f >> 4, i0 = (f & 15) * 4;
        split_store4(v[k], UH, UL, c * USTR + i0);
    }
}

// ---------------- K0: per-h tables ----------------
__global__ void k_setup_tab(const float* __restrict__ log_dt,
                            const float* __restrict__ A_re, const float* __restrict__ A_im,
                            const float* __restrict__ C_re, const float* __restrict__ C_im,
                            const float* __restrict__ Dv)
{
    int h = blockIdx.x;
    int j = threadIdx.x;          // 0..63
    __shared__ float2 wf[NN];
    __shared__ float2 c2f[NN];
    __shared__ float Ks[64];

    double dt = exp((double)log_dt[h]);
    if (j < NN) {
        int i = h * NN + j;
        float ar = A_re[i], ai = A_im[i];
        double mre = dt * (double)ar, mim = dt * (double)ai;
        double e1 = exp(mre);
        float wr = (float)(e1 * cos(mim)), wi = (float)(e1 * sin(mim));
        wf[j] = make_float2(wr, wi);
        float den = ar * ar + ai * ai;
        float nr = wr - 1.0f, ni = wi;
        float qr = (nr * ar + ni * ai) / den, qi = (ni * ar - nr * ai) / den;
        float cr = C_re[i], ci = C_im[i];
        c2f[j] = make_float2(2.0f * (cr * qr - ci * qi), 2.0f * (cr * qi + ci * qr));
        float2 w64 = cpowf(make_float2(wr, wi), 64);
        g_w64c[h * 16 + j] = w64;
        g_wGc[h * 16 + j] = cpowf(w64, 16);   // w^1024
    }
    __syncthreads();

    float kacc = 0.0f;
    for (int n = 0; n < NN; n++) {
        float2 w = wf[n];
        float2 c2 = c2f[n];
        float2 wj = cpowf(w, j);
        kacc += c2.x * wj.x - c2.y * wj.y;
        float2 wj1 = cmulf(wj, w);
        bsplit(c2.x * wj1.x - c2.y * wj1.y,
               &g_Eh[h * 2048 + j * 32 + n], &g_El[h * 2048 + j * 32 + n]);
        bsplit(-(c2.x * wj1.y + c2.y * wj1.x),
               &g_Eh[h * 2048 + j * 32 + 16 + n], &g_El[h * 2048 + j * 32 + 16 + n]);
        float2 wv = cpowf(w, 63 - j);
        bsplit(wv.x, &g_Vh[h * 2048 + n * 64 + j], &g_Vl[h * 2048 + n * 64 + j]);
        bsplit(wv.y, &g_Vh[h * 2048 + (16 + n) * 64 + j], &g_Vl[h * 2048 + (16 + n) * 64 + j]);
    }
    Ks[j] = kacc;
    __syncthreads();

    float dD = Dv[h];
    for (int i2 = 0; i2 < 64; i2++) {
        float m = (i2 < j) ? Ks[j - i2] : (i2 == j ? Ks[0] + dD : 0.0f);
        bsplit(m, &g_Mh[h * 4096 + j * 64 + i2], &g_Ml[h * 4096 + j * 64 + i2]);
    }
}

// ---------------- K1: conditioning MLP + FiLM ----------------
__global__ void k_setup_mlp(const float* __restrict__ cp,
                            const float* __restrict__ W0, const float* __restrict__ b0,
                            const float* __restrict__ W1, const float* __restrict__ b1,
                            const float* __restrict__ W2, const float* __restrict__ b2,
                            const float* __restrict__ W_film, const float* __restrict__ b_film)
{
    __shared__ float c0[BB * DMM];
    __shared__ float c1[BB * DMM];
    int t = threadIdx.x;
    for (int i = t; i < BB * DMM; i += blockDim.x) {
        int b = i / DMM, d = i % DMM;
        float v = fmaf(cp[b * 2 + 0], W0[d], fmaf(cp[b * 2 + 1], W0[DMM + d], b0[d]));
        c0[i] = gelu_f(v);
    }
    __syncthreads();
    for (int i = t; i < BB * DMM; i += blockDim.x) {
        int b = i / DMM, d = i % DMM;
        float v = b1[d];
        for (int k = 0; k < DMM; k++) v = fmaf(c0[b * DMM + k], W1[k * DMM + d], v);
        c1[i] = gelu_f(v);
    }
    __syncthreads();
    for (int i = t; i < BB * DMM; i += blockDim.x) {
        int b = i / DMM, d = i % DMM;
        float v = b2[d];
        for (int k = 0; k < DMM; k++) v = fmaf(c1[b * DMM + k], W2[k * DMM + d], v);
        c0[i] = gelu_f(v);
    }
    __syncthreads();
    for (int i = t; i < BB * 2 * HH; i += blockDim.x) {
        int b = i / (2 * HH), j = i % (2 * HH);
        float v = b_film[j];
        for (int k = 0; k < DMM; k++) v = fmaf(c0[b * DMM + k], W_film[k * 2 * HH + j], v);
        if (j < HH) g_gamma[b * HH + j] = v;
        else        g_beta[b * HH + j - HH] = v;
    }
}

// ---------------- K2: u = gelu(x @ W_lin + b_lin) via bf16-split MMA, 2 blocks/SM ----------------
__global__ __launch_bounds__(256, 2) void k_linear_mma(const float* __restrict__ x,
                                                       const float* __restrict__ W,
                                                       const float* __restrict__ bias)
{
    extern __shared__ char sm[];
    bf16* WtH = (bf16*)(sm + LM_WTH);   // [64 h][72 k]
    bf16* WtL = (bf16*)(sm + LM_WTL);
    float* bs = (float*)(sm + LM_BS);   // [64]
    bf16* XH = (bf16*)(sm + LM_XH);     // [256 l][72 k]
    bf16* XL = (bf16*)(sm + LM_XL);
    float* Ys = (float*)(sm + LM_YS);   // OVERLAYS XH/XL after MMA

    int t = threadIdx.x, wid = t >> 5, lane = t & 31;
    int b = blockIdx.x >> 7, tile = blockIdx.x & 127;
    int l0 = tile * 256;

    for (int i = t; i < 4096; i += 256) {
        int k = i >> 6, h = i & 63;
        bsplit(W[i], &WtH[h * WSTR + k], &WtL[h * WSTR + k]);
    }
    if (t < 64) bs[t] = bias[t];
    const float4* xg4 = (const float4*)(x + ((size_t)b * LL + l0) * HH);
    #pragma unroll
    for (int kk = 0; kk < 16; kk++) {
        int f = t + kk * 256;
        float4 v = xg4[f];
        int l = f >> 4, i0 = (f & 15) * 4;
        split_store4(v, XH, XL, l * XSTR + i0);
    }
    __syncthreads();

    float C[2][8][4];
    #pragma unroll
    for (int mt = 0; mt < 2; mt++)
        #pragma unroll
        for (int nt = 0; nt < 8; nt++) {
            int c0 = nt * 8 + (lane & 3) * 2;
            C[mt][nt][0] = bs[c0]; C[mt][nt][1] = bs[c0 + 1];
            C[mt][nt][2] = bs[c0]; C[mt][nt][3] = bs[c0 + 1];
        }
    #pragma unroll
    for (int kt = 0; kt < 4; kt++) {
        int k0 = kt * 16;
        u32 bhf[8][2], blf[8][2];
        #pragma unroll
        for (int nt = 0; nt < 8; nt++) {
            ldB(bhf[nt], WtH, WSTR, nt * 8, k0, lane);
            ldB(blf[nt], WtL, WSTR, nt * 8, k0, lane);
        }
        #pragma unroll
        for (int mt = 0; mt < 2; mt++) {
            u32 ah[4], al[4];
            ldA(ah, XH, XSTR, wid * 32 + mt * 16, k0, lane);
            ldA(al, XL, XSTR, wid * 32 + mt * 16, k0, lane);
            #pragma unroll
            for (int nt = 0; nt < 8; nt++) {
                mma16816(C[mt][nt], ah, bhf[nt]);
                mma16816(C[mt][nt], ah, blf[nt]);
                mma16816(C[mt][nt], al, bhf[nt]);
            }
        }
    }
    __syncthreads();   // all XH/XL reads done before Ys overlay writes
    #pragma unroll
    for (int mt = 0; mt < 2; mt++)
        #pragma unroll
        for (int nt = 0; nt < 8; nt++) {
            int l = wid * 32 + mt * 16 + (lane >> 2);
            int h0 = nt * 8 + (lane & 3) * 2;
            Ys[h0 * YL + l] = gelu_f(C[mt][nt][0]);
            Ys[(h0 + 1) * YL + l] = gelu_f(C[mt][nt][1]);
            Ys[h0 * YL + l + 8] = gelu_f(C[mt][nt][2]);
            Ys[(h0 + 1) * YL + l + 8] = gelu_f(C[mt][nt][3]);
        }
    __syncthreads();
    #pragma unroll
    for (int i = t; i < 4096; i += 256) {
        int h = i >> 6, q = i & 63;
        float4 v = *(const float4*)&Ys[h * YL + q * 4];
        *(float4*)(g_u + ((size_t)b * HH + h) * LL + l0 + q * 4) = v;
    }
}

// ---------------- K3: chunked S4 conv, 512 threads + register prefetch ----------------
__global__ __launch_bounds__(512) void k_scan_mma()
{
    extern __shared__ char smem[];
    bf16* MHs = (bf16*)(smem + SM_MH);
    bf16* MLs = (bf16*)(smem + SM_ML);
    bf16* VHs = (bf16*)(smem + SM_VH);
    bf16* VLs = (bf16*)(smem + SM_VL);
    bf16* EHs = (bf16*)(smem + SM_EH);
    bf16* ELs = (bf16*)(smem + SM_EL);
    bf16* UHs = (bf16*)(smem + SM_UH);
    bf16* ULs = (bf16*)(smem + SM_UL);
    float* SLOC = (float*)(smem + SM_SLOC);
    bf16* SINH = (bf16*)(smem + SM_SINH);
    bf16* SINL = (bf16*)(smem + SM_SINL);
    float2* GBUF = (float2*)(smem + SM_GBUF);   // [32 g][16 n]

    int t = threadIdx.x;
    int bh = blockIdx.x;
    int h = bh & 63;
    int wid = t >> 5, lane = t & 31;   // wid 0..15

    {
        const u32* gmh = (const u32*)(g_Mh + (size_t)h * 4096);
        const u32* gml = (const u32*)(g_Ml + (size_t)h * 4096);
        u32* smh = (u32*)MHs; u32* sml = (u32*)MLs;
        for (int i = t; i < 2048; i += 512) {
            int r = i >> 5, c = i & 31;
            smh[r * 36 + c] = gmh[i]; sml[r * 36 + c] = gml[i];
        }
        const u32* gvh = (const u32*)(g_Vh + (size_t)h * 2048);
        const u32* gvl = (const u32*)(g_Vl + (size_t)h * 2048);
        u32* svh = (u32*)VHs; u32* svl = (u32*)VLs;
        for (int i = t; i < 1024; i += 512) {
            int r = i >> 5, c = i & 31;
            svh[r * 36 + c] = gvh[i]; svl[r * 36 + c] = gvl[i];
        }
        const u32* geh = (const u32*)(g_Eh + (size_t)h * 2048);
        const u32* gel = (const u32*)(g_El + (size_t)h * 2048);
        u32* seh = (u32*)EHs; u32* sel = (u32*)ELs;
        for (int i = t; i < 1024; i += 512) {
            int r = i >> 4, c = i & 15;
            seh[r * 20 + c] = geh[i]; sel[r * 20 + c] = gel[i];
        }
    }

    const float4* gu4 = (const float4*)(g_u + (size_t)bh * LL);
    float4 v[4];
    load_q(gu4, 0, t, v);

    // ---- pass 1: S_local = V @ U (warp = 8 chunks) ----
    for (int q = 0; q < 4; q++) {
        __syncthreads();
        store_q(v, UHs, ULs, t);
        __syncthreads();
        if (q < 3) load_q(gu4, q + 1, t, v);
        int cloc = wid * 8, cglob = q * 128 + cloc;
        float C1[2][4] = {};
        #pragma unroll
        for (int kt = 0; kt < 4; kt++) {
            int k0 = kt * 16;
            u32 bh_[2], bl_[2];
            ldB(bh_, UHs, USTR, cloc, k0, lane);
            ldB(bl_, ULs, USTR, cloc, k0, lane);
            #pragma unroll
            for (int mt = 0; mt < 2; mt++) {
                u32 ah[4], al[4];
                ldA(ah, VHs, VSTR, mt * 16, k0, lane);
                ldA(al, VLs, VSTR, mt * 16, k0, lane);
                mma16816(C1[mt], ah, bh_);
                mma16816(C1[mt], ah, bl_);
                mma16816(C1[mt], al, bh_);
            }
        }
        #pragma unroll
        for (int mt = 0; mt < 2; mt++) {
            int r = mt * 16 + (lane >> 2);
            int cc = cglob + (lane & 3) * 2;
            SLOC[r * LSTR + cc] = C1[mt][0];
            SLOC[r * LSTR + cc + 1] = C1[mt][1];
            SLOC[(r + 8) * LSTR + cc] = C1[mt][2];
            SLOC[(r + 8) * LSTR + cc + 1] = C1[mt][3];
        }
    }
    __syncthreads();

    // ---- chunk-state scan: 32 groups x 16 chunks ----
    {
        int n = t & 15, g = t >> 4;   // g 0..31
        float2 w64 = g_w64c[h * 16 + n];
        float sr = 0.f, si = 0.f;
        for (int m = 0; m < 16; m++) {
            int c = g * 16 + m;
            float xr = SLOC[n * LSTR + c], xi = SLOC[(16 + n) * LSTR + c];
            float nr = fmaf(w64.x, sr, fmaf(-w64.y, si, xr));
            si = fmaf(w64.x, si, fmaf(w64.y, sr, xi));
            sr = nr;
        }
        GBUF[g * 16 + n] = make_float2(sr, si);
        __syncthreads();
        if (t < 16) {
            float2 wG = g_wGc[h * 16 + t];   // w^1024
            float pr = 0.f, pi = 0.f;
            for (int gg = 0; gg < 32; gg++) {
                float2 tm = GBUF[gg * 16 + t];
                GBUF[gg * 16 + t] = make_float2(pr, pi);
                float nr = fmaf(wG.x, pr, fmaf(-wG.y, pi, tm.x));
                pi = fmaf(wG.x, pi, fmaf(wG.y, pr, tm.y));
                pr = nr;
            }
        }
        __syncthreads();
        float2 I = GBUF[g * 16 + n];
        sr = I.x; si = I.y;
        for (int m = 0; m < 16; m++) {
            int c = g * 16 + m;
            bsplit(sr, &SINH[c * SSTR + n], &SINL[c * SSTR + n]);
            bsplit(si, &SINH[c * SSTR + 16 + n], &SINL[c * SSTR + 16 + n]);
            float xr = SLOC[n * LSTR + c], xi = SLOC[(16 + n) * LSTR + c];
            float nr = fmaf(w64.x, sr, fmaf(-w64.y, si, xr));
            si = fmaf(w64.x, si, fmaf(w64.y, sr, xi));
            sr = nr;
        }
    }

    // ---- pass 2: Y = M@U + E@S_in, FiLM, writeback ----
    float gam = g_gamma[bh];
    float bet = g_beta[bh];
    float* Ys = SLOC;
    float4* gz4 = (float4*)(g_z + (size_t)bh * LL);
    load_q(gu4, 0, t, v);

    for (int q = 0; q < 4; q++) {
        __syncthreads();
        store_q(v, UHs, ULs, t);
        __syncthreads();
        if (q < 3) load_q(gu4, q + 1, t, v);
        int cloc = wid * 8, cglob = q * 128 + cloc;
        float C2[4][4] = {};
        #pragma unroll
        for (int kt = 0; kt < 4; kt++) {
            int k0 = kt * 16;
            u32 bh_[2], bl_[2];
            ldB(bh_, UHs, USTR, cloc, k0, lane);
            ldB(bl_, ULs, USTR, cloc, k0, lane);
            #pragma unroll
            for (int mt = 0; mt < 4; mt++) {
                if (kt > mt) continue;
                u32 ah[4], al[4];
                ldA(ah, MHs, MSTR, mt * 16, k0, lane);
                ldA(al, MLs, MSTR, mt * 16, k0, lane);
                mma16816(C2[mt], ah, bh_);
                mma16816(C2[mt], ah, bl_);
                mma16816(C2[mt], al, bh_);
            }
        }
        #pragma unroll
        for (int kt = 0; kt < 2; kt++) {
            int k0 = kt * 16;
            u32 bh_[2], bl_[2];
            ldB(bh_, SINH, SSTR, cglob, k0, lane);
            ldB(bl_, SINL, SSTR, cglob, k0, lane);
            #pragma unroll
            for (int mt = 0; mt < 4; mt++) {
                u32 ah[4], al[4];
                ldA(ah, EHs, ESTR, mt * 16, k0, lane);
                ldA(al, ELs, ESTR, mt * 16, k0, lane);
                mma16816(C2[mt], ah, bh_);
                mma16816(C2[mt], ah, bl_);
                mma16816(C2[mt], al, bh_);
            }
        }
        #pragma unroll
        for (int mt = 0; mt < 4; mt++) {
            int j = mt * 16 + (lane >> 2);
            int cc = cloc + (lane & 3) * 2;
            Ys[cc * YSTR + j] = fmaf(C2[mt][0], gam, bet);
            Ys[(cc + 1) * YSTR + j] = fmaf(C2[mt][1], gam, bet);
            Ys[cc * YSTR + j + 8] = fmaf(C2[mt][2], gam, bet);
            Ys[(cc + 1) * YSTR + j + 8] = fmaf(C2[mt][3], gam, bet);
        }
        __syncthreads();
        #pragma unroll
        for (int k = 0; k < 4; k++) {
            int f = t + k * 512;
            int c = f >> 4, qq = f & 15;
            float4 o = *(const float4*)&Ys[c * YSTR + qq * 4];
            gz4[q * 2048 + f] = o;
        }
    }
}

// ---------------- K4: out = x * gelu(z) ----------------
__global__ __launch_bounds__(256) void k_epilogue(const float* __restrict__ x,
                                                  float* __restrict__ out)
{
    __shared__ float zt[64 * 65];
    int t = threadIdx.x;
    int b = blockIdx.x >> 9;
    int tile = blockIdx.x & 511;
    int l0 = tile * 64;
    #pragma unroll
    for (int i = t; i < 1024; i += 256) {
        int hh = i >> 4, q = i & 15;
        float4 v = *reinterpret_cast<const float4*>(
            g_z + ((size_t)b * HH + hh) * LL + l0 + 4 * q);
        float* d = zt + hh * 65 + 4 * q;
        d[0] = v.x; d[1] = v.y; d[2] = v.z; d[3] = v.w;
    }
    __syncthreads();
    #pragma unroll
    for (int i = t; i < 1024; i += 256) {
        int l = i >> 4, hq = i & 15;
        float z0 = zt[(4 * hq + 0) * 65 + l];
        float z1 = zt[(4 * hq + 1) * 65 + l];
        float z2 = zt[(4 * hq + 2) * 65 + l];
        float z3 = zt[(4 * hq + 3) * 65 + l];
        size_t base = ((size_t)b * LL + l0 + l) * HH + 4 * hq;
        float4 xv = *reinterpret_cast<const float4*>(x + base);
        float4 o;
        o.x = xv.x * gelu_f(z0);
        o.y = xv.y * gelu_f(z1);
        o.z = xv.z * gelu_f(z2);
        o.w = xv.w * gelu_f(z3);
        *reinterpret_cast<float4*>(out + base) = o;
    }
}

// ---------------- launch ----------------
extern "C" void kernel_launch(void* const* d_in, const int* in_sizes, int n_in,
                              void* d_out, int out_size)
{
    const float* x      = (const float*)d_in[0];
    const float* cp     = (const float*)d_in[1];
    const float* W0     = (const float*)d_in[2];
    const float* b0     = (const float*)d_in[3];
    const float* W1     = (const float*)d_in[4];
    const float* b1     = (const float*)d_in[5];
    const float* W2     = (const float*)d_in[6];
    const float* b2     = (const float*)d_in[7];
    const float* W_lin  = (const float*)d_in[8];
    const float* b_lin  = (const float*)d_in[9];
    const float* log_dt = (const float*)d_in[10];
    const float* A_re   = (const float*)d_in[11];
    const float* A_im   = (const float*)d_in[12];
    const float* C_re   = (const float*)d_in[13];
    const float* C_im   = (const float*)d_in[14];
    const float* Dv     = (const float*)d_in[15];
    const float* W_film = (const float*)d_in[16];
    const float* b_film = (const float*)d_in[17];
    float* out = (float*)d_out;

    cudaFuncSetAttribute(k_linear_mma, cudaFuncAttributeMaxDynamicSharedMemorySize, LM_TOT);
    cudaFuncSetAttribute(k_scan_mma, cudaFuncAttributeMaxDynamicSharedMemorySize, SM_TOT);

    k_setup_tab<<<HH, 64>>>(log_dt, A_re, A_im, C_re, C_im, Dv);
    k_setup_mlp<<<1, 256>>>(cp, W0, b0, W1, b1, W2, b2, W_film, b_film);
    k_linear_mma<<<BB * (LL / 256), 256, LM_TOT>>>(x, W_lin, b_lin);
    k_scan_mma<<<BB * HH, 512, SM_TOT>>>();
    k_epilogue<<<BB * (LL / 64), 256>>>(x, out);
}

// round 11
// speedup vs baseline: 1.6688x; 1.0361x over previous
#include <cuda_runtime.h>
#include <cuda_bf16.h>
#include <cstdint>
#include <cstddef>

#define BB 16
#define LL 32768
#define HH 64
#define NN 16
#define DMM 32

typedef unsigned long long u64;
typedef uint32_t u32;
typedef __nv_bfloat16 bf16;

// strides (elements)
#define USTR 72
#define MSTR 72
#define VSTR 72
#define ESTR 40
#define SSTR 40
#define YSTR 68
#define LSTR 521

// scan smem byte offsets (total 227456 <= 232448)
#define SM_MH 0
#define SM_ML 9216
#define SM_VH 18432
#define SM_VL 23040
#define SM_EH 27648
#define SM_EL 32768
#define SM_UH 37888
#define SM_UL 56320
#define SM_SLOC 74752
#define SM_SINH 141440
#define SM_SINL 182400
#define SM_GBUF 223360
#define SM_TOT 227456

// linear-mma smem
#define LM_WTH 0
#define LM_WTL 9216
#define LM_BS 18432
#define LM_XH 18688
#define LM_XL 55552
#define LM_YS 18688
#define LM_TOT 92416
#define XSTR 72
#define WSTR 72
#define YL 264

// ---------------- scratch ----------------
__device__ u32 g_u[(size_t)BB * HH * LL];    // packed (bf16 hi | bf16 lo) per element
__device__ float g_z[(size_t)BB * HH * LL];
__device__ bf16 g_Mh[HH * 4096], g_Ml[HH * 4096];
__device__ bf16 g_Vh[HH * 2048], g_Vl[HH * 2048];
__device__ bf16 g_Eh[HH * 2048], g_El[HH * 2048];
__device__ bf16 g_WH[4096], g_WL[4096];      // W transposed [h][k], split
__device__ float2 g_w64c[HH * 16], g_wGc[HH * 16];
__device__ float g_gamma[BB * HH], g_beta[BB * HH];

// ---------------- helpers ----------------
__device__ __forceinline__ float gelu_f(float x) {
    float x3 = x * x * x;
    float z = 0.7978845608028654f * fmaf(0.044715f, x3, x);
    float az = fabsf(z);
    float e = __expf(2.0f * az);
    float t = 1.0f - __fdividef(2.0f, e + 1.0f);
    t = copysignf(t, z);
    return 0.5f * x * (1.0f + t);
}
__device__ __forceinline__ void bsplit(float v, bf16* ph, bf16* pl) {
    bf16 hi = __float2bfloat16(v);
    *ph = hi; *pl = __float2bfloat16(v - __bfloat162float(hi));
}
__device__ __forceinline__ u32 pk2bf(bf16 a, bf16 b) {
    __nv_bfloat162 v; v.x = a; v.y = b; return *reinterpret_cast<u32*>(&v);
}
__device__ __forceinline__ u32 pack_split(float v) {
    bf16 hi = __float2bfloat16(v);
    bf16 lo = __float2bfloat16(v - __bfloat162float(hi));
    return pk2bf(hi, lo);
}
__device__ __forceinline__ float2 cmulf(float2 a, float2 b) {
    return make_float2(a.x * b.x - a.y * b.y, a.x * b.y + a.y * b.x);
}
__device__ __forceinline__ float2 cpowf(float2 w, int e) {
    float2 r = make_float2(1.0f, 0.0f);
    while (e) {
        if (e & 1) r = cmulf(r, w);
        w = cmulf(w, w);
        e >>= 1;
    }
    return r;
}
__device__ __forceinline__ void mma16816(float* c, const u32* a, const u32* b) {
    asm volatile(
        "mma.sync.aligned.m16n8k16.row.col.f32.bf16.bf16.f32 "
        "{%0,%1,%2,%3}, {%4,%5,%6,%7}, {%8,%9}, {%0,%1,%2,%3};"
        : "+f"(c[0]), "+f"(c[1]), "+f"(c[2]), "+f"(c[3])
        : "r"(a[0]), "r"(a[1]), "r"(a[2]), "r"(a[3]), "r"(b[0]), "r"(b[1]));
}
// ldmatrix fragment loads (distribution == manual mma layout)
__device__ __forceinline__ void ldsm_x4(u32* r, const bf16* base, int stride,
                                        int r0, int k0, int lane) {
    const bf16* p = base + (r0 + (lane & 15)) * stride + k0 + (lane >> 4) * 8;
    u32 addr = (u32)__cvta_generic_to_shared(p);
    asm volatile("ldmatrix.sync.aligned.m8n8.x4.shared.b16 {%0,%1,%2,%3}, [%4];"
        : "=r"(r[0]), "=r"(r[1]), "=r"(r[2]), "=r"(r[3]) : "r"(addr));
}
__device__ __forceinline__ void ldsm_x2(u32* r, const bf16* base, int stride,
                                        int n0, int k0, int lane) {
    const bf16* p = base + (n0 + (lane & 7)) * stride + k0 + ((lane >> 3) & 1) * 8;
    u32 addr = (u32)__cvta_generic_to_shared(p);
    asm volatile("ldmatrix.sync.aligned.m8n8.x2.shared.b16 {%0,%1}, [%2];"
        : "=r"(r[0]), "=r"(r[1]) : "r"(addr));
}
// staging from packed g_u (512 threads): PRMT repack, no converts
__device__ __forceinline__ void load_q(const uint4* gu4, int q, int t, uint4* v) {
    #pragma unroll
    for (int k = 0; k < 4; k++) v[k] = gu4[q * 2048 + t + k * 512];
}
__device__ __forceinline__ void store_q(const uint4* v, bf16* UH, bf16* UL, int t) {
    #pragma unroll
    for (int k = 0; k < 4; k++) {
        int f = t + k * 512;
        int c = f >> 4, i0 = (f & 15) * 4;
        u32 w0 = v[k].x, w1 = v[k].y, w2 = v[k].z, w3 = v[k].w;
        *(u32*)&UH[c * USTR + i0]     = __byte_perm(w0, w1, 0x5410);
        *(u32*)&UH[c * USTR + i0 + 2] = __byte_perm(w2, w3, 0x5410);
        *(u32*)&UL[c * USTR + i0]     = __byte_perm(w0, w1, 0x7632);
        *(u32*)&UL[c * USTR + i0 + 2] = __byte_perm(w2, w3, 0x7632);
    }
}

// ---------------- K0: per-h tables ----------------
__global__ void k_setup_tab(const float* __restrict__ log_dt,
                            const float* __restrict__ A_re, const float* __restrict__ A_im,
                            const float* __restrict__ C_re, const float* __restrict__ C_im,
                            const float* __restrict__ Dv)
{
    int h = blockIdx.x;
    int j = threadIdx.x;
    __shared__ float2 wf[NN];
    __shared__ float2 c2f[NN];
    __shared__ float Ks[64];

    double dt = exp((double)log_dt[h]);
    if (j < NN) {
        int i = h * NN + j;
        float ar = A_re[i], ai = A_im[i];
        double mre = dt * (double)ar, mim = dt * (double)ai;
        double e1 = exp(mre);
        float wr = (float)(e1 * cos(mim)), wi = (float)(e1 * sin(mim));
        wf[j] = make_float2(wr, wi);
        float den = ar * ar + ai * ai;
        float nr = wr - 1.0f, ni = wi;
        float qr = (nr * ar + ni * ai) / den, qi = (ni * ar - nr * ai) / den;
        float cr = C_re[i], ci = C_im[i];
        c2f[j] = make_float2(2.0f * (cr * qr - ci * qi), 2.0f * (cr * qi + ci * qr));
        float2 w64 = cpowf(make_float2(wr, wi), 64);
        g_w64c[h * 16 + j] = w64;
        g_wGc[h * 16 + j] = cpowf(w64, 16);
    }
    __syncthreads();

    float kacc = 0.0f;
    for (int n = 0; n < NN; n++) {
        float2 w = wf[n];
        float2 c2 = c2f[n];
        float2 wj = cpowf(w, j);
        kacc += c2.x * wj.x - c2.y * wj.y;
        float2 wj1 = cmulf(wj, w);
        bsplit(c2.x * wj1.x - c2.y * wj1.y,
               &g_Eh[h * 2048 + j * 32 + n], &g_El[h * 2048 + j * 32 + n]);
        bsplit(-(c2.x * wj1.y + c2.y * wj1.x),
               &g_Eh[h * 2048 + j * 32 + 16 + n], &g_El[h * 2048 + j * 32 + 16 + n]);
        float2 wv = cpowf(w, 63 - j);
        bsplit(wv.x, &g_Vh[h * 2048 + n * 64 + j], &g_Vl[h * 2048 + n * 64 + j]);
        bsplit(wv.y, &g_Vh[h * 2048 + (16 + n) * 64 + j], &g_Vl[h * 2048 + (16 + n) * 64 + j]);
    }
    Ks[j] = kacc;
    __syncthreads();

    float dD = Dv[h];
    for (int i2 = 0; i2 < 64; i2++) {
        float m = (i2 < j) ? Ks[j - i2] : (i2 == j ? Ks[0] + dD : 0.0f);
        bsplit(m, &g_Mh[h * 4096 + j * 64 + i2], &g_Ml[h * 4096 + j * 64 + i2]);
    }
}

// ---------------- K1: conditioning MLP + FiLM + W pre-split ----------------
__global__ void k_setup_mlp(const float* __restrict__ cp,
                            const float* __restrict__ W0, const float* __restrict__ b0,
                            const float* __restrict__ W1, const float* __restrict__ b1,
                            const float* __restrict__ W2, const float* __restrict__ b2,
                            const float* __restrict__ W_film, const float* __restrict__ b_film,
                            const float* __restrict__ W_lin)
{
    __shared__ float c0[BB * DMM];
    __shared__ float c1[BB * DMM];
    int t = threadIdx.x;
    // W transpose + split (once for whole run)
    for (int i = t; i < 4096; i += 256) {
        int k = i >> 6, h = i & 63;
        bsplit(W_lin[i], &g_WH[h * 64 + k], &g_WL[h * 64 + k]);
    }
    for (int i = t; i < BB * DMM; i += blockDim.x) {
        int b = i / DMM, d = i % DMM;
        float v = fmaf(cp[b * 2 + 0], W0[d], fmaf(cp[b * 2 + 1], W0[DMM + d], b0[d]));
        c0[i] = gelu_f(v);
    }
    __syncthreads();
    for (int i = t; i < BB * DMM; i += blockDim.x) {
        int b = i / DMM, d = i % DMM;
        float v = b1[d];
        for (int k = 0; k < DMM; k++) v = fmaf(c0[b * DMM + k], W1[k * DMM + d], v);
        c1[i] = gelu_f(v);
    }
    __syncthreads();
    for (int i = t; i < BB * DMM; i += blockDim.x) {
        int b = i / DMM, d = i % DMM;
        float v = b2[d];
        for (int k = 0; k < DMM; k++) v = fmaf(c1[b * DMM + k], W2[k * DMM + d], v);
        c0[i] = gelu_f(v);
    }
    __syncthreads();
    for (int i = t; i < BB * 2 * HH; i += blockDim.x) {
        int b = i / (2 * HH), j = i % (2 * HH);
        float v = b_film[j];
        for (int k = 0; k < DMM; k++) v = fmaf(c0[b * DMM + k], W_film[k * 2 * HH + j], v);
        if (j < HH) g_gamma[b * HH + j] = v;
        else        g_beta[b * HH + j - HH] = v;
    }
}

// ---------------- K2: u = gelu(x @ W_lin + b) via MMA + LDSM; writes packed g_u ----------------
__global__ __launch_bounds__(256, 2) void k_linear_mma(const float* __restrict__ x,
                                                       const float* __restrict__ bias)
{
    extern __shared__ char sm[];
    bf16* WtH = (bf16*)(sm + LM_WTH);
    bf16* WtL = (bf16*)(sm + LM_WTL);
    float* bs = (float*)(sm + LM_BS);
    bf16* XH = (bf16*)(sm + LM_XH);
    bf16* XL = (bf16*)(sm + LM_XL);
    u32* Ysu = (u32*)(sm + LM_YS);   // overlays XH/XL after MMA

    int t = threadIdx.x, wid = t >> 5, lane = t & 31;
    int b = blockIdx.x >> 7, tile = blockIdx.x & 127;
    int l0 = tile * 256;

    // stage pre-split W (u32 copies), bias
    {
        const u32* gwh = (const u32*)g_WH;
        const u32* gwl = (const u32*)g_WL;
        u32* swh = (u32*)WtH; u32* swl = (u32*)WtL;
        for (int i = t; i < 2048; i += 256) {
            int r = i >> 5, c = i & 31;
            swh[r * 36 + c] = gwh[i];
            swl[r * 36 + c] = gwl[i];
        }
    }
    if (t < 64) bs[t] = bias[t];
    // stage x split
    const float4* xg4 = (const float4*)(x + ((size_t)b * LL + l0) * HH);
    #pragma unroll
    for (int kk = 0; kk < 16; kk++) {
        int f = t + kk * 256;
        float4 v = xg4[f];
        int l = f >> 4, i0 = (f & 15) * 4;
        bf16 h0, l0b, h1, l1b, h2, l2b, h3, l3b;
        bsplit(v.x, &h0, &l0b); bsplit(v.y, &h1, &l1b);
        bsplit(v.z, &h2, &l2b); bsplit(v.w, &h3, &l3b);
        *(u32*)&XH[l * XSTR + i0] = pk2bf(h0, h1);
        *(u32*)&XH[l * XSTR + i0 + 2] = pk2bf(h2, h3);
        *(u32*)&XL[l * XSTR + i0] = pk2bf(l0b, l1b);
        *(u32*)&XL[l * XSTR + i0 + 2] = pk2bf(l2b, l3b);
    }
    __syncthreads();

    float C[2][8][4];
    #pragma unroll
    for (int mt = 0; mt < 2; mt++)
        #pragma unroll
        for (int nt = 0; nt < 8; nt++) {
            int c0 = nt * 8 + (lane & 3) * 2;
            C[mt][nt][0] = bs[c0]; C[mt][nt][1] = bs[c0 + 1];
            C[mt][nt][2] = bs[c0]; C[mt][nt][3] = bs[c0 + 1];
        }
    #pragma unroll
    for (int kt = 0; kt < 4; kt++) {
        int k0 = kt * 16;
        u32 ah[2][4], al[2][4];
        #pragma unroll
        for (int mt = 0; mt < 2; mt++) {
            ldsm_x4(ah[mt], XH, XSTR, wid * 32 + mt * 16, k0, lane);
            ldsm_x4(al[mt], XL, XSTR, wid * 32 + mt * 16, k0, lane);
        }
        #pragma unroll
        for (int nt = 0; nt < 8; nt++) {
            u32 bh[2], bl[2];
            ldsm_x2(bh, WtH, WSTR, nt * 8, k0, lane);
            ldsm_x2(bl, WtL, WSTR, nt * 8, k0, lane);
            #pragma unroll
            for (int mt = 0; mt < 2; mt++) {
                mma16816(C[mt][nt], ah[mt], bh);
                mma16816(C[mt][nt], ah[mt], bl);
                mma16816(C[mt][nt], al[mt], bh);
            }
        }
    }
    __syncthreads();   // XH/XL reads done before Ysu overlay writes
    #pragma unroll
    for (int mt = 0; mt < 2; mt++)
        #pragma unroll
        for (int nt = 0; nt < 8; nt++) {
            int l = wid * 32 + mt * 16 + (lane >> 2);
            int h0 = nt * 8 + (lane & 3) * 2;
            Ysu[h0 * YL + l] = pack_split(gelu_f(C[mt][nt][0]));
            Ysu[(h0 + 1) * YL + l] = pack_split(gelu_f(C[mt][nt][1]));
            Ysu[h0 * YL + l + 8] = pack_split(gelu_f(C[mt][nt][2]));
            Ysu[(h0 + 1) * YL + l + 8] = pack_split(gelu_f(C[mt][nt][3]));
        }
    __syncthreads();
    #pragma unroll
    for (int i = t; i < 4096; i += 256) {
        int h = i >> 6, q = i & 63;
        uint4 v = *(const uint4*)&Ysu[h * YL + q * 4];
        *(uint4*)(g_u + ((size_t)b * HH + h) * LL + l0 + q * 4) = v;
    }
}

// ---------------- K3: chunked S4 conv, 512 threads, LDSM + prefetch ----------------
__global__ __launch_bounds__(512) void k_scan_mma()
{
    extern __shared__ char smem[];
    bf16* MHs = (bf16*)(smem + SM_MH);
    bf16* MLs = (bf16*)(smem + SM_ML);
    bf16* VHs = (bf16*)(smem + SM_VH);
    bf16* VLs = (bf16*)(smem + SM_VL);
    bf16* EHs = (bf16*)(smem + SM_EH);
    bf16* ELs = (bf16*)(smem + SM_EL);
    bf16* UHs = (bf16*)(smem + SM_UH);
    bf16* ULs = (bf16*)(smem + SM_UL);
    float* SLOC = (float*)(smem + SM_SLOC);
    bf16* SINH = (bf16*)(smem + SM_SINH);
    bf16* SINL = (bf16*)(smem + SM_SINL);
    float2* GBUF = (float2*)(smem + SM_GBUF);

    int t = threadIdx.x;
    int bh = blockIdx.x;
    int h = bh & 63;
    int wid = t >> 5, lane = t & 31;

    {
        const u32* gmh = (const u32*)(g_Mh + (size_t)h * 4096);
        const u32* gml = (const u32*)(g_Ml + (size_t)h * 4096);
        u32* smh = (u32*)MHs; u32* sml = (u32*)MLs;
        for (int i = t; i < 2048; i += 512) {
            int r = i >> 5, c = i & 31;
            smh[r * 36 + c] = gmh[i]; sml[r * 36 + c] = gml[i];
        }
        const u32* gvh = (const u32*)(g_Vh + (size_t)h * 2048);
        const u32* gvl = (const u32*)(g_Vl + (size_t)h * 2048);
        u32* svh = (u32*)VHs; u32* svl = (u32*)VLs;
        for (int i = t; i < 1024; i += 512) {
            int r = i >> 5, c = i & 31;
            svh[r * 36 + c] = gvh[i]; svl[r * 36 + c] = gvl[i];
        }
        const u32* geh = (const u32*)(g_Eh + (size_t)h * 2048);
        const u32* gel = (const u32*)(g_El + (size_t)h * 2048);
        u32* seh = (u32*)EHs; u32* sel = (u32*)ELs;
        for (int i = t; i < 1024; i += 512) {
            int r = i >> 4, c = i & 15;
            seh[r * 20 + c] = geh[i]; sel[r * 20 + c] = gel[i];
        }
    }

    const uint4* gu4 = (const uint4*)(g_u + (size_t)bh * LL);
    uint4 v[4];
    load_q(gu4, 0, t, v);

    // ---- pass 1: S_local = V @ U ----
    for (int q = 0; q < 4; q++) {
        __syncthreads();
        store_q(v, UHs, ULs, t);
        __syncthreads();
        if (q < 3) load_q(gu4, q + 1, t, v);
        int cloc = wid * 8, cglob = q * 128 + cloc;
        float C1[2][4] = {};
        #pragma unroll
        for (int kt = 0; kt < 4; kt++) {
            int k0 = kt * 16;
            u32 bh_[2], bl_[2];
            ldsm_x2(bh_, UHs, USTR, cloc, k0, lane);
            ldsm_x2(bl_, ULs, USTR, cloc, k0, lane);
            #pragma unroll
            for (int mt = 0; mt < 2; mt++) {
                u32 ah[4], al[4];
                ldsm_x4(ah, VHs, VSTR, mt * 16, k0, lane);
                ldsm_x4(al, VLs, VSTR, mt * 16, k0, lane);
                mma16816(C1[mt], ah, bh_);
                mma16816(C1[mt], ah, bl_);
                mma16816(C1[mt], al, bh_);
            }
        }
        #pragma unroll
        for (int mt = 0; mt < 2; mt++) {
            int r = mt * 16 + (lane >> 2);
            int cc = cglob + (lane & 3) * 2;
            SLOC[r * LSTR + cc] = C1[mt][0];
            SLOC[r * LSTR + cc + 1] = C1[mt][1];
            SLOC[(r + 8) * LSTR + cc] = C1[mt][2];
            SLOC[(r + 8) * LSTR + cc + 1] = C1[mt][3];
        }
    }
    __syncthreads();

    // ---- chunk-state scan: 32 groups x 16 chunks ----
    {
        int n = t & 15, g = t >> 4;
        float2 w64 = g_w64c[h * 16 + n];
        float sr = 0.f, si = 0.f;
        for (int m = 0; m < 16; m++) {
            int c = g * 16 + m;
            float xr = SLOC[n * LSTR + c], xi = SLOC[(16 + n) * LSTR + c];
            float nr = fmaf(w64.x, sr, fmaf(-w64.y, si, xr));
            si = fmaf(w64.x, si, fmaf(w64.y, sr, xi));
            sr = nr;
        }
        GBUF[g * 16 + n] = make_float2(sr, si);
        __syncthreads();
        if (t < 16) {
            float2 wG = g_wGc[h * 16 + t];
            float pr = 0.f, pi = 0.f;
            for (int gg = 0; gg < 32; gg++) {
                float2 tm = GBUF[gg * 16 + t];
                GBUF[gg * 16 + t] = make_float2(pr, pi);
                float nr = fmaf(wG.x, pr, fmaf(-wG.y, pi, tm.x));
                pi = fmaf(wG.x, pi, fmaf(wG.y, pr, tm.y));
                pr = nr;
            }
        }
        __syncthreads();
        float2 I = GBUF[g * 16 + n];
        sr = I.x; si = I.y;
        for (int m = 0; m < 16; m++) {
            int c = g * 16 + m;
            bsplit(sr, &SINH[c * SSTR + n], &SINL[c * SSTR + n]);
            bsplit(si, &SINH[c * SSTR + 16 + n], &SINL[c * SSTR + 16 + n]);
            float xr = SLOC[n * LSTR + c], xi = SLOC[(16 + n) * LSTR + c];
            float nr = fmaf(w64.x, sr, fmaf(-w64.y, si, xr));
            si = fmaf(w64.x, si, fmaf(w64.y, sr, xi));
            sr = nr;
        }
    }

    // ---- pass 2: Y = M@U + E@S_in, FiLM, writeback ----
    float gam = g_gamma[bh];
    float bet = g_beta[bh];
    float* Ys = SLOC;
    float4* gz4 = (float4*)(g_z + (size_t)bh * LL);
    load_q(gu4, 0, t, v);

    for (int q = 0; q < 4; q++) {
        __syncthreads();
        store_q(v, UHs, ULs, t);
        __syncthreads();
        if (q < 3) load_q(gu4, q + 1, t, v);
        int cloc = wid * 8, cglob = q * 128 + cloc;
        float C2[4][4] = {};
        #pragma unroll
        for (int kt = 0; kt < 4; kt++) {
            int k0 = kt * 16;
            u32 bh_[2], bl_[2];
            ldsm_x2(bh_, UHs, USTR, cloc, k0, lane);
            ldsm_x2(bl_, ULs, USTR, cloc, k0, lane);
            #pragma unroll
            for (int mt = 0; mt < 4; mt++) {
                if (kt > mt) continue;
                u32 ah[4], al[4];
                ldsm_x4(ah, MHs, MSTR, mt * 16, k0, lane);
                ldsm_x4(al, MLs, MSTR, mt * 16, k0, lane);
                mma16816(C2[mt], ah, bh_);
                mma16816(C2[mt], ah, bl_);
                mma16816(C2[mt], al, bh_);
            }
        }
        #pragma unroll
        for (int kt = 0; kt < 2; kt++) {
            int k0 = kt * 16;
            u32 bh_[2], bl_[2];
            ldsm_x2(bh_, SINH, SSTR, cglob, k0, lane);
            ldsm_x2(bl_, SINL, SSTR, cglob, k0, lane);
            #pragma unroll
            for (int mt = 0; mt < 4; mt++) {
                u32 ah[4], al[4];
                ldsm_x4(ah, EHs, ESTR, mt * 16, k0, lane);
                ldsm_x4(al, ELs, ESTR, mt * 16, k0, lane);
                mma16816(C2[mt], ah, bh_);
                mma16816(C2[mt], ah, bl_);
                mma16816(C2[mt], al, bh_);
            }
        }
        #pragma unroll
        for (int mt = 0; mt < 4; mt++) {
            int j = mt * 16 + (lane >> 2);
            int cc = cloc + (lane & 3) * 2;
            Ys[cc * YSTR + j] = fmaf(C2[mt][0], gam, bet);
            Ys[(cc + 1) * YSTR + j] = fmaf(C2[mt][1], gam, bet);
            Ys[cc * YSTR + j + 8] = fmaf(C2[mt][2], gam, bet);
            Ys[(cc + 1) * YSTR + j + 8] = fmaf(C2[mt][3], gam, bet);
        }
        __syncthreads();
        #pragma unroll
        for (int k = 0; k < 4; k++) {
            int f = t + k * 512;
            int c = f >> 4, qq = f & 15;
            float4 o = *(const float4*)&Ys[c * YSTR + qq * 4];
            gz4[q * 2048 + f] = o;
        }
    }
}

// ---------------- K4: out = x * gelu(z) ----------------
__global__ __launch_bounds__(256) void k_epilogue(const float* __restrict__ x,
                                                  float* __restrict__ out)
{
    __shared__ float zt[64 * 65];
    int t = threadIdx.x;
    int b = blockIdx.x >> 9;
    int tile = blockIdx.x & 511;
    int l0 = tile * 64;
    #pragma unroll
    for (int i = t; i < 1024; i += 256) {
        int hh = i >> 4, q = i & 15;
        float4 v = *reinterpret_cast<const float4*>(
            g_z + ((size_t)b * HH + hh) * LL + l0 + 4 * q);
        float* d = zt + hh * 65 + 4 * q;
        d[0] = v.x; d[1] = v.y; d[2] = v.z; d[3] = v.w;
    }
    __syncthreads();
    #pragma unroll
    for (int i = t; i < 1024; i += 256) {
        int l = i >> 4, hq = i & 15;
        float z0 = zt[(4 * hq + 0) * 65 + l];
        float z1 = zt[(4 * hq + 1) * 65 + l];
        float z2 = zt[(4 * hq + 2) * 65 + l];
        float z3 = zt[(4 * hq + 3) * 65 + l];
        size_t base = ((size_t)b * LL + l0 + l) * HH + 4 * hq;
        float4 xv = *reinterpret_cast<const float4*>(x + base);
        float4 o;
        o.x = xv.x * gelu_f(z0);
        o.y = xv.y * gelu_f(z1);
        o.z = xv.z * gelu_f(z2);
        o.w = xv.w * gelu_f(z3);
        *reinterpret_cast<float4*>(out + base) = o;
    }
}

// ---------------- launch ----------------
extern "C" void kernel_launch(void* const* d_in, const int* in_sizes, int n_in,
                              void* d_out, int out_size)
{
    const float* x      = (const float*)d_in[0];
    const float* cp     = (const float*)d_in[1];
    const float* W0     = (const float*)d_in[2];
    const float* b0     = (const float*)d_in[3];
    const float* W1     = (const float*)d_in[4];
    const float* b1     = (const float*)d_in[5];
    const float* W2     = (const float*)d_in[6];
    const float* b2     = (const float*)d_in[7];
    const float* W_lin  = (const float*)d_in[8];
    const float* b_lin  = (const float*)d_in[9];
    const float* log_dt = (const float*)d_in[10];
    const float* A_re   = (const float*)d_in[11];
    const float* A_im   = (const float*)d_in[12];
    const float* C_re   = (const float*)d_in[13];
    const float* C_im   = (const float*)d_in[14];
    const float* Dv     = (const float*)d_in[15];
    const float* W_film = (const float*)d_in[16];
    const float* b_film = (const float*)d_in[17];
    float* out = (float*)d_out;

    cudaFuncSetAttribute(k_linear_mma, cudaFuncAttributeMaxDynamicSharedMemorySize, LM_TOT);
    cudaFuncSetAttribute(k_scan_mma, cudaFuncAttributeMaxDynamicSharedMemorySize, SM_TOT);

    k_setup_tab<<<HH, 64>>>(log_dt, A_re, A_im, C_re, C_im, Dv);
    k_setup_mlp<<<1, 256>>>(cp, W0, b0, W1, b1, W2, b2, W_film, b_film, W_lin);
    k_linear_mma<<<BB * (LL / 256), 256, LM_TOT>>>(x, b_lin);
    k_scan_mma<<<BB * HH, 512, SM_TOT>>>();
    k_epilogue<<<BB * (LL / 64), 256>>>(x, out);
}

// round 12
// speedup vs baseline: 1.7279x; 1.0355x over previous
#include <cuda_runtime.h>
#include <cuda_bf16.h>
#include <cstdint>
#include <cstddef>

#define BB 16
#define LL 32768
#define HH 64
#define NN 16
#define DMM 32

typedef unsigned long long u64;
typedef uint32_t u32;
typedef __nv_bfloat16 bf16;

// strides (elements)
#define USTR 72
#define MSTR 72
#define VSTR 72
#define ESTR 40
#define SSTR 40
#define YSTR 68
#define LSTR 521

// scan smem byte offsets (total 227456 <= 232448)
#define SM_MH 0
#define SM_ML 9216
#define SM_VH 18432
#define SM_VL 23040
#define SM_EH 27648
#define SM_EL 32768
#define SM_UH 37888
#define SM_UL 56320
#define SM_SLOC 74752
#define SM_SINH 141440
#define SM_SINL 182400
#define SM_GBUF 223360
#define SM_TOT 227456

// linear-mma smem
#define LM_WTH 0
#define LM_WTL 9216
#define LM_BS 18432
#define LM_XH 18688
#define LM_XL 55552
#define LM_YS 18688
#define LM_TOT 92416
#define XSTR 72
#define WSTR 72
#define YL 264

// ---------------- scratch ----------------
__device__ u32 g_u[(size_t)BB * HH * LL];    // packed (bf16 hi | bf16 lo)
__device__ float g_z[(size_t)BB * HH * LL];
__device__ bf16 g_Mh[HH * 4096], g_Ml[HH * 4096];
__device__ bf16 g_Vh[HH * 2048], g_Vl[HH * 2048];
__device__ bf16 g_Eh[HH * 2048], g_El[HH * 2048];
__device__ bf16 g_WH[4096], g_WL[4096];
__device__ float2 g_w64c[HH * 16], g_wGc[HH * 16];
__device__ float g_gamma[BB * HH], g_beta[BB * HH];

// ---------------- helpers ----------------
__device__ __forceinline__ float gelu_f(float x) {
    float x3 = x * x * x;
    float z = 0.7978845608028654f * fmaf(0.044715f, x3, x);
    float az = fabsf(z);
    float e = __expf(2.0f * az);
    float t = 1.0f - __fdividef(2.0f, e + 1.0f);
    t = copysignf(t, z);
    return 0.5f * x * (1.0f + t);
}
__device__ __forceinline__ void bsplit(float v, bf16* ph, bf16* pl) {
    bf16 hi = __float2bfloat16(v);
    *ph = hi; *pl = __float2bfloat16(v - __bfloat162float(hi));
}
__device__ __forceinline__ u32 pk2bf(bf16 a, bf16 b) {
    __nv_bfloat162 v; v.x = a; v.y = b; return *reinterpret_cast<u32*>(&v);
}
__device__ __forceinline__ u32 pack_split(float v) {
    bf16 hi = __float2bfloat16(v);
    bf16 lo = __float2bfloat16(v - __bfloat162float(hi));
    return pk2bf(hi, lo);
}
__device__ __forceinline__ float2 cmulf(float2 a, float2 b) {
    return make_float2(a.x * b.x - a.y * b.y, a.x * b.y + a.y * b.x);
}
__device__ __forceinline__ float2 cpowf(float2 w, int e) {
    float2 r = make_float2(1.0f, 0.0f);
    while (e) {
        if (e & 1) r = cmulf(r, w);
        w = cmulf(w, w);
        e >>= 1;
    }
    return r;
}
__device__ __forceinline__ void mma16816(float* c, const u32* a, const u32* b) {
    asm volatile(
        "mma.sync.aligned.m16n8k16.row.col.f32.bf16.bf16.f32 "
        "{%0,%1,%2,%3}, {%4,%5,%6,%7}, {%8,%9}, {%0,%1,%2,%3};"
        : "+f"(c[0]), "+f"(c[1]), "+f"(c[2]), "+f"(c[3])
        : "r"(a[0]), "r"(a[1]), "r"(a[2]), "r"(a[3]), "r"(b[0]), "r"(b[1]));
}
__device__ __forceinline__ void ldsm_x4(u32* r, const bf16* base, int stride,
                                        int r0, int k0, int lane) {
    const bf16* p = base + (r0 + (lane & 15)) * stride + k0 + (lane >> 4) * 8;
    u32 addr = (u32)__cvta_generic_to_shared(p);
    asm volatile("ldmatrix.sync.aligned.m8n8.x4.shared.b16 {%0,%1,%2,%3}, [%4];"
        : "=r"(r[0]), "=r"(r[1]), "=r"(r[2]), "=r"(r[3]) : "r"(addr));
}
__device__ __forceinline__ void ldsm_x2(u32* r, const bf16* base, int stride,
                                        int n0, int k0, int lane) {
    const bf16* p = base + (n0 + (lane & 7)) * stride + k0 + ((lane >> 3) & 1) * 8;
    u32 addr = (u32)__cvta_generic_to_shared(p);
    asm volatile("ldmatrix.sync.aligned.m8n8.x2.shared.b16 {%0,%1}, [%2];"
        : "=r"(r[0]), "=r"(r[1]) : "r"(addr));
}
__device__ __forceinline__ void load_q(const uint4* gu4, int q, int t, uint4* v) {
    #pragma unroll
    for (int k = 0; k < 4; k++) v[k] = gu4[q * 2048 + t + k * 512];
}
__device__ __forceinline__ void store_q(const uint4* v, bf16* UH, bf16* UL, int t) {
    #pragma unroll
    for (int k = 0; k < 4; k++) {
        int f = t + k * 512;
        int c = f >> 4, i0 = (f & 15) * 4;
        u32 w0 = v[k].x, w1 = v[k].y, w2 = v[k].z, w3 = v[k].w;
        *(u32*)&UH[c * USTR + i0]     = __byte_perm(w0, w1, 0x5410);
        *(u32*)&UH[c * USTR + i0 + 2] = __byte_perm(w2, w3, 0x5410);
        *(u32*)&UL[c * USTR + i0]     = __byte_perm(w0, w1, 0x7632);
        *(u32*)&UL[c * USTR + i0 + 2] = __byte_perm(w2, w3, 0x7632);
    }
}

// ---------------- K0: per-h tables ----------------
__global__ void k_setup_tab(const float* __restrict__ log_dt,
                            const float* __restrict__ A_re, const float* __restrict__ A_im,
                            const float* __restrict__ C_re, const float* __restrict__ C_im,
                            const float* __restrict__ Dv)
{
    int h = blockIdx.x;
    int j = threadIdx.x;
    __shared__ float2 wf[NN];
    __shared__ float2 c2f[NN];
    __shared__ float Ks[64];

    double dt = exp((double)log_dt[h]);
    if (j < NN) {
        int i = h * NN + j;
        float ar = A_re[i], ai = A_im[i];
        double mre = dt * (double)ar, mim = dt * (double)ai;
        double e1 = exp(mre);
        float wr = (float)(e1 * cos(mim)), wi = (float)(e1 * sin(mim));
        wf[j] = make_float2(wr, wi);
        float den = ar * ar + ai * ai;
        float nr = wr - 1.0f, ni = wi;
        float qr = (nr * ar + ni * ai) / den, qi = (ni * ar - nr * ai) / den;
        float cr = C_re[i], ci = C_im[i];
        c2f[j] = make_float2(2.0f * (cr * qr - ci * qi), 2.0f * (cr * qi + ci * qr));
        float2 w64 = cpowf(make_float2(wr, wi), 64);
        g_w64c[h * 16 + j] = w64;
        g_wGc[h * 16 + j] = cpowf(w64, 16);
    }
    __syncthreads();

    float kacc = 0.0f;
    for (int n = 0; n < NN; n++) {
        float2 w = wf[n];
        float2 c2 = c2f[n];
        float2 wj = cpowf(w, j);
        kacc += c2.x * wj.x - c2.y * wj.y;
        float2 wj1 = cmulf(wj, w);
        bsplit(c2.x * wj1.x - c2.y * wj1.y,
               &g_Eh[h * 2048 + j * 32 + n], &g_El[h * 2048 + j * 32 + n]);
        bsplit(-(c2.x * wj1.y + c2.y * wj1.x),
               &g_Eh[h * 2048 + j * 32 + 16 + n], &g_El[h * 2048 + j * 32 + 16 + n]);
        float2 wv = cpowf(w, 63 - j);
        bsplit(wv.x, &g_Vh[h * 2048 + n * 64 + j], &g_Vl[h * 2048 + n * 64 + j]);
        bsplit(wv.y, &g_Vh[h * 2048 + (16 + n) * 64 + j], &g_Vl[h * 2048 + (16 + n) * 64 + j]);
    }
    Ks[j] = kacc;
    __syncthreads();

    float dD = Dv[h];
    for (int i2 = 0; i2 < 64; i2++) {
        float m = (i2 < j) ? Ks[j - i2] : (i2 == j ? Ks[0] + dD : 0.0f);
        bsplit(m, &g_Mh[h * 4096 + j * 64 + i2], &g_Ml[h * 4096 + j * 64 + i2]);
    }
}

// ---------------- K1: conditioning MLP + FiLM + W pre-split ----------------
__global__ void k_setup_mlp(const float* __restrict__ cp,
                            const float* __restrict__ W0, const float* __restrict__ b0,
                            const float* __restrict__ W1, const float* __restrict__ b1,
                            const float* __restrict__ W2, const float* __restrict__ b2,
                            const float* __restrict__ W_film, const float* __restrict__ b_film,
                            const float* __restrict__ W_lin)
{
    __shared__ float c0[BB * DMM];
    __shared__ float c1[BB * DMM];
    int t = threadIdx.x;
    for (int i = t; i < 4096; i += 256) {
        int k = i >> 6, h = i & 63;
        bsplit(W_lin[i], &g_WH[h * 64 + k], &g_WL[h * 64 + k]);
    }
    for (int i = t; i < BB * DMM; i += blockDim.x) {
        int b = i / DMM, d = i % DMM;
        float v = fmaf(cp[b * 2 + 0], W0[d], fmaf(cp[b * 2 + 1], W0[DMM + d], b0[d]));
        c0[i] = gelu_f(v);
    }
    __syncthreads();
    for (int i = t; i < BB * DMM; i += blockDim.x) {
        int b = i / DMM, d = i % DMM;
        float v = b1[d];
        for (int k = 0; k < DMM; k++) v = fmaf(c0[b * DMM + k], W1[k * DMM + d], v);
        c1[i] = gelu_f(v);
    }
    __syncthreads();
    for (int i = t; i < BB * DMM; i += blockDim.x) {
        int b = i / DMM, d = i % DMM;
        float v = b2[d];
        for (int k = 0; k < DMM; k++) v = fmaf(c1[b * DMM + k], W2[k * DMM + d], v);
        c0[i] = gelu_f(v);
    }
    __syncthreads();
    for (int i = t; i < BB * 2 * HH; i += blockDim.x) {
        int b = i / (2 * HH), j = i % (2 * HH);
        float v = b_film[j];
        for (int k = 0; k < DMM; k++) v = fmaf(c0[b * DMM + k], W_film[k * 2 * HH + j], v);
        if (j < HH) g_gamma[b * HH + j] = v;
        else        g_beta[b * HH + j - HH] = v;
    }
}

// ---------------- K2: u = gelu(x @ W_lin + b) via MMA + LDSM; writes packed g_u ----------------
__global__ __launch_bounds__(256, 2) void k_linear_mma(const float* __restrict__ x,
                                                       const float* __restrict__ bias)
{
    extern __shared__ char sm[];
    bf16* WtH = (bf16*)(sm + LM_WTH);
    bf16* WtL = (bf16*)(sm + LM_WTL);
    float* bs = (float*)(sm + LM_BS);
    bf16* XH = (bf16*)(sm + LM_XH);
    bf16* XL = (bf16*)(sm + LM_XL);
    u32* Ysu = (u32*)(sm + LM_YS);

    int t = threadIdx.x, wid = t >> 5, lane = t & 31;
    int b = blockIdx.x >> 7, tile = blockIdx.x & 127;
    int l0 = tile * 256;

    {
        const u32* gwh = (const u32*)g_WH;
        const u32* gwl = (const u32*)g_WL;
        u32* swh = (u32*)WtH; u32* swl = (u32*)WtL;
        for (int i = t; i < 2048; i += 256) {
            int r = i >> 5, c = i & 31;
            swh[r * 36 + c] = gwh[i];
            swl[r * 36 + c] = gwl[i];
        }
    }
    if (t < 64) bs[t] = bias[t];
    const float4* xg4 = (const float4*)(x + ((size_t)b * LL + l0) * HH);
    #pragma unroll
    for (int kk = 0; kk < 16; kk++) {
        int f = t + kk * 256;
        float4 v = xg4[f];
        int l = f >> 4, i0 = (f & 15) * 4;
        bf16 h0, l0b, h1, l1b, h2, l2b, h3, l3b;
        bsplit(v.x, &h0, &l0b); bsplit(v.y, &h1, &l1b);
        bsplit(v.z, &h2, &l2b); bsplit(v.w, &h3, &l3b);
        *(u32*)&XH[l * XSTR + i0] = pk2bf(h0, h1);
        *(u32*)&XH[l * XSTR + i0 + 2] = pk2bf(h2, h3);
        *(u32*)&XL[l * XSTR + i0] = pk2bf(l0b, l1b);
        *(u32*)&XL[l * XSTR + i0 + 2] = pk2bf(l2b, l3b);
    }
    __syncthreads();

    float C[2][8][4];
    #pragma unroll
    for (int mt = 0; mt < 2; mt++)
        #pragma unroll
        for (int nt = 0; nt < 8; nt++) {
            int c0 = nt * 8 + (lane & 3) * 2;
            C[mt][nt][0] = bs[c0]; C[mt][nt][1] = bs[c0 + 1];
            C[mt][nt][2] = bs[c0]; C[mt][nt][3] = bs[c0 + 1];
        }
    #pragma unroll
    for (int kt = 0; kt < 4; kt++) {
        int k0 = kt * 16;
        u32 ah[2][4], al[2][4];
        #pragma unroll
        for (int mt = 0; mt < 2; mt++) {
            ldsm_x4(ah[mt], XH, XSTR, wid * 32 + mt * 16, k0, lane);
            ldsm_x4(al[mt], XL, XSTR, wid * 32 + mt * 16, k0, lane);
        }
        #pragma unroll
        for (int nt = 0; nt < 8; nt++) {
            u32 bh[2], bl[2];
            ldsm_x2(bh, WtH, WSTR, nt * 8, k0, lane);
            ldsm_x2(bl, WtL, WSTR, nt * 8, k0, lane);
            #pragma unroll
            for (int mt = 0; mt < 2; mt++) {
                mma16816(C[mt][nt], ah[mt], bh);
                mma16816(C[mt][nt], ah[mt], bl);
                mma16816(C[mt][nt], al[mt], bh);
            }
        }
    }
    __syncthreads();
    #pragma unroll
    for (int mt = 0; mt < 2; mt++)
        #pragma unroll
        for (int nt = 0; nt < 8; nt++) {
            int l = wid * 32 + mt * 16 + (lane >> 2);
            int h0 = nt * 8 + (lane & 3) * 2;
            Ysu[h0 * YL + l] = pack_split(gelu_f(C[mt][nt][0]));
            Ysu[(h0 + 1) * YL + l] = pack_split(gelu_f(C[mt][nt][1]));
            Ysu[h0 * YL + l + 8] = pack_split(gelu_f(C[mt][nt][2]));
            Ysu[(h0 + 1) * YL + l + 8] = pack_split(gelu_f(C[mt][nt][3]));
        }
    __syncthreads();
    #pragma unroll
    for (int i = t; i < 4096; i += 256) {
        int h = i >> 6, q = i & 63;
        uint4 v = *(const uint4*)&Ysu[h * YL + q * 4];
        *(uint4*)(g_u + ((size_t)b * HH + h) * LL + l0 + q * 4) = v;
    }
}

// ---------------- K3: fused single-staging scan: pass1 = V@U + M@U(regs), pass2 = E@S only ----------------
__global__ __launch_bounds__(512) void k_scan_mma()
{
    extern __shared__ char smem[];
    bf16* MHs = (bf16*)(smem + SM_MH);
    bf16* MLs = (bf16*)(smem + SM_ML);
    bf16* VHs = (bf16*)(smem + SM_VH);
    bf16* VLs = (bf16*)(smem + SM_VL);
    bf16* EHs = (bf16*)(smem + SM_EH);
    bf16* ELs = (bf16*)(smem + SM_EL);
    bf16* UHs = (bf16*)(smem + SM_UH);
    bf16* ULs = (bf16*)(smem + SM_UL);
    float* SLOC = (float*)(smem + SM_SLOC);
    bf16* SINH = (bf16*)(smem + SM_SINH);
    bf16* SINL = (bf16*)(smem + SM_SINL);
    float2* GBUF = (float2*)(smem + SM_GBUF);

    int t = threadIdx.x;
    int bh = blockIdx.x;
    int h = bh & 63;
    int wid = t >> 5, lane = t & 31;

    {
        const u32* gmh = (const u32*)(g_Mh + (size_t)h * 4096);
        const u32* gml = (const u32*)(g_Ml + (size_t)h * 4096);
        u32* smh = (u32*)MHs; u32* sml = (u32*)MLs;
        for (int i = t; i < 2048; i += 512) {
            int r = i >> 5, c = i & 31;
            smh[r * 36 + c] = gmh[i]; sml[r * 36 + c] = gml[i];
        }
        const u32* gvh = (const u32*)(g_Vh + (size_t)h * 2048);
        const u32* gvl = (const u32*)(g_Vl + (size_t)h * 2048);
        u32* svh = (u32*)VHs; u32* svl = (u32*)VLs;
        for (int i = t; i < 1024; i += 512) {
            int r = i >> 5, c = i & 31;
            svh[r * 36 + c] = gvh[i]; svl[r * 36 + c] = gvl[i];
        }
        const u32* geh = (const u32*)(g_Eh + (size_t)h * 2048);
        const u32* gel = (const u32*)(g_El + (size_t)h * 2048);
        u32* seh = (u32*)EHs; u32* sel = (u32*)ELs;
        for (int i = t; i < 1024; i += 512) {
            int r = i >> 4, c = i & 15;
            seh[r * 20 + c] = geh[i]; sel[r * 20 + c] = gel[i];
        }
    }

    const uint4* gu4 = (const uint4*)(g_u + (size_t)bh * LL);
    uint4 v[4];
    load_q(gu4, 0, t, v);

    // Ymu accumulators for all 4 quarters (fully unrolled indexing)
    float Yreg[64];
    #pragma unroll
    for (int i = 0; i < 64; i++) Yreg[i] = 0.0f;

    int cloc = wid * 8;

    // ---- fused pass 1: stage U once; V@U -> SLOC, M@U -> Yreg ----
    #pragma unroll
    for (int q = 0; q < 4; q++) {
        __syncthreads();
        store_q(v, UHs, ULs, t);
        __syncthreads();
        if (q < 3) load_q(gu4, q + 1, t, v);
        int cglob = q * 128 + cloc;
        float C1[2][4] = {};
        #pragma unroll
        for (int kt = 0; kt < 4; kt++) {
            int k0 = kt * 16;
            u32 bh_[2], bl_[2];
            ldsm_x2(bh_, UHs, USTR, cloc, k0, lane);
            ldsm_x2(bl_, ULs, USTR, cloc, k0, lane);
            #pragma unroll
            for (int mt = 0; mt < 2; mt++) {
                u32 ah[4], al[4];
                ldsm_x4(ah, VHs, VSTR, mt * 16, k0, lane);
                ldsm_x4(al, VLs, VSTR, mt * 16, k0, lane);
                mma16816(C1[mt], ah, bh_);
                mma16816(C1[mt], ah, bl_);
                mma16816(C1[mt], al, bh_);
            }
            #pragma unroll
            for (int mt = 0; mt < 4; mt++) {
                if (kt > mt) continue;
                u32 ah[4], al[4];
                ldsm_x4(ah, MHs, MSTR, mt * 16, k0, lane);
                ldsm_x4(al, MLs, MSTR, mt * 16, k0, lane);
                float* Cm = &Yreg[q * 16 + mt * 4];
                mma16816(Cm, ah, bh_);
                mma16816(Cm, ah, bl_);
                mma16816(Cm, al, bh_);
            }
        }
        #pragma unroll
        for (int mt = 0; mt < 2; mt++) {
            int r = mt * 16 + (lane >> 2);
            int cc = cglob + (lane & 3) * 2;
            SLOC[r * LSTR + cc] = C1[mt][0];
            SLOC[r * LSTR + cc + 1] = C1[mt][1];
            SLOC[(r + 8) * LSTR + cc] = C1[mt][2];
            SLOC[(r + 8) * LSTR + cc + 1] = C1[mt][3];
        }
    }
    __syncthreads();

    // ---- chunk-state scan: 32 groups x 16 chunks ----
    {
        int n = t & 15, g = t >> 4;
        float2 w64 = g_w64c[h * 16 + n];
        float sr = 0.f, si = 0.f;
        for (int m = 0; m < 16; m++) {
            int c = g * 16 + m;
            float xr = SLOC[n * LSTR + c], xi = SLOC[(16 + n) * LSTR + c];
            float nr = fmaf(w64.x, sr, fmaf(-w64.y, si, xr));
            si = fmaf(w64.x, si, fmaf(w64.y, sr, xi));
            sr = nr;
        }
        GBUF[g * 16 + n] = make_float2(sr, si);
        __syncthreads();
        if (t < 16) {
            float2 wG = g_wGc[h * 16 + t];
            float pr = 0.f, pi = 0.f;
            for (int gg = 0; gg < 32; gg++) {
                float2 tm = GBUF[gg * 16 + t];
                GBUF[gg * 16 + t] = make_float2(pr, pi);
                float nr = fmaf(wG.x, pr, fmaf(-wG.y, pi, tm.x));
                pi = fmaf(wG.x, pi, fmaf(wG.y, pr, tm.y));
                pr = nr;
            }
        }
        __syncthreads();
        float2 I = GBUF[g * 16 + n];
        sr = I.x; si = I.y;
        for (int m = 0; m < 16; m++) {
            int c = g * 16 + m;
            bsplit(sr, &SINH[c * SSTR + n], &SINL[c * SSTR + n]);
            bsplit(si, &SINH[c * SSTR + 16 + n], &SINL[c * SSTR + 16 + n]);
            float xr = SLOC[n * LSTR + c], xi = SLOC[(16 + n) * LSTR + c];
            float nr = fmaf(w64.x, sr, fmaf(-w64.y, si, xr));
            si = fmaf(w64.x, si, fmaf(w64.y, sr, xi));
            sr = nr;
        }
    }
    __syncthreads();

    // ---- pass 2: Y += E@S_in; FiLM; writeback ----
    float gam = g_gamma[bh];
    float bet = g_beta[bh];
    float* Ys = SLOC;
    float4* gz4 = (float4*)(g_z + (size_t)bh * LL);

    #pragma unroll
    for (int q = 0; q < 4; q++) {
        int cglob = q * 128 + cloc;
        #pragma unroll
        for (int kt = 0; kt < 2; kt++) {
            int k0 = kt * 16;
            u32 bh_[2], bl_[2];
            ldsm_x2(bh_, SINH, SSTR, cglob, k0, lane);
            ldsm_x2(bl_, SINL, SSTR, cglob, k0, lane);
            #pragma unroll
            for (int mt = 0; mt < 4; mt++) {
                u32 ah[4], al[4];
                ldsm_x4(ah, EHs, ESTR, mt * 16, k0, lane);
                ldsm_x4(al, ELs, ESTR, mt * 16, k0, lane);
                float* Cm = &Yreg[q * 16 + mt * 4];
                mma16816(Cm, ah, bh_);
                mma16816(Cm, ah, bl_);
                mma16816(Cm, al, bh_);
            }
        }
        #pragma unroll
        for (int mt = 0; mt < 4; mt++) {
            int j = mt * 16 + (lane >> 2);
            int cc = cloc + (lane & 3) * 2;
            const float* Cm = &Yreg[q * 16 + mt * 4];
            Ys[cc * YSTR + j] = fmaf(Cm[0], gam, bet);
            Ys[(cc + 1) * YSTR + j] = fmaf(Cm[1], gam, bet);
            Ys[cc * YSTR + j + 8] = fmaf(Cm[2], gam, bet);
            Ys[(cc + 1) * YSTR + j + 8] = fmaf(Cm[3], gam, bet);
        }
        __syncthreads();
        #pragma unroll
        for (int k = 0; k < 4; k++) {
            int f = t + k * 512;
            int c = f >> 4, qq = f & 15;
            float4 o = *(const float4*)&Ys[c * YSTR + qq * 4];
            gz4[q * 2048 + f] = o;
        }
        __syncthreads();
    }
}

// ---------------- K4: out = x * gelu(z) ----------------
__global__ __launch_bounds__(256) void k_epilogue(const float* __restrict__ x,
                                                  float* __restrict__ out)
{
    __shared__ float zt[64 * 65];
    int t = threadIdx.x;
    int b = blockIdx.x >> 9;
    int tile = blockIdx.x & 511;
    int l0 = tile * 64;
    #pragma unroll
    for (int i = t; i < 1024; i += 256) {
        int hh = i >> 4, q = i & 15;
        float4 v = *reinterpret_cast<const float4*>(
            g_z + ((size_t)b * HH + hh) * LL + l0 + 4 * q);
        float* d = zt + hh * 65 + 4 * q;
        d[0] = v.x; d[1] = v.y; d[2] = v.z; d[3] = v.w;
    }
    __syncthreads();
    #pragma unroll
    for (int i = t; i < 1024; i += 256) {
        int l = i >> 4, hq = i & 15;
        float z0 = zt[(4 * hq + 0) * 65 + l];
        float z1 = zt[(4 * hq + 1) * 65 + l];
        float z2 = zt[(4 * hq + 2) * 65 + l];
        float z3 = zt[(4 * hq + 3) * 65 + l];
        size_t base = ((size_t)b * LL + l0 + l) * HH + 4 * hq;
        float4 xv = *reinterpret_cast<const float4*>(x + base);
        float4 o;
        o.x = xv.x * gelu_f(z0);
        o.y = xv.y * gelu_f(z1);
        o.z = xv.z * gelu_f(z2);
        o.w = xv.w * gelu_f(z3);
        *reinterpret_cast<float4*>(out + base) = o;
    }
}

// ---------------- launch ----------------
extern "C" void kernel_launch(void* const* d_in, const int* in_sizes, int n_in,
                              void* d_out, int out_size)
{
    const float* x      = (const float*)d_in[0];
    const float* cp     = (const float*)d_in[1];
    const float* W0     = (const float*)d_in[2];
    const float* b0     = (const float*)d_in[3];
    const float* W1     = (const float*)d_in[4];
    const float* b1     = (const float*)d_in[5];
    const float* W2     = (const float*)d_in[6];
    const float* b2     = (const float*)d_in[7];
    const float* W_lin  = (const float*)d_in[8];
    const float* b_lin  = (const float*)d_in[9];
    const float* log_dt = (const float*)d_in[10];
    const float* A_re   = (const float*)d_in[11];
    const float* A_im   = (const float*)d_in[12];
    const float* C_re   = (const float*)d_in[13];
    const float* C_im   = (const float*)d_in[14];
    const float* Dv     = (const float*)d_in[15];
    const float* W_film = (const float*)d_in[16];
    const float* b_film = (const float*)d_in[17];
    float* out = (float*)d_out;

    cudaFuncSetAttribute(k_linear_mma, cudaFuncAttributeMaxDynamicSharedMemorySize, LM_TOT);
    cudaFuncSetAttribute(k_scan_mma, cudaFuncAttributeMaxDynamicSharedMemorySize, SM_TOT);

    k_setup_tab<<<HH, 64>>>(log_dt, A_re, A_im, C_re, C_im, Dv);
    k_setup_mlp<<<1, 256>>>(cp, W0, b0, W1, b1, W2, b2, W_film, b_film, W_lin);
    k_linear_mma<<<BB * (LL / 256), 256, LM_TOT>>>(x, b_lin);
    k_scan_mma<<<BB * HH, 512, SM_TOT>>>();
    k_epilogue<<<BB * (LL / 64), 256>>>(x, out);
}

// round 13
// speedup vs baseline: 1.8178x; 1.0520x over previous
#include <cuda_runtime.h>
#include <cuda_bf16.h>
#include <cstdint>
#include <cstddef>

#define BB 16
#define LL 32768
#define HH 64
#define NN 16
#define DMM 32

typedef unsigned long long u64;
typedef uint32_t u32;
typedef __nv_bfloat16 bf16;

// strides (elements)
#define USTR 72
#define MSTR 72
#define VSTR 72
#define ESTR 40
#define SSTR 40
#define YSTR 68
#define LSTR 521

// scan smem (total 227456 <= 232448)
#define SM_MH 0
#define SM_ML 9216
#define SM_VH 18432
#define SM_VL 23040
#define SM_EH 27648
#define SM_EL 32768
#define SM_UB0 37888
#define SM_SLOC 74752
#define SM_UB1 141440
#define SM_UB2 178304
#define SM_SINH 141440
#define SM_SINL 182400
#define SM_GBUF 223360
#define SM_TOT 227456
#define UBUF_HALF 18432   // bytes: 128 chunks * 72 * 2

// linear-mma smem
#define LM_WTH 0
#define LM_WTL 9216
#define LM_BS 18432
#define LM_XH 18688
#define LM_XL 55552
#define LM_YS 18688
#define LM_TOT 92416
#define XSTR 72
#define WSTR 72
#define YL 264

// ---------------- scratch ----------------
__device__ bf16 g_uh[(size_t)BB * HH * LL];
__device__ bf16 g_ul[(size_t)BB * HH * LL];
__device__ float g_z[(size_t)BB * HH * LL];
__device__ bf16 g_Mh[HH * 4096], g_Ml[HH * 4096];
__device__ bf16 g_Vh[HH * 2048], g_Vl[HH * 2048];
__device__ bf16 g_Eh[HH * 2048], g_El[HH * 2048];
__device__ bf16 g_WH[4096], g_WL[4096];
__device__ float2 g_w64c[HH * 16], g_wGc[HH * 16];
__device__ float g_gamma[BB * HH], g_beta[BB * HH];

// ---------------- helpers ----------------
__device__ __forceinline__ float gelu_f(float x) {
    float x3 = x * x * x;
    float z = 0.7978845608028654f * fmaf(0.044715f, x3, x);
    float az = fabsf(z);
    float e = __expf(2.0f * az);
    float t = 1.0f - __fdividef(2.0f, e + 1.0f);
    t = copysignf(t, z);
    return 0.5f * x * (1.0f + t);
}
__device__ __forceinline__ void bsplit(float v, bf16* ph, bf16* pl) {
    bf16 hi = __float2bfloat16(v);
    *ph = hi; *pl = __float2bfloat16(v - __bfloat162float(hi));
}
__device__ __forceinline__ u32 pk2bf(bf16 a, bf16 b) {
    __nv_bfloat162 v; v.x = a; v.y = b; return *reinterpret_cast<u32*>(&v);
}
__device__ __forceinline__ float2 cmulf(float2 a, float2 b) {
    return make_float2(a.x * b.x - a.y * b.y, a.x * b.y + a.y * b.x);
}
__device__ __forceinline__ float2 cpowf(float2 w, int e) {
    float2 r = make_float2(1.0f, 0.0f);
    while (e) {
        if (e & 1) r = cmulf(r, w);
        w = cmulf(w, w);
        e >>= 1;
    }
    return r;
}
__device__ __forceinline__ void mma16816(float* c, const u32* a, const u32* b) {
    asm volatile(
        "mma.sync.aligned.m16n8k16.row.col.f32.bf16.bf16.f32 "
        "{%0,%1,%2,%3}, {%4,%5,%6,%7}, {%8,%9}, {%0,%1,%2,%3};"
        : "+f"(c[0]), "+f"(c[1]), "+f"(c[2]), "+f"(c[3])
        : "r"(a[0]), "r"(a[1]), "r"(a[2]), "r"(a[3]), "r"(b[0]), "r"(b[1]));
}
__device__ __forceinline__ void ldsm_x4(u32* r, const bf16* base, int stride,
                                        int r0, int k0, int lane) {
    const bf16* p = base + (r0 + (lane & 15)) * stride + k0 + (lane >> 4) * 8;
    u32 addr = (u32)__cvta_generic_to_shared(p);
    asm volatile("ldmatrix.sync.aligned.m8n8.x4.shared.b16 {%0,%1,%2,%3}, [%4];"
        : "=r"(r[0]), "=r"(r[1]), "=r"(r[2]), "=r"(r[3]) : "r"(addr));
}
__device__ __forceinline__ void ldsm_x2(u32* r, const bf16* base, int stride,
                                        int n0, int k0, int lane) {
    const bf16* p = base + (n0 + (lane & 7)) * stride + k0 + ((lane >> 3) & 1) * 8;
    u32 addr = (u32)__cvta_generic_to_shared(p);
    asm volatile("ldmatrix.sync.aligned.m8n8.x2.shared.b16 {%0,%1}, [%2];"
        : "=r"(r[0]), "=r"(r[1]) : "r"(addr));
}
__device__ __forceinline__ void cpasync16(void* sdst, const void* gsrc) {
    u32 s = (u32)__cvta_generic_to_shared(sdst);
    asm volatile("cp.async.cg.shared.global [%0], [%1], 16;" :: "r"(s), "l"(gsrc) : "memory");
}
#define CP_COMMIT() asm volatile("cp.async.commit_group;" ::: "memory")
#define CP_WAIT(n) asm volatile("cp.async.wait_group %0;" :: "n"(n) : "memory")

// stage one quarter (16KB/plane) via cp.async: 512 threads x 2 x 2 transfers
__device__ __forceinline__ void stage_async(const bf16* guh, const bf16* gul,
                                            int q, int t, bf16* UH, bf16* UL) {
    #pragma unroll
    for (int k = 0; k < 2; k++) {
        int f = t + k * 512;              // 0..1023
        int c = f >> 3, i0 = (f & 7) * 8;
        cpasync16(&UH[c * USTR + i0], guh + q * 8192 + c * 64 + i0);
        cpasync16(&UL[c * USTR + i0], gul + q * 8192 + c * 64 + i0);
    }
}

// ---------------- K0: per-h tables ----------------
__global__ void k_setup_tab(const float* __restrict__ log_dt,
                            const float* __restrict__ A_re, const float* __restrict__ A_im,
                            const float* __restrict__ C_re, const float* __restrict__ C_im,
                            const float* __restrict__ Dv)
{
    int h = blockIdx.x;
    int j = threadIdx.x;
    __shared__ float2 wf[NN];
    __shared__ float2 c2f[NN];
    __shared__ float Ks[64];

    double dt = exp((double)log_dt[h]);
    if (j < NN) {
        int i = h * NN + j;
        float ar = A_re[i], ai = A_im[i];
        double mre = dt * (double)ar, mim = dt * (double)ai;
        double e1 = exp(mre);
        float wr = (float)(e1 * cos(mim)), wi = (float)(e1 * sin(mim));
        wf[j] = make_float2(wr, wi);
        float den = ar * ar + ai * ai;
        float nr = wr - 1.0f, ni = wi;
        float qr = (nr * ar + ni * ai) / den, qi = (ni * ar - nr * ai) / den;
        float cr = C_re[i], ci = C_im[i];
        c2f[j] = make_float2(2.0f * (cr * qr - ci * qi), 2.0f * (cr * qi + ci * qr));
        float2 w64 = cpowf(make_float2(wr, wi), 64);
        g_w64c[h * 16 + j] = w64;
        g_wGc[h * 16 + j] = cpowf(w64, 16);
    }
    __syncthreads();

    float kacc = 0.0f;
    for (int n = 0; n < NN; n++) {
        float2 w = wf[n];
        float2 c2 = c2f[n];
        float2 wj = cpowf(w, j);
        kacc += c2.x * wj.x - c2.y * wj.y;
        float2 wj1 = cmulf(wj, w);
        bsplit(c2.x * wj1.x - c2.y * wj1.y,
               &g_Eh[h * 2048 + j * 32 + n], &g_El[h * 2048 + j * 32 + n]);
        bsplit(-(c2.x * wj1.y + c2.y * wj1.x),
               &g_Eh[h * 2048 + j * 32 + 16 + n], &g_El[h * 2048 + j * 32 + 16 + n]);
        float2 wv = cpowf(w, 63 - j);
        bsplit(wv.x, &g_Vh[h * 2048 + n * 64 + j], &g_Vl[h * 2048 + n * 64 + j]);
        bsplit(wv.y, &g_Vh[h * 2048 + (16 + n) * 64 + j], &g_Vl[h * 2048 + (16 + n) * 64 + j]);
    }
    Ks[j] = kacc;
    __syncthreads();

    float dD = Dv[h];
    for (int i2 = 0; i2 < 64; i2++) {
        float m = (i2 < j) ? Ks[j - i2] : (i2 == j ? Ks[0] + dD : 0.0f);
        bsplit(m, &g_Mh[h * 4096 + j * 64 + i2], &g_Ml[h * 4096 + j * 64 + i2]);
    }
}

// ---------------- K1: conditioning MLP + FiLM + W pre-split ----------------
__global__ void k_setup_mlp(const float* __restrict__ cp,
                            const float* __restrict__ W0, const float* __restrict__ b0,
                            const float* __restrict__ W1, const float* __restrict__ b1,
                            const float* __restrict__ W2, const float* __restrict__ b2,
                            const float* __restrict__ W_film, const float* __restrict__ b_film,
                            const float* __restrict__ W_lin)
{
    __shared__ float c0[BB * DMM];
    __shared__ float c1[BB * DMM];
    int t = threadIdx.x;
    for (int i = t; i < 4096; i += 256) {
        int k = i >> 6, h = i & 63;
        bsplit(W_lin[i], &g_WH[h * 64 + k], &g_WL[h * 64 + k]);
    }
    for (int i = t; i < BB * DMM; i += blockDim.x) {
        int b = i / DMM, d = i % DMM;
        float v = fmaf(cp[b * 2 + 0], W0[d], fmaf(cp[b * 2 + 1], W0[DMM + d], b0[d]));
        c0[i] = gelu_f(v);
    }
    __syncthreads();
    for (int i = t; i < BB * DMM; i += blockDim.x) {
        int b = i / DMM, d = i % DMM;
        float v = b1[d];
        for (int k = 0; k < DMM; k++) v = fmaf(c0[b * DMM + k], W1[k * DMM + d], v);
        c1[i] = gelu_f(v);
    }
    __syncthreads();
    for (int i = t; i < BB * DMM; i += blockDim.x) {
        int b = i / DMM, d = i % DMM;
        float v = b2[d];
        for (int k = 0; k < DMM; k++) v = fmaf(c1[b * DMM + k], W2[k * DMM + d], v);
        c0[i] = gelu_f(v);
    }
    __syncthreads();
    for (int i = t; i < BB * 2 * HH; i += blockDim.x) {
        int b = i / (2 * HH), j = i % (2 * HH);
        float v = b_film[j];
        for (int k = 0; k < DMM; k++) v = fmaf(c0[b * DMM + k], W_film[k * 2 * HH + j], v);
        if (j < HH) g_gamma[b * HH + j] = v;
        else        g_beta[b * HH + j - HH] = v;
    }
}

// ---------------- K2: u = gelu(x @ W_lin + b); writes hi/lo planes ----------------
__global__ __launch_bounds__(256, 2) void k_linear_mma(const float* __restrict__ x,
                                                       const float* __restrict__ bias)
{
    extern __shared__ char sm[];
    bf16* WtH = (bf16*)(sm + LM_WTH);
    bf16* WtL = (bf16*)(sm + LM_WTL);
    float* bs = (float*)(sm + LM_BS);
    bf16* XH = (bf16*)(sm + LM_XH);
    bf16* XL = (bf16*)(sm + LM_XL);
    bf16* YsH = (bf16*)(sm + LM_YS);            // overlays XH/XL after MMA
    bf16* YsL = YsH + 64 * YL;

    int t = threadIdx.x, wid = t >> 5, lane = t & 31;
    int b = blockIdx.x >> 7, tile = blockIdx.x & 127;
    int l0 = tile * 256;

    {
        const u32* gwh = (const u32*)g_WH;
        const u32* gwl = (const u32*)g_WL;
        u32* swh = (u32*)WtH; u32* swl = (u32*)WtL;
        for (int i = t; i < 2048; i += 256) {
            int r = i >> 5, c = i & 31;
            swh[r * 36 + c] = gwh[i];
            swl[r * 36 + c] = gwl[i];
        }
    }
    if (t < 64) bs[t] = bias[t];
    const float4* xg4 = (const float4*)(x + ((size_t)b * LL + l0) * HH);
    #pragma unroll
    for (int kk = 0; kk < 16; kk++) {
        int f = t + kk * 256;
        float4 v = xg4[f];
        int l = f >> 4, i0 = (f & 15) * 4;
        bf16 h0, l0b, h1, l1b, h2, l2b, h3, l3b;
        bsplit(v.x, &h0, &l0b); bsplit(v.y, &h1, &l1b);
        bsplit(v.z, &h2, &l2b); bsplit(v.w, &h3, &l3b);
        *(u32*)&XH[l * XSTR + i0] = pk2bf(h0, h1);
        *(u32*)&XH[l * XSTR + i0 + 2] = pk2bf(h2, h3);
        *(u32*)&XL[l * XSTR + i0] = pk2bf(l0b, l1b);
        *(u32*)&XL[l * XSTR + i0 + 2] = pk2bf(l2b, l3b);
    }
    __syncthreads();

    float C[2][8][4];
    #pragma unroll
    for (int mt = 0; mt < 2; mt++)
        #pragma unroll
        for (int nt = 0; nt < 8; nt++) {
            int c0 = nt * 8 + (lane & 3) * 2;
            C[mt][nt][0] = bs[c0]; C[mt][nt][1] = bs[c0 + 1];
            C[mt][nt][2] = bs[c0]; C[mt][nt][3] = bs[c0 + 1];
        }
    #pragma unroll
    for (int kt = 0; kt < 4; kt++) {
        int k0 = kt * 16;
        u32 ah[2][4], al[2][4];
        #pragma unroll
        for (int mt = 0; mt < 2; mt++) {
            ldsm_x4(ah[mt], XH, XSTR, wid * 32 + mt * 16, k0, lane);
            ldsm_x4(al[mt], XL, XSTR, wid * 32 + mt * 16, k0, lane);
        }
        #pragma unroll
        for (int nt = 0; nt < 8; nt++) {
            u32 bh[2], bl[2];
            ldsm_x2(bh, WtH, WSTR, nt * 8, k0, lane);
            ldsm_x2(bl, WtL, WSTR, nt * 8, k0, lane);
            #pragma unroll
            for (int mt = 0; mt < 2; mt++) {
                mma16816(C[mt][nt], ah[mt], bh);
                mma16816(C[mt][nt], ah[mt], bl);
                mma16816(C[mt][nt], al[mt], bh);
            }
        }
    }
    __syncthreads();
    #pragma unroll
    for (int mt = 0; mt < 2; mt++)
        #pragma unroll
        for (int nt = 0; nt < 8; nt++) {
            int l = wid * 32 + mt * 16 + (lane >> 2);
            int h0 = nt * 8 + (lane & 3) * 2;
            #pragma unroll
            for (int e = 0; e < 4; e++) {
                int hh = h0 + (e & 1);
                int ll = l + (e >> 1) * 8;
                bf16 hi, lo;
                bsplit(gelu_f(C[mt][nt][e]), &hi, &lo);
                YsH[hh * YL + ll] = hi;
                YsL[hh * YL + ll] = lo;
            }
        }
    __syncthreads();
    #pragma unroll
    for (int i = t; i < 2048; i += 256) {
        int h = i >> 5, q = i & 31;
        uint4 vh = *(const uint4*)&YsH[h * YL + q * 8];
        uint4 vl = *(const uint4*)&YsL[h * YL + q * 8];
        size_t base = ((size_t)b * HH + h) * LL + l0 + q * 8;
        *(uint4*)(g_uh + base) = vh;
        *(uint4*)(g_ul + base) = vl;
    }
}

// ---------------- K3: fused scan; pair-processed quarters, cp.async staging ----------------
__global__ __launch_bounds__(512) void k_scan_mma()
{
    extern __shared__ char smem[];
    bf16* MHs = (bf16*)(smem + SM_MH);
    bf16* MLs = (bf16*)(smem + SM_ML);
    bf16* VHs = (bf16*)(smem + SM_VH);
    bf16* VLs = (bf16*)(smem + SM_VL);
    bf16* EHs = (bf16*)(smem + SM_EH);
    bf16* ELs = (bf16*)(smem + SM_EL);
    float* SLOC = (float*)(smem + SM_SLOC);
    bf16* SINH = (bf16*)(smem + SM_SINH);
    bf16* SINL = (bf16*)(smem + SM_SINL);
    float2* GBUF = (float2*)(smem + SM_GBUF);
    bf16* B0H = (bf16*)(smem + SM_UB0);
    bf16* B0L = (bf16*)(smem + SM_UB0 + UBUF_HALF);
    bf16* B1H = (bf16*)(smem + SM_UB1);
    bf16* B1L = (bf16*)(smem + SM_UB1 + UBUF_HALF);
    bf16* B2H = (bf16*)(smem + SM_UB2);
    bf16* B2L = (bf16*)(smem + SM_UB2 + UBUF_HALF);

    int t = threadIdx.x;
    int bh = blockIdx.x;
    int h = bh & 63;
    int wid = t >> 5, lane = t & 31;
    int cloc = wid * 8;

    const bf16* guh = g_uh + (size_t)bh * LL;
    const bf16* gul = g_ul + (size_t)bh * LL;

    // kick off async staging of q0,q1,q2 first
    stage_async(guh, gul, 0, t, B0H, B0L); CP_COMMIT();
    stage_async(guh, gul, 1, t, B1H, B1L); CP_COMMIT();
    stage_async(guh, gul, 2, t, B2H, B2L); CP_COMMIT();

    // stage tables (regular stores; covered by first barrier)
    {
        const u32* gmh = (const u32*)(g_Mh + (size_t)h * 4096);
        const u32* gml = (const u32*)(g_Ml + (size_t)h * 4096);
        u32* smh = (u32*)MHs; u32* sml = (u32*)MLs;
        for (int i = t; i < 2048; i += 512) {
            int r = i >> 5, c = i & 31;
            smh[r * 36 + c] = gmh[i]; sml[r * 36 + c] = gml[i];
        }
        const u32* gvh = (const u32*)(g_Vh + (size_t)h * 2048);
        const u32* gvl = (const u32*)(g_Vl + (size_t)h * 2048);
        u32* svh = (u32*)VHs; u32* svl = (u32*)VLs;
        for (int i = t; i < 1024; i += 512) {
            int r = i >> 5, c = i & 31;
            svh[r * 36 + c] = gvh[i]; svl[r * 36 + c] = gvl[i];
        }
        const u32* geh = (const u32*)(g_Eh + (size_t)h * 2048);
        const u32* gel = (const u32*)(g_El + (size_t)h * 2048);
        u32* seh = (u32*)EHs; u32* sel = (u32*)ELs;
        for (int i = t; i < 1024; i += 512) {
            int r = i >> 4, c = i & 15;
            seh[r * 20 + c] = geh[i]; sel[r * 20 + c] = gel[i];
        }
    }

    float Yreg[64];
    #pragma unroll
    for (int i = 0; i < 64; i++) Yreg[i] = 0.0f;

    // ---- fused pass 1: pairs of quarters; shared A-fragments ----
#define PAIR(P, UHA, ULA, UHB, ULB)                                            \
    {                                                                          \
        float C1a[2][4] = {}, C1b[2][4] = {};                                  \
        _Pragma("unroll")                                                      \
        for (int kt = 0; kt < 4; kt++) {                                       \
            int k0 = kt * 16;                                                  \
            u32 bah[2], bal[2], bbh[2], bbl[2];                                \
            ldsm_x2(bah, UHA, USTR, cloc, k0, lane);                           \
            ldsm_x2(bal, ULA, USTR, cloc, k0, lane);                           \
            ldsm_x2(bbh, UHB, USTR, cloc, k0, lane);                           \
            ldsm_x2(bbl, ULB, USTR, cloc, k0, lane);                           \
            _Pragma("unroll")                                                  \
            for (int mt = 0; mt < 2; mt++) {                                   \
                u32 ah[4], al[4];                                              \
                ldsm_x4(ah, VHs, VSTR, mt * 16, k0, lane);                     \
                ldsm_x4(al, VLs, VSTR, mt * 16, k0, lane);                     \
                mma16816(C1a[mt], ah, bah); mma16816(C1a[mt], ah, bal);        \
                mma16816(C1a[mt], al, bah);                                    \
                mma16816(C1b[mt], ah, bbh); mma16816(C1b[mt], ah, bbl);        \
                mma16816(C1b[mt], al, bbh);                                    \
            }                                                                  \
            _Pragma("unroll")                                                  \
            for (int mt = 0; mt < 4; mt++) {                                   \
                if (kt > mt) continue;                                         \
                u32 ah[4], al[4];                                              \
                ldsm_x4(ah, MHs, MSTR, mt * 16, k0, lane);                     \
                ldsm_x4(al, MLs, MSTR, mt * 16, k0, lane);                     \
                float* Ca = &Yreg[(2 * (P)) * 16 + mt * 4];                    \
                float* Cb = &Yreg[(2 * (P) + 1) * 16 + mt * 4];                \
                mma16816(Ca, ah, bah); mma16816(Ca, ah, bal);                  \
                mma16816(Ca, al, bah);                                         \
                mma16816(Cb, ah, bbh); mma16816(Cb, ah, bbl);                  \
                mma16816(Cb, al, bbh);                                         \
            }                                                                  \
        }                                                                      \
        _Pragma("unroll")                                                      \
        for (int mt = 0; mt < 2; mt++) {                                       \
            int r = mt * 16 + (lane >> 2);                                     \
            int ca = (2 * (P)) * 128 + cloc + (lane & 3) * 2;                  \
            int cb = (2 * (P) + 1) * 128 + cloc + (lane & 3) * 2;              \
            SLOC[r * LSTR + ca] = C1a[mt][0];                                  \
            SLOC[r * LSTR + ca + 1] = C1a[mt][1];                              \
            SLOC[(r + 8) * LSTR + ca] = C1a[mt][2];                            \
            SLOC[(r + 8) * LSTR + ca + 1] = C1a[mt][3];                        \
            SLOC[r * LSTR + cb] = C1b[mt][0];                                  \
            SLOC[r * LSTR + cb + 1] = C1b[mt][1];                              \
            SLOC[(r + 8) * LSTR + cb] = C1b[mt][2];                            \
            SLOC[(r + 8) * LSTR + cb + 1] = C1b[mt][3];                        \
        }                                                                      \
    }

    CP_WAIT(1);            // q0,q1 landed (q2 may still be in flight)
    __syncthreads();       // + tables visible
    PAIR(0, B0H, B0L, B1H, B1L)
    __syncthreads();       // B0 free
    stage_async(guh, gul, 3, t, B0H, B0L); CP_COMMIT();
    CP_WAIT(0);
    __syncthreads();
    PAIR(1, B2H, B2L, B0H, B0L)
    __syncthreads();
#undef PAIR

    // ---- chunk-state scan: 32 groups x 16 chunks (SIN overwrites B1/B2 region) ----
    {
        int n = t & 15, g = t >> 4;
        float2 w64 = g_w64c[h * 16 + n];
        float sr = 0.f, si = 0.f;
        for (int m = 0; m < 16; m++) {
            int c = g * 16 + m;
            float xr = SLOC[n * LSTR + c], xi = SLOC[(16 + n) * LSTR + c];
            float nr = fmaf(w64.x, sr, fmaf(-w64.y, si, xr));
            si = fmaf(w64.x, si, fmaf(w64.y, sr, xi));
            sr = nr;
        }
        GBUF[g * 16 + n] = make_float2(sr, si);
        __syncthreads();
        if (t < 16) {
            float2 wG = g_wGc[h * 16 + t];
            float pr = 0.f, pi = 0.f;
            for (int gg = 0; gg < 32; gg++) {
                float2 tm = GBUF[gg * 16 + t];
                GBUF[gg * 16 + t] = make_float2(pr, pi);
                float nr = fmaf(wG.x, pr, fmaf(-wG.y, pi, tm.x));
                pi = fmaf(wG.x, pi, fmaf(wG.y, pr, tm.y));
                pr = nr;
            }
        }
        __syncthreads();
        float2 I = GBUF[g * 16 + n];
        sr = I.x; si = I.y;
        for (int m = 0; m < 16; m++) {
            int c = g * 16 + m;
            bsplit(sr, &SINH[c * SSTR + n], &SINL[c * SSTR + n]);
            bsplit(si, &SINH[c * SSTR + 16 + n], &SINL[c * SSTR + 16 + n]);
            float xr = SLOC[n * LSTR + c], xi = SLOC[(16 + n) * LSTR + c];
            float nr = fmaf(w64.x, sr, fmaf(-w64.y, si, xr));
            si = fmaf(w64.x, si, fmaf(w64.y, sr, xi));
            sr = nr;
        }
    }
    __syncthreads();

    // ---- pass 2: Y += E@S_in; FiLM; writeback ----
    float gam = g_gamma[bh];
    float bet = g_beta[bh];
    float* Ys = SLOC;
    float4* gz4 = (float4*)(g_z + (size_t)bh * LL);

    #pragma unroll
    for (int q = 0; q < 4; q++) {
        int cglob = q * 128 + cloc;
        #pragma unroll
        for (int kt = 0; kt < 2; kt++) {
            int k0 = kt * 16;
            u32 bh_[2], bl_[2];
            ldsm_x2(bh_, SINH, SSTR, cglob, k0, lane);
            ldsm_x2(bl_, SINL, SSTR, cglob, k0, lane);
            #pragma unroll
            for (int mt = 0; mt < 4; mt++) {
                u32 ah[4], al[4];
                ldsm_x4(ah, EHs, ESTR, mt * 16, k0, lane);
                ldsm_x4(al, ELs, ESTR, mt * 16, k0, lane);
                float* Cm = &Yreg[q * 16 + mt * 4];
                mma16816(Cm, ah, bh_);
                mma16816(Cm, ah, bl_);
                mma16816(Cm, al, bh_);
            }
        }
        #pragma unroll
        for (int mt = 0; mt < 4; mt++) {
            int j = mt * 16 + (lane >> 2);
            int cc = cloc + (lane & 3) * 2;
            const float* Cm = &Yreg[q * 16 + mt * 4];
            Ys[cc * YSTR + j] = fmaf(Cm[0], gam, bet);
            Ys[(cc + 1) * YSTR + j] = fmaf(Cm[1], gam, bet);
            Ys[cc * YSTR + j + 8] = fmaf(Cm[2], gam, bet);
            Ys[(cc + 1) * YSTR + j + 8] = fmaf(Cm[3], gam, bet);
        }
        __syncthreads();
        #pragma unroll
        for (int k = 0; k < 4; k++) {
            int f = t + k * 512;
            int c = f >> 4, qq = f & 15;
            float4 o = *(const float4*)&Ys[c * YSTR + qq * 4];
            gz4[q * 2048 + f] = o;
        }
        __syncthreads();
    }
}

// ---------------- K4: out = x * gelu(z) ----------------
__global__ __launch_bounds__(256) void k_epilogue(const float* __restrict__ x,
                                                  float* __restrict__ out)
{
    __shared__ float zt[64 * 65];
    int t = threadIdx.x;
    int b = blockIdx.x >> 9;
    int tile = blockIdx.x & 511;
    int l0 = tile * 64;
    #pragma unroll
    for (int i = t; i < 1024; i += 256) {
        int hh = i >> 4, q = i & 15;
        float4 v = *reinterpret_cast<const float4*>(
            g_z + ((size_t)b * HH + hh) * LL + l0 + 4 * q);
        float* d = zt + hh * 65 + 4 * q;
        d[0] = v.x; d[1] = v.y; d[2] = v.z; d[3] = v.w;
    }
    __syncthreads();
    #pragma unroll
    for (int i = t; i < 1024; i += 256) {
        int l = i >> 4, hq = i & 15;
        float z0 = zt[(4 * hq + 0) * 65 + l];
        float z1 = zt[(4 * hq + 1) * 65 + l];
        float z2 = zt[(4 * hq + 2) * 65 + l];
        float z3 = zt[(4 * hq + 3) * 65 + l];
        size_t base = ((size_t)b * LL + l0 + l) * HH + 4 * hq;
        float4 xv = *reinterpret_cast<const float4*>(x + base);
        float4 o;
        o.x = xv.x * gelu_f(z0);
        o.y = xv.y * gelu_f(z1);
        o.z = xv.z * gelu_f(z2);
        o.w = xv.w * gelu_f(z3);
        *reinterpret_cast<float4*>(out + base) = o;
    }
}

// ---------------- launch ----------------
extern "C" void kernel_launch(void* const* d_in, const int* in_sizes, int n_in,
                              void* d_out, int out_size)
{
    const float* x      = (const float*)d_in[0];
    const float* cp     = (const float*)d_in[1];
    const float* W0     = (const float*)d_in[2];
    const float* b0     = (const float*)d_in[3];
    const float* W1     = (const float*)d_in[4];
    const float* b1     = (const float*)d_in[5];
    const float* W2     = (const float*)d_in[6];
    const float* b2     = (const float*)d_in[7];
    const float* W_lin  = (const float*)d_in[8];
    const float* b_lin  = (const float*)d_in[9];
    const float* log_dt = (const float*)d_in[10];
    const float* A_re   = (const float*)d_in[11];
    const float* A_im   = (const float*)d_in[12];
    const float* C_re   = (const float*)d_in[13];
    const float* C_im   = (const float*)d_in[14];
    const float* Dv     = (const float*)d_in[15];
    const float* W_film = (const float*)d_in[16];
    const float* b_film = (const float*)d_in[17];
    float* out = (float*)d_out;

    cudaFuncSetAttribute(k_linear_mma, cudaFuncAttributeMaxDynamicSharedMemorySize, LM_TOT);
    cudaFuncSetAttribute(k_scan_mma, cudaFuncAttributeMaxDynamicSharedMemorySize, SM_TOT);

    k_setup_tab<<<HH, 64>>>(log_dt, A_re, A_im, C_re, C_im, Dv);
    k_setup_mlp<<<1, 256>>>(cp, W0, b0, W1, b1, W2, b2, W_film, b_film, W_lin);
    k_linear_mma<<<BB * (LL / 256), 256, LM_TOT>>>(x, b_lin);
    k_scan_mma<<<BB * HH, 512, SM_TOT>>>();
    k_epilogue<<<BB * (LL / 64), 256>>>(x, out);
}